// round 1
// baseline (speedup 1.0000x reference)
#include <cuda_runtime.h>
#include <cuda_bf16.h>
#include <math.h>

// Problem constants
#define D_MODEL 768
#define NUM_HEADS 12
#define DKH 64          // d_k per head
#define BATCH 2
#define SEQ 4096
#define MROWS (BATCH * SEQ)   // 8192

// ---------------- scratch (device globals; no allocation) ----------------
__device__ float g_q[BATCH * NUM_HEADS * SEQ * DKH];   // [bh][s][dk]
__device__ float g_k[BATCH * NUM_HEADS * SEQ * DKH];
__device__ float g_v[BATCH * NUM_HEADS * SEQ * DKH];
__device__ float g_att[MROWS * D_MODEL];               // [b*s][d]

// =========================================================================
// GEMM: out = X @ W^T + bias.   X:[M,768], W:[768,768] row-major.
// Tile 64x64, K-step 16, 256 threads, 4x4 per thread.
// split=1: write head-split layout [bh][s][dk]; split=0: flat [m][n].
// =========================================================================
#define GM 64
#define GN 64
#define GK 16
#define GPAD 68   // smem row stride (floats), multiple of 4

__global__ __launch_bounds__(256) void gemm_xwT_kernel(
    const float* __restrict__ X, const float* __restrict__ W,
    const float* __restrict__ bias, float* __restrict__ out, int split)
{
    __shared__ float As[GK * GPAD];   // As[k][m]
    __shared__ float Bs[GK * GPAD];   // Bs[k][n]

    const int tid = threadIdx.x;
    const int tx = tid & 15;
    const int ty = tid >> 4;
    const int row0 = blockIdx.y * GM;
    const int col0 = blockIdx.x * GN;

    const int lm = tid >> 2;            // 0..63
    const int lk = (tid & 3) << 2;      // 0,4,8,12

    float acc[4][4] = {};

    for (int k0 = 0; k0 < D_MODEL; k0 += GK) {
        float4 a = *(const float4*)(X + (size_t)(row0 + lm) * D_MODEL + k0 + lk);
        float4 b = *(const float4*)(W + (size_t)(col0 + lm) * D_MODEL + k0 + lk);
        As[(lk + 0) * GPAD + lm] = a.x;
        As[(lk + 1) * GPAD + lm] = a.y;
        As[(lk + 2) * GPAD + lm] = a.z;
        As[(lk + 3) * GPAD + lm] = a.w;
        Bs[(lk + 0) * GPAD + lm] = b.x;
        Bs[(lk + 1) * GPAD + lm] = b.y;
        Bs[(lk + 2) * GPAD + lm] = b.z;
        Bs[(lk + 3) * GPAD + lm] = b.w;
        __syncthreads();

        #pragma unroll
        for (int kk = 0; kk < GK; kk++) {
            float4 av = *(const float4*)(As + kk * GPAD + ty * 4);
            float4 bv = *(const float4*)(Bs + kk * GPAD + tx * 4);
            float ar[4] = {av.x, av.y, av.z, av.w};
            float br[4] = {bv.x, bv.y, bv.z, bv.w};
            #pragma unroll
            for (int i = 0; i < 4; i++)
                #pragma unroll
                for (int j = 0; j < 4; j++)
                    acc[i][j] += ar[i] * br[j];
        }
        __syncthreads();
    }

    const int n0 = col0 + tx * 4;
    const float4 bv4 = *(const float4*)(bias + n0);
    #pragma unroll
    for (int i = 0; i < 4; i++) {
        const int m = row0 + ty * 4 + i;
        float4 r;
        r.x = acc[i][0] + bv4.x;
        r.y = acc[i][1] + bv4.y;
        r.z = acc[i][2] + bv4.z;
        r.w = acc[i][3] + bv4.w;
        if (split) {
            const int b = m >> 12;          // m / SEQ
            const int s = m & (SEQ - 1);
            const int h = n0 >> 6;          // n0 / DKH
            const int d = n0 & (DKH - 1);
            float* p = out + (((size_t)(b * NUM_HEADS + h) * SEQ + s) * DKH + d);
            *(float4*)p = r;
        } else {
            *(float4*)(out + (size_t)m * D_MODEL + n0) = r;
        }
    }
}

// =========================================================================
// Flash attention, fp32. Per block: one (b,h) and a Q-tile of 64 rows.
// KV tile = 32. Online softmax. Static smem (< 48KB).
// =========================================================================
#define QT 64
#define KT 32
#define KSP 68   // Ks row stride (pad to break conflicts), mult of 4
#define PSP 36   // Ps row stride, mult of 4

__global__ __launch_bounds__(256) void attn_kernel(
    const float* __restrict__ Q, const float* __restrict__ K,
    const float* __restrict__ V, float* __restrict__ O)
{
    __shared__ float Qs[QT * DKH];      // [q][d], stride 64
    __shared__ float Ks[KT * KSP];      // [k][d], stride 68
    __shared__ float Vs[KT * DKH];      // [k][d], stride 64
    __shared__ float Ps[QT * PSP];      // [q][k], stride 36
    __shared__ float rowm[QT], rowl[QT], rowa[QT];
    __shared__ float red[QT * 4];

    const int tid = threadIdx.x;
    const int tx = tid & 15;
    const int ty = tid >> 4;
    const int q0 = blockIdx.x * QT;
    const int bh = blockIdx.y;

    const float* Qg = Q + ((size_t)bh * SEQ + q0) * DKH;
    const float* Kg = K + (size_t)bh * SEQ * DKH;
    const float* Vg = V + (size_t)bh * SEQ * DKH;

    // Load Q tile: 4096 floats = 1024 float4
    #pragma unroll
    for (int it = 0; it < 4; it++) {
        int idx = tid + it * 256;
        int r = idx >> 4;
        int c = (idx & 15) << 2;
        *(float4*)(Qs + r * DKH + c) = *(const float4*)(Qg + (size_t)r * DKH + c);
    }
    if (tid < QT) { rowm[tid] = -1e30f; rowl[tid] = 0.f; }

    float oacc[4][4] = {};
    __syncthreads();

    for (int kt = 0; kt < SEQ; kt += KT) {
        // Load K,V tiles: 2048 floats each = 512 float4 each
        #pragma unroll
        for (int it = 0; it < 2; it++) {
            int idx = tid + it * 256;
            int r = idx >> 4;
            int c = (idx & 15) << 2;
            *(float4*)(Ks + r * KSP + c) = *(const float4*)(Kg + (size_t)(kt + r) * DKH + c);
            *(float4*)(Vs + r * DKH + c) = *(const float4*)(Vg + (size_t)(kt + r) * DKH + c);
        }
        __syncthreads();

        // S = Q K^T * scale ; thread owns rows 4ty..+3, cols 2tx..+1
        float sacc[4][2] = {};
        #pragma unroll 4
        for (int d = 0; d < DKH; d += 4) {
            float4 k0v = *(const float4*)(Ks + (tx * 2 + 0) * KSP + d);
            float4 k1v = *(const float4*)(Ks + (tx * 2 + 1) * KSP + d);
            #pragma unroll
            for (int i = 0; i < 4; i++) {
                float4 q4 = *(const float4*)(Qs + (ty * 4 + i) * DKH + d);
                sacc[i][0] += q4.x * k0v.x + q4.y * k0v.y + q4.z * k0v.z + q4.w * k0v.w;
                sacc[i][1] += q4.x * k1v.x + q4.y * k1v.y + q4.z * k1v.z + q4.w * k1v.w;
            }
        }
        #pragma unroll
        for (int i = 0; i < 4; i++) {
            float2 w2;
            w2.x = sacc[i][0] * 0.125f;  // 1/sqrt(64)
            w2.y = sacc[i][1] * 0.125f;
            *(float2*)(Ps + (ty * 4 + i) * PSP + tx * 2) = w2;
        }
        __syncthreads();

        // Row max (4 threads per row, 8 cols each)
        {
            int row = tid >> 2, part = tid & 3;
            float mx = -1e30f;
            #pragma unroll
            for (int c = 0; c < 8; c++)
                mx = fmaxf(mx, Ps[row * PSP + part * 8 + c]);
            red[row * 4 + part] = mx;
        }
        __syncthreads();
        if ((tid & 3) == 0) {
            int row = tid >> 2;
            float mnew = fmaxf(fmaxf(red[row * 4 + 0], red[row * 4 + 1]),
                               fmaxf(red[row * 4 + 2], red[row * 4 + 3]));
            mnew = fmaxf(mnew, rowm[row]);
            rowa[row] = __expf(rowm[row] - mnew);
            rowm[row] = mnew;
        }
        __syncthreads();
        // exp pass + partial sums
        {
            int row = tid >> 2, part = tid & 3;
            float mnew = rowm[row];
            float s = 0.f;
            #pragma unroll
            for (int c = 0; c < 8; c++) {
                float e = __expf(Ps[row * PSP + part * 8 + c] - mnew);
                Ps[row * PSP + part * 8 + c] = e;
                s += e;
            }
            red[row * 4 + part] = s;
        }
        __syncthreads();
        if ((tid & 3) == 0) {
            int row = tid >> 2;
            rowl[row] = rowl[row] * rowa[row] +
                        red[row * 4 + 0] + red[row * 4 + 1] +
                        red[row * 4 + 2] + red[row * 4 + 3];
        }

        // O = O*alpha + P @ V ; thread owns rows 4ty..+3, d-cols 4tx..+3
        float al[4];
        #pragma unroll
        for (int i = 0; i < 4; i++) al[i] = rowa[ty * 4 + i];
        #pragma unroll
        for (int i = 0; i < 4; i++)
            #pragma unroll
            for (int j = 0; j < 4; j++) oacc[i][j] *= al[i];

        #pragma unroll
        for (int k = 0; k < KT; k += 4) {
            float4 v0 = *(const float4*)(Vs + (k + 0) * DKH + tx * 4);
            float4 v1 = *(const float4*)(Vs + (k + 1) * DKH + tx * 4);
            float4 v2 = *(const float4*)(Vs + (k + 2) * DKH + tx * 4);
            float4 v3 = *(const float4*)(Vs + (k + 3) * DKH + tx * 4);
            #pragma unroll
            for (int i = 0; i < 4; i++) {
                float4 p = *(const float4*)(Ps + (ty * 4 + i) * PSP + k);
                oacc[i][0] += p.x * v0.x + p.y * v1.x + p.z * v2.x + p.w * v3.x;
                oacc[i][1] += p.x * v0.y + p.y * v1.y + p.z * v2.y + p.w * v3.y;
                oacc[i][2] += p.x * v0.z + p.y * v1.z + p.z * v2.z + p.w * v3.z;
                oacc[i][3] += p.x * v0.w + p.y * v1.w + p.z * v2.w + p.w * v3.w;
            }
        }
        __syncthreads();
    }

    // Epilogue: normalize and write to [b][s][h*64+d]
    const int b = bh / NUM_HEADS;
    const int h = bh % NUM_HEADS;
    #pragma unroll
    for (int i = 0; i < 4; i++) {
        const int row = ty * 4 + i;
        const float inv = 1.f / rowl[row];
        float4 r;
        r.x = oacc[i][0] * inv;
        r.y = oacc[i][1] * inv;
        r.z = oacc[i][2] * inv;
        r.w = oacc[i][3] * inv;
        *(float4*)(O + ((size_t)(b * SEQ + q0 + row)) * D_MODEL + h * DKH + tx * 4) = r;
    }
}

// =========================================================================
// Launch
// =========================================================================
extern "C" void kernel_launch(void* const* d_in, const int* in_sizes, int n_in,
                              void* d_out, int out_size)
{
    const float* query = (const float*)d_in[0];
    const float* key   = (const float*)d_in[1];
    const float* value = (const float*)d_in[2];
    const float* Wq = (const float*)d_in[3];
    const float* bq = (const float*)d_in[4];
    const float* Wk = (const float*)d_in[5];
    const float* bk = (const float*)d_in[6];
    const float* Wv = (const float*)d_in[7];
    const float* bv = (const float*)d_in[8];
    const float* Wo = (const float*)d_in[9];
    const float* bo = (const float*)d_in[10];
    float* out = (float*)d_out;

    float *pq, *pk, *pv, *patt;
    cudaGetSymbolAddress((void**)&pq,  g_q);
    cudaGetSymbolAddress((void**)&pk,  g_k);
    cudaGetSymbolAddress((void**)&pv,  g_v);
    cudaGetSymbolAddress((void**)&patt, g_att);

    dim3 ggrid(D_MODEL / GN, MROWS / GM);   // (12, 128)
    gemm_xwT_kernel<<<ggrid, 256>>>(query, Wq, bq, pq, 1);
    gemm_xwT_kernel<<<ggrid, 256>>>(key,   Wk, bk, pk, 1);
    gemm_xwT_kernel<<<ggrid, 256>>>(value, Wv, bv, pv, 1);

    dim3 agrid(SEQ / QT, BATCH * NUM_HEADS);  // (64, 24)
    attn_kernel<<<agrid, 256>>>(pq, pk, pv, patt);

    gemm_xwT_kernel<<<ggrid, 256>>>(patt, Wo, bo, out, 0);
}

// round 2
// speedup vs baseline: 2.9517x; 2.9517x over previous
#include <cuda_runtime.h>
#include <cuda_fp16.h>
#include <math.h>
#include <stdint.h>

#define D_MODEL 768
#define NUM_HEADS 12
#define DKH 64
#define BATCH 2
#define SEQ 4096
#define MROWS (BATCH * SEQ)   // 8192
#define NBH (BATCH * NUM_HEADS)

// ---------------- scratch (device globals; no allocation) ----------------
__device__ float g_q[(size_t)NBH * SEQ * DKH];    // [bh][s][d], pre-scaled by 1/8
__device__ float g_k[(size_t)NBH * SEQ * DKH];    // [bh][s][d]
__device__ float g_vT[(size_t)NBH * DKH * SEQ];   // [bh][d][s]  (transposed!)
__device__ float g_att[(size_t)MROWS * D_MODEL];  // [b*s][dmodel]

// ---------------- helpers ----------------
__device__ __forceinline__ uint32_t smem_u32(const void* p) {
    return (uint32_t)__cvta_generic_to_shared(p);
}
__device__ __forceinline__ uint32_t pk(__half2 h) {
    union { __half2 h; uint32_t u; } x; x.h = h; return x.u;
}
__device__ __forceinline__ void ldsm_x4(uint32_t a, uint32_t& r0, uint32_t& r1,
                                        uint32_t& r2, uint32_t& r3) {
    asm volatile("ldmatrix.sync.aligned.m8n8.x4.shared.b16 {%0,%1,%2,%3}, [%4];"
                 : "=r"(r0), "=r"(r1), "=r"(r2), "=r"(r3) : "r"(a));
}
__device__ __forceinline__ void mma4(float* c, const uint32_t* a, uint32_t b0, uint32_t b1) {
    asm volatile(
        "mma.sync.aligned.m16n8k16.row.col.f32.f16.f16.f32 "
        "{%0,%1,%2,%3}, {%4,%5,%6,%7}, {%8,%9}, {%0,%1,%2,%3};"
        : "+f"(c[0]), "+f"(c[1]), "+f"(c[2]), "+f"(c[3])
        : "r"(a[0]), "r"(a[1]), "r"(a[2]), "r"(a[3]), "r"(b0), "r"(b1));
}
// split two fp32 into hi/lo fp16 pairs (packed)
__device__ __forceinline__ void split2(float x, float y, uint32_t& hi, uint32_t& lo) {
    __half2 h = __floats2half2_rn(x, y);
    float rx = x - __half2float(__low2half(h));
    float ry = y - __half2float(__high2half(h));
    hi = pk(h);
    lo = pk(__floats2half2_rn(rx, ry));
}

// =========================================================================
// GEMM (3-pass fp16 mma): C = X @ W^T + bias, optional scale / layout modes.
// X:[M,768] fp32, W:[N,768] fp32 (row-major; we need W[n][k] = B col-major).
// Block: 256 thr (8 warps). Tile M=128 (16 rows/warp), N=64. K-chunk 16.
// mode 0: out fp32 flat [m][n] (+bias)
// mode 1: head-split [bh][s][d]          (k)
// mode 2: head-split, scaled by 0.125    (q)
// mode 3: head-split transposed [bh][d][s] (v)
// =========================================================================
#define GBM 128
#define GBN 64
#define GKC 16
#define GSTR 24   // smem row stride in halves (48B -> conflict-free ldmatrix)

__global__ __launch_bounds__(256, 1) void gemm3p(
    const float* __restrict__ X, const float* __restrict__ W,
    const float* __restrict__ bias, float* __restrict__ out, int mode)
{
    __shared__ __align__(16) __half Ah[GBM * GSTR];
    __shared__ __align__(16) __half Al[GBM * GSTR];
    __shared__ __align__(16) __half Bh[GBN * GSTR];
    __shared__ __align__(16) __half Bl[GBN * GSTR];

    const int tid = threadIdx.x;
    const int w = tid >> 5;
    const int lane = tid & 31;
    const int row0 = blockIdx.y * GBM;
    const int col0 = blockIdx.x * GBN;

    float acc[8][4] = {};

    const int ar = tid >> 1, ac = (tid & 1) * 8;   // A: 2 float4 per thread
    const int br = tid >> 2, bc = (tid & 3) * 4;   // B: 1 float4 per thread

    const int blk = lane >> 3;
    const int lrow = lane & 7;
    // ldmatrix addresses (within-warp)
    const uint32_t a_addr_h = smem_u32(Ah + (16 * w + (blk & 1) * 8 + lrow) * GSTR + (blk >> 1) * 8);
    const uint32_t a_addr_l = smem_u32(Al + (16 * w + (blk & 1) * 8 + lrow) * GSTR + (blk >> 1) * 8);

    for (int k0 = 0; k0 < D_MODEL; k0 += GKC) {
        // ---- load + split A tile (128x16) ----
        {
            const float4* ap = (const float4*)(X + (size_t)(row0 + ar) * D_MODEL + k0 + ac);
            float4 f0 = ap[0], f1 = ap[1];
            uint32_t h0, l0, h1, l1, h2, l2, h3, l3;
            split2(f0.x, f0.y, h0, l0); split2(f0.z, f0.w, h1, l1);
            split2(f1.x, f1.y, h2, l2); split2(f1.z, f1.w, h3, l3);
            uint32_t* dh = (uint32_t*)(Ah + ar * GSTR + ac);
            uint32_t* dl = (uint32_t*)(Al + ar * GSTR + ac);
            dh[0] = h0; dh[1] = h1; dh[2] = h2; dh[3] = h3;
            dl[0] = l0; dl[1] = l1; dl[2] = l2; dl[3] = l3;
        }
        // ---- load + split B tile (64x16) ----
        {
            const float4* bp = (const float4*)(W + (size_t)(col0 + br) * D_MODEL + k0 + bc);
            float4 g = bp[0];
            uint32_t h0, l0, h1, l1;
            split2(g.x, g.y, h0, l0); split2(g.z, g.w, h1, l1);
            uint32_t* dh = (uint32_t*)(Bh + br * GSTR + bc);
            uint32_t* dl = (uint32_t*)(Bl + br * GSTR + bc);
            dh[0] = h0; dh[1] = h1;
            dl[0] = l0; dl[1] = l1;
        }
        __syncthreads();

        uint32_t ahi[4], alo[4];
        ldsm_x4(a_addr_h, ahi[0], ahi[1], ahi[2], ahi[3]);
        ldsm_x4(a_addr_l, alo[0], alo[1], alo[2], alo[3]);

        #pragma unroll
        for (int np = 0; np < 4; np++) {
            // B pair: ntiles 2np, 2np+1 ; mats: [rows(+0/+8)] x [k(+0/+8)]
            uint32_t bh0, bh1, bh2, bh3, bl0, bl1, bl2, bl3;
            const uint32_t b_h = smem_u32(Bh + (np * 16 + (blk >> 1) * 8 + lrow) * GSTR + (blk & 1) * 8);
            const uint32_t b_l = smem_u32(Bl + (np * 16 + (blk >> 1) * 8 + lrow) * GSTR + (blk & 1) * 8);
            ldsm_x4(b_h, bh0, bh1, bh2, bh3);
            ldsm_x4(b_l, bl0, bl1, bl2, bl3);
            mma4(acc[2 * np],     ahi, bh0, bh1);
            mma4(acc[2 * np],     ahi, bl0, bl1);
            mma4(acc[2 * np],     alo, bh0, bh1);
            mma4(acc[2 * np + 1], ahi, bh2, bh3);
            mma4(acc[2 * np + 1], ahi, bl2, bl3);
            mma4(acc[2 * np + 1], alo, bh2, bh3);
        }
        __syncthreads();
    }

    // ---- epilogue ----
    const float scale = (mode == 2) ? 0.125f : 1.0f;
    const int rloc = 16 * w + (lane >> 2);
    #pragma unroll
    for (int nt = 0; nt < 8; nt++) {
        const int n = col0 + nt * 8 + (lane & 3) * 2;
        const float bx = bias[n], by = bias[n + 1];
        const int m0 = row0 + rloc;
        float o00 = (acc[nt][0] + bx) * scale;
        float o01 = (acc[nt][1] + by) * scale;
        float o10 = (acc[nt][2] + bx) * scale;
        float o11 = (acc[nt][3] + by) * scale;
        if (mode == 0) {
            *(float2*)(out + (size_t)m0 * D_MODEL + n) = make_float2(o00, o01);
            *(float2*)(out + (size_t)(m0 + 8) * D_MODEL + n) = make_float2(o10, o11);
        } else {
            const int h = n >> 6, d = n & 63;
            const int b0m = m0 >> 12, s0 = m0 & (SEQ - 1);
            const int b1m = (m0 + 8) >> 12, s1 = (m0 + 8) & (SEQ - 1);
            if (mode == 3) {
                float* p0 = out + (((size_t)(b0m * NUM_HEADS + h) * DKH + d) * SEQ + s0);
                p0[0] = o00; p0[SEQ] = o01;
                float* p1 = out + (((size_t)(b1m * NUM_HEADS + h) * DKH + d) * SEQ + s1);
                p1[0] = o10; p1[SEQ] = o11;
            } else {
                *(float2*)(out + (((size_t)(b0m * NUM_HEADS + h) * SEQ + s0) * DKH + d)) =
                    make_float2(o00, o01);
                *(float2*)(out + (((size_t)(b1m * NUM_HEADS + h) * SEQ + s1) * DKH + d)) =
                    make_float2(o10, o11);
            }
        }
    }
}

// =========================================================================
// Flash attention with fp16 3-pass mma. Block: 256 thr (8 warps).
// Q tile 128 rows (16/warp, kept in registers, hi/lo). KV tile 64.
// K smem [kv][d], V^T smem [d][kv], both padded stride 72 halves.
// =========================================================================
#define QT 128
#define KVT 64
#define VSTR 72

__global__ __launch_bounds__(256, 1) void attn_mma(
    const float* __restrict__ Q, const float* __restrict__ K,
    const float* __restrict__ VT, float* __restrict__ O)
{
    __shared__ __align__(16) __half Kh[KVT * VSTR];
    __shared__ __align__(16) __half Kl[KVT * VSTR];
    __shared__ __align__(16) __half Vh[DKH * VSTR];
    __shared__ __align__(16) __half Vl[DKH * VSTR];

    const int tid = threadIdx.x;
    const int w = tid >> 5;
    const int lane = tid & 31;
    const int q0 = blockIdx.x * QT;
    const int bh = blockIdx.y;

    const float* Qg = Q + (size_t)bh * SEQ * DKH;
    const float* Kg = K + (size_t)bh * SEQ * DKH;
    const float* Vg = VT + (size_t)bh * DKH * SEQ;

    // ---- load Q fragments into registers (hi/lo), once ----
    uint32_t qh[4][4], ql[4][4];
    const int qr = q0 + 16 * w + (lane >> 2);
    #pragma unroll
    for (int ks = 0; ks < 4; ks++) {
        const int c0 = ks * 16 + (lane & 3) * 2;
        float2 v00 = *(const float2*)(Qg + (size_t)qr * DKH + c0);
        float2 v10 = *(const float2*)(Qg + (size_t)(qr + 8) * DKH + c0);
        float2 v01 = *(const float2*)(Qg + (size_t)qr * DKH + c0 + 8);
        float2 v11 = *(const float2*)(Qg + (size_t)(qr + 8) * DKH + c0 + 8);
        split2(v00.x, v00.y, qh[ks][0], ql[ks][0]);
        split2(v10.x, v10.y, qh[ks][1], ql[ks][1]);
        split2(v01.x, v01.y, qh[ks][2], ql[ks][2]);
        split2(v11.x, v11.y, qh[ks][3], ql[ks][3]);
    }

    float o[8][4] = {};
    float m0 = -1e30f, m1 = -1e30f, l0 = 0.f, l1 = 0.f;

    const int r = tid >> 2;                // 0..63
    const int cb = (tid & 3) * 16;         // column base (16 floats)
    const int blk = lane >> 3;
    const int lrow = lane & 7;

    for (int kt = 0; kt < SEQ; kt += KVT) {
        // ---- load + split K tile [64 kv][64 d] and V^T tile [64 d][64 kv] ----
        {
            const float4* kp = (const float4*)(Kg + (size_t)(kt + r) * DKH + cb);
            const float4* vp = (const float4*)(Vg + (size_t)r * SEQ + kt + cb);
            uint32_t* kdh = (uint32_t*)(Kh + r * VSTR + cb);
            uint32_t* kdl = (uint32_t*)(Kl + r * VSTR + cb);
            uint32_t* vdh = (uint32_t*)(Vh + r * VSTR + cb);
            uint32_t* vdl = (uint32_t*)(Vl + r * VSTR + cb);
            #pragma unroll
            for (int i = 0; i < 4; i++) {
                float4 f = kp[i];
                uint32_t h0, l0_, h1, l1_;
                split2(f.x, f.y, h0, l0_); split2(f.z, f.w, h1, l1_);
                kdh[2 * i] = h0; kdh[2 * i + 1] = h1;
                kdl[2 * i] = l0_; kdl[2 * i + 1] = l1_;
                float4 g = vp[i];
                split2(g.x, g.y, h0, l0_); split2(g.z, g.w, h1, l1_);
                vdh[2 * i] = h0; vdh[2 * i + 1] = h1;
                vdl[2 * i] = l0_; vdl[2 * i + 1] = l1_;
            }
        }
        __syncthreads();

        // ---- S = Q K^T (3-pass) ----
        float s[8][4] = {};
        #pragma unroll
        for (int ks = 0; ks < 4; ks++) {
            const int cc = ks * 16 + (blk & 1) * 8;
            #pragma unroll
            for (int np = 0; np < 4; np++) {
                const int rr = np * 16 + (blk >> 1) * 8 + lrow;
                uint32_t bh0, bh1, bh2, bh3, bl0, bl1, bl2, bl3;
                ldsm_x4(smem_u32(Kh + rr * VSTR + cc), bh0, bh1, bh2, bh3);
                ldsm_x4(smem_u32(Kl + rr * VSTR + cc), bl0, bl1, bl2, bl3);
                mma4(s[2 * np],     qh[ks], bh0, bh1);
                mma4(s[2 * np],     qh[ks], bl0, bl1);
                mma4(s[2 * np],     ql[ks], bh0, bh1);
                mma4(s[2 * np + 1], qh[ks], bh2, bh3);
                mma4(s[2 * np + 1], qh[ks], bl2, bl3);
                mma4(s[2 * np + 1], ql[ks], bh2, bh3);
            }
        }

        // ---- online softmax (rows: r0 = lane>>2, r1 = r0+8) ----
        float mn0 = -1e30f, mn1 = -1e30f;
        #pragma unroll
        for (int nt = 0; nt < 8; nt++) {
            mn0 = fmaxf(mn0, fmaxf(s[nt][0], s[nt][1]));
            mn1 = fmaxf(mn1, fmaxf(s[nt][2], s[nt][3]));
        }
        mn0 = fmaxf(mn0, __shfl_xor_sync(0xffffffffu, mn0, 1));
        mn0 = fmaxf(mn0, __shfl_xor_sync(0xffffffffu, mn0, 2));
        mn1 = fmaxf(mn1, __shfl_xor_sync(0xffffffffu, mn1, 1));
        mn1 = fmaxf(mn1, __shfl_xor_sync(0xffffffffu, mn1, 2));
        const float M0 = fmaxf(m0, mn0), M1 = fmaxf(m1, mn1);
        const float al0 = __expf(m0 - M0), al1 = __expf(m1 - M1);
        m0 = M0; m1 = M1;

        float sum0 = 0.f, sum1 = 0.f;
        #pragma unroll
        for (int nt = 0; nt < 8; nt++) {
            s[nt][0] = __expf(s[nt][0] - M0); sum0 += s[nt][0];
            s[nt][1] = __expf(s[nt][1] - M0); sum0 += s[nt][1];
            s[nt][2] = __expf(s[nt][2] - M1); sum1 += s[nt][2];
            s[nt][3] = __expf(s[nt][3] - M1); sum1 += s[nt][3];
        }
        sum0 += __shfl_xor_sync(0xffffffffu, sum0, 1);
        sum0 += __shfl_xor_sync(0xffffffffu, sum0, 2);
        sum1 += __shfl_xor_sync(0xffffffffu, sum1, 1);
        sum1 += __shfl_xor_sync(0xffffffffu, sum1, 2);
        l0 = l0 * al0 + sum0;
        l1 = l1 * al1 + sum1;

        #pragma unroll
        for (int nt = 0; nt < 8; nt++) {
            o[nt][0] *= al0; o[nt][1] *= al0;
            o[nt][2] *= al1; o[nt][3] *= al1;
        }

        // ---- P -> fp16 hi/lo A-fragments ----
        uint32_t ph[4][4], pl[4][4];
        #pragma unroll
        for (int ks = 0; ks < 4; ks++) {
            split2(s[2 * ks][0],     s[2 * ks][1],     ph[ks][0], pl[ks][0]);
            split2(s[2 * ks][2],     s[2 * ks][3],     ph[ks][1], pl[ks][1]);
            split2(s[2 * ks + 1][0], s[2 * ks + 1][1], ph[ks][2], pl[ks][2]);
            split2(s[2 * ks + 1][2], s[2 * ks + 1][3], ph[ks][3], pl[ks][3]);
        }

        // ---- O += P V (3-pass); V^T smem is [d][kv] ----
        #pragma unroll
        for (int ks = 0; ks < 4; ks++) {
            const int cc = ks * 16 + (blk & 1) * 8;   // kv offset
            #pragma unroll
            for (int np = 0; np < 4; np++) {
                const int rr = np * 16 + (blk >> 1) * 8 + lrow;  // d rows
                uint32_t bh0, bh1, bh2, bh3, bl0, bl1, bl2, bl3;
                ldsm_x4(smem_u32(Vh + rr * VSTR + cc), bh0, bh1, bh2, bh3);
                ldsm_x4(smem_u32(Vl + rr * VSTR + cc), bl0, bl1, bl2, bl3);
                mma4(o[2 * np],     ph[ks], bh0, bh1);
                mma4(o[2 * np],     ph[ks], bl0, bl1);
                mma4(o[2 * np],     pl[ks], bh0, bh1);
                mma4(o[2 * np + 1], ph[ks], bh2, bh3);
                mma4(o[2 * np + 1], ph[ks], bl2, bl3);
                mma4(o[2 * np + 1], pl[ks], bh2, bh3);
            }
        }
        __syncthreads();
    }

    // ---- epilogue: normalize, write att [b*s][h*64+d] fp32 ----
    const float inv0 = 1.f / l0, inv1 = 1.f / l1;
    const int b = bh / NUM_HEADS, h = bh % NUM_HEADS;
    const int rg = q0 + 16 * w + (lane >> 2);
    #pragma unroll
    for (int nt = 0; nt < 8; nt++) {
        const int d = h * DKH + nt * 8 + (lane & 3) * 2;
        *(float2*)(O + (size_t)(b * SEQ + rg) * D_MODEL + d) =
            make_float2(o[nt][0] * inv0, o[nt][1] * inv0);
        *(float2*)(O + (size_t)(b * SEQ + rg + 8) * D_MODEL + d) =
            make_float2(o[nt][2] * inv1, o[nt][3] * inv1);
    }
}

// =========================================================================
// Launch
// =========================================================================
extern "C" void kernel_launch(void* const* d_in, const int* in_sizes, int n_in,
                              void* d_out, int out_size)
{
    const float* query = (const float*)d_in[0];
    const float* key   = (const float*)d_in[1];
    const float* value = (const float*)d_in[2];
    const float* Wq = (const float*)d_in[3];
    const float* bq = (const float*)d_in[4];
    const float* Wk = (const float*)d_in[5];
    const float* bk = (const float*)d_in[6];
    const float* Wv = (const float*)d_in[7];
    const float* bv = (const float*)d_in[8];
    const float* Wo = (const float*)d_in[9];
    const float* bo = (const float*)d_in[10];
    float* out = (float*)d_out;

    float *pq, *pk, *pv, *patt;
    cudaGetSymbolAddress((void**)&pq,   g_q);
    cudaGetSymbolAddress((void**)&pk,   g_k);
    cudaGetSymbolAddress((void**)&pv,   g_vT);
    cudaGetSymbolAddress((void**)&patt, g_att);

    dim3 ggrid(D_MODEL / GBN, MROWS / GBM);   // (12, 64)
    gemm3p<<<ggrid, 256>>>(query, Wq, bq, pq, 2);   // q, scaled 1/8
    gemm3p<<<ggrid, 256>>>(key,   Wk, bk, pk, 1);   // k
    gemm3p<<<ggrid, 256>>>(value, Wv, bv, pv, 3);   // v transposed

    dim3 agrid(SEQ / QT, NBH);                // (32, 24)
    attn_mma<<<agrid, 256>>>(pq, pk, pv, patt);

    gemm3p<<<ggrid, 256>>>(patt, Wo, bo, out, 0);   // output projection
}

// round 3
// speedup vs baseline: 3.2621x; 1.1051x over previous
#include <cuda_runtime.h>
#include <cuda_fp16.h>
#include <math.h>
#include <stdint.h>

#define D_MODEL 768
#define NUM_HEADS 12
#define DKH 64
#define BATCH 2
#define SEQ 4096
#define MROWS (BATCH * SEQ)   // 8192
#define NBH (BATCH * NUM_HEADS)

// ---------------- scratch (device globals; no allocation) ----------------
#define QKV_ELEMS ((size_t)NBH * SEQ * DKH)      // 6.29M
__device__ __half g_qh[QKV_ELEMS], g_ql[QKV_ELEMS];       // [bh][s][d], prescaled 1/8
__device__ __half g_kh[QKV_ELEMS], g_kl[QKV_ELEMS];       // [bh][s][d]
__device__ __half g_vth[QKV_ELEMS], g_vtl[QKV_ELEMS];     // [bh][d][s]
__device__ __half g_xh[(size_t)MROWS * D_MODEL], g_xl[(size_t)MROWS * D_MODEL];
__device__ __half g_wh[(size_t)D_MODEL * D_MODEL], g_wl[(size_t)D_MODEL * D_MODEL];
__device__ __half g_ath[(size_t)MROWS * D_MODEL], g_atl[(size_t)MROWS * D_MODEL];

// ---------------- helpers ----------------
__device__ __forceinline__ uint32_t smem_u32(const void* p) {
    return (uint32_t)__cvta_generic_to_shared(p);
}
__device__ __forceinline__ uint32_t pk(__half2 h) {
    union { __half2 h; uint32_t u; } x; x.h = h; return x.u;
}
__device__ __forceinline__ void ldsm_x4(uint32_t a, uint32_t& r0, uint32_t& r1,
                                        uint32_t& r2, uint32_t& r3) {
    asm volatile("ldmatrix.sync.aligned.m8n8.x4.shared.b16 {%0,%1,%2,%3}, [%4];"
                 : "=r"(r0), "=r"(r1), "=r"(r2), "=r"(r3) : "r"(a));
}
__device__ __forceinline__ void mma4(float* c, const uint32_t* a, uint32_t b0, uint32_t b1) {
    asm volatile(
        "mma.sync.aligned.m16n8k16.row.col.f32.f16.f16.f32 "
        "{%0,%1,%2,%3}, {%4,%5,%6,%7}, {%8,%9}, {%0,%1,%2,%3};"
        : "+f"(c[0]), "+f"(c[1]), "+f"(c[2]), "+f"(c[3])
        : "r"(a[0]), "r"(a[1]), "r"(a[2]), "r"(a[3]), "r"(b0), "r"(b1));
}
__device__ __forceinline__ void split2(float x, float y, uint32_t& hi, uint32_t& lo) {
    __half2 h = __floats2half2_rn(x, y);
    float rx = x - __half2float(__low2half(h));
    float ry = y - __half2float(__high2half(h));
    hi = pk(h);
    lo = pk(__floats2half2_rn(rx, ry));
}
__device__ __forceinline__ void cpa16(uint32_t s, const void* g) {
    asm volatile("cp.async.cg.shared.global [%0], [%1], 16;" :: "r"(s), "l"(g));
}
__device__ __forceinline__ void cpa_commit() {
    asm volatile("cp.async.commit_group;");
}

// =========================================================================
// Converter: fp32 -> (half hi, half lo).  n4 = elements/4.
// =========================================================================
__global__ __launch_bounds__(256) void cvt_split(
    const float* __restrict__ x, __half* __restrict__ hi,
    __half* __restrict__ lo, int n4)
{
    uint32_t* hio = (uint32_t*)hi;
    uint32_t* loo = (uint32_t*)lo;
    for (int i = blockIdx.x * 256 + threadIdx.x; i < n4; i += gridDim.x * 256) {
        float4 f = ((const float4*)x)[i];
        uint32_t h0, l0, h1, l1;
        split2(f.x, f.y, h0, l0);
        split2(f.z, f.w, h1, l1);
        hio[2 * i] = h0; hio[2 * i + 1] = h1;
        loo[2 * i] = l0; loo[2 * i + 1] = l1;
    }
}

// =========================================================================
// GEMM (3-pass fp16 mma), pre-split inputs, cp.async double-buffered.
// A:[M,768] half hi/lo, W:[768,768] half hi/lo (row n = output feature).
// Block: 256 thr (8 warps). Tile M=128, N=64, K-chunk 16.
// mode 0: fp32 flat [m][n] (+bias)
// mode 1: head-split halves [bh][s][d]           (k)
// mode 2: head-split halves, scaled 0.125        (q)
// mode 3: head-split transposed halves [bh][d][s] (v)
// =========================================================================
#define GBM 128
#define GBN 64
#define GKC 16
#define GSTR 24   // smem row stride in halves (48B)
#define NKC (D_MODEL / GKC)   // 48

// per-stage smem layout (halves): Ah[128*24] Al[128*24] Bh[64*24] Bl[64*24]
#define GS_A (GBM * GSTR)
#define GS_B (GBN * GSTR)
#define GS_STAGE (2 * GS_A + 2 * GS_B)   // 9216 halves

__global__ __launch_bounds__(256, 1) void gemm_h(
    const __half* __restrict__ Ah, const __half* __restrict__ Al,
    const __half* __restrict__ Wh, const __half* __restrict__ Wl,
    const float* __restrict__ bias, float* __restrict__ outf,
    __half* __restrict__ outh, __half* __restrict__ outl, int mode)
{
    __shared__ __align__(16) __half gs[2 * GS_STAGE];

    const int tid = threadIdx.x;
    const int w = tid >> 5;
    const int lane = tid & 31;
    const int row0 = blockIdx.y * GBM;
    const int col0 = blockIdx.x * GBN;

    const int ar = tid >> 1;           // A row 0..127
    const int aoff = (tid & 1) * 8;    // halves
    const int br = tid >> 1;           // B row 0..63 (tid<128)
    const int blk = lane >> 3;
    const int lrow = lane & 7;

    float acc[8][4] = {};

    auto issue = [&](int kc, int st) {
        const int k0 = kc * GKC;
        __half* S = gs + st * GS_STAGE;
        uint32_t dA = smem_u32(S + ar * GSTR + aoff);
        cpa16(dA,                    Ah + (size_t)(row0 + ar) * D_MODEL + k0 + aoff);
        cpa16(dA + GS_A * 2,         Al + (size_t)(row0 + ar) * D_MODEL + k0 + aoff);
        if (tid < 128) {
            uint32_t dB = smem_u32(S + 2 * GS_A + br * GSTR + aoff);
            cpa16(dB,                Wh + (size_t)(col0 + br) * D_MODEL + k0 + aoff);
            cpa16(dB + GS_B * 2,     Wl + (size_t)(col0 + br) * D_MODEL + k0 + aoff);
        }
    };

    issue(0, 0);
    cpa_commit();

    for (int kc = 0; kc < NKC; kc++) {
        if (kc + 1 < NKC) {
            issue(kc + 1, (kc + 1) & 1);
            cpa_commit();
            asm volatile("cp.async.wait_group 1;");
        } else {
            asm volatile("cp.async.wait_group 0;");
        }
        __syncthreads();

        const __half* S = gs + (kc & 1) * GS_STAGE;
        const __half* sAh = S;
        const __half* sAl = S + GS_A;
        const __half* sBh = S + 2 * GS_A;
        const __half* sBl = S + 2 * GS_A + GS_B;

        uint32_t ahi[4], alo[4];
        const int arow = 16 * w + (blk & 1) * 8 + lrow;
        const int acol = (blk >> 1) * 8;
        ldsm_x4(smem_u32(sAh + arow * GSTR + acol), ahi[0], ahi[1], ahi[2], ahi[3]);
        ldsm_x4(smem_u32(sAl + arow * GSTR + acol), alo[0], alo[1], alo[2], alo[3]);

        #pragma unroll
        for (int np = 0; np < 4; np++) {
            const int brow = np * 16 + (blk >> 1) * 8 + lrow;
            const int bcol = (blk & 1) * 8;
            uint32_t bh0, bh1, bh2, bh3, bl0, bl1, bl2, bl3;
            ldsm_x4(smem_u32(sBh + brow * GSTR + bcol), bh0, bh1, bh2, bh3);
            ldsm_x4(smem_u32(sBl + brow * GSTR + bcol), bl0, bl1, bl2, bl3);
            mma4(acc[2 * np],     ahi, bh0, bh1);
            mma4(acc[2 * np],     ahi, bl0, bl1);
            mma4(acc[2 * np],     alo, bh0, bh1);
            mma4(acc[2 * np + 1], ahi, bh2, bh3);
            mma4(acc[2 * np + 1], ahi, bl2, bl3);
            mma4(acc[2 * np + 1], alo, bh2, bh3);
        }
        __syncthreads();
    }

    // ---- epilogue ----
    const float scale = (mode == 2) ? 0.125f : 1.0f;
    const int rloc = 16 * w + (lane >> 2);
    #pragma unroll
    for (int nt = 0; nt < 8; nt++) {
        const int n = col0 + nt * 8 + (lane & 3) * 2;
        const float bx = bias[n], by = bias[n + 1];
        const int m0 = row0 + rloc;
        float o00 = (acc[nt][0] + bx) * scale;
        float o01 = (acc[nt][1] + by) * scale;
        float o10 = (acc[nt][2] + bx) * scale;
        float o11 = (acc[nt][3] + by) * scale;
        if (mode == 0) {
            *(float2*)(outf + (size_t)m0 * D_MODEL + n) = make_float2(o00, o01);
            *(float2*)(outf + (size_t)(m0 + 8) * D_MODEL + n) = make_float2(o10, o11);
        } else {
            const int h = n >> 6, d = n & 63;
            const int b0m = m0 >> 12, s0 = m0 & (SEQ - 1);
            const int b1m = (m0 + 8) >> 12, s1 = (m0 + 8) & (SEQ - 1);
            if (mode == 3) {
                // transposed [bh][d][s], scalar half stores
                size_t p0 = ((size_t)(b0m * NUM_HEADS + h) * DKH + d) * SEQ + s0;
                size_t p1 = ((size_t)(b1m * NUM_HEADS + h) * DKH + d) * SEQ + s1;
                uint32_t h0u, l0u, h1u, l1u;
                split2(o00, o01, h0u, l0u);
                split2(o10, o11, h1u, l1u);
                __half2 H0 = *(__half2*)&h0u, L0 = *(__half2*)&l0u;
                __half2 H1 = *(__half2*)&h1u, L1 = *(__half2*)&l1u;
                outh[p0] = __low2half(H0);  outh[p0 + SEQ] = __high2half(H0);
                outl[p0] = __low2half(L0);  outl[p0 + SEQ] = __high2half(L0);
                outh[p1] = __low2half(H1);  outh[p1 + SEQ] = __high2half(H1);
                outl[p1] = __low2half(L1);  outl[p1 + SEQ] = __high2half(L1);
            } else {
                size_t p0 = ((size_t)(b0m * NUM_HEADS + h) * SEQ + s0) * DKH + d;
                size_t p1 = ((size_t)(b1m * NUM_HEADS + h) * SEQ + s1) * DKH + d;
                uint32_t h0u, l0u, h1u, l1u;
                split2(o00, o01, h0u, l0u);
                split2(o10, o11, h1u, l1u);
                *(uint32_t*)(outh + p0) = h0u;
                *(uint32_t*)(outl + p0) = l0u;
                *(uint32_t*)(outh + p1) = h1u;
                *(uint32_t*)(outl + p1) = l1u;
            }
        }
    }
}

// =========================================================================
// Flash attention, fp16 3-pass mma, pre-split inputs, cp.async 2-stage.
// Block 256 thr (8 warps). Q tile 128 rows (in regs). KV tile 64.
// K smem [kv][d], V^T smem [d][kv], stride 72 halves. Dynamic smem 72KB.
// =========================================================================
#define QT 128
#define KVT 64
#define VSTR 72
#define AT_TILE (KVT * VSTR)             // halves per array per stage
#define AT_STAGE (4 * AT_TILE)           // Kh,Kl,Vh,Vl

__global__ __launch_bounds__(256, 1) void attn_mma2(
    const __half* __restrict__ Qh, const __half* __restrict__ Ql,
    const __half* __restrict__ Kh, const __half* __restrict__ Kl,
    const __half* __restrict__ VTh, const __half* __restrict__ VTl,
    __half* __restrict__ Oh, __half* __restrict__ Ol)
{
    extern __shared__ __align__(16) __half dsm[];

    const int tid = threadIdx.x;
    const int w = tid >> 5;
    const int lane = tid & 31;
    const int q0 = blockIdx.x * QT;
    const int bh = blockIdx.y;

    const __half* Qgh = Qh + (size_t)bh * SEQ * DKH;
    const __half* Qgl = Ql + (size_t)bh * SEQ * DKH;
    const __half* Kgh = Kh + (size_t)bh * SEQ * DKH;
    const __half* Kgl = Kl + (size_t)bh * SEQ * DKH;
    const __half* Vgh = VTh + (size_t)bh * DKH * SEQ;
    const __half* Vgl = VTl + (size_t)bh * DKH * SEQ;

    // ---- Q fragments in registers (hi/lo), direct half loads ----
    uint32_t qh[4][4], ql[4][4];
    const int qr = q0 + 16 * w + (lane >> 2);
    #pragma unroll
    for (int ks = 0; ks < 4; ks++) {
        const int c0 = ks * 16 + (lane & 3) * 2;
        qh[ks][0] = *(const uint32_t*)(Qgh + (size_t)qr * DKH + c0);
        qh[ks][1] = *(const uint32_t*)(Qgh + (size_t)(qr + 8) * DKH + c0);
        qh[ks][2] = *(const uint32_t*)(Qgh + (size_t)qr * DKH + c0 + 8);
        qh[ks][3] = *(const uint32_t*)(Qgh + (size_t)(qr + 8) * DKH + c0 + 8);
        ql[ks][0] = *(const uint32_t*)(Qgl + (size_t)qr * DKH + c0);
        ql[ks][1] = *(const uint32_t*)(Qgl + (size_t)(qr + 8) * DKH + c0);
        ql[ks][2] = *(const uint32_t*)(Qgl + (size_t)qr * DKH + c0 + 8);
        ql[ks][3] = *(const uint32_t*)(Qgl + (size_t)(qr + 8) * DKH + c0 + 8);
    }

    float o[8][4] = {};
    float m0 = -1e30f, m1 = -1e30f, l0 = 0.f, l1 = 0.f;

    const int r = tid >> 2;                // 0..63
    const int cb = (tid & 3) * 16;         // half offset within 64
    const int blk = lane >> 3;
    const int lrow = lane & 7;

    auto issue = [&](int t, int st) {
        const size_t kg = (size_t)(t * KVT + r) * DKH + cb;
        const size_t vg = (size_t)r * SEQ + t * KVT + cb;
        __half* S = dsm + st * AT_STAGE;
        uint32_t dst = smem_u32(S + r * VSTR + cb);
        cpa16(dst,                  Kgh + kg);
        cpa16(dst + 16,             Kgh + kg + 8);
        cpa16(dst + AT_TILE * 2,        Kgl + kg);
        cpa16(dst + AT_TILE * 2 + 16,   Kgl + kg + 8);
        cpa16(dst + AT_TILE * 4,        Vgh + vg);
        cpa16(dst + AT_TILE * 4 + 16,   Vgh + vg + 8);
        cpa16(dst + AT_TILE * 6,        Vgl + vg);
        cpa16(dst + AT_TILE * 6 + 16,   Vgl + vg + 8);
    };

    issue(0, 0);
    cpa_commit();

    const int T = SEQ / KVT;   // 64
    for (int t = 0; t < T; t++) {
        if (t + 1 < T) {
            issue(t + 1, (t + 1) & 1);
            cpa_commit();
            asm volatile("cp.async.wait_group 1;");
        } else {
            asm volatile("cp.async.wait_group 0;");
        }
        __syncthreads();

        const __half* S = dsm + (t & 1) * AT_STAGE;
        const __half* sKh = S;
        const __half* sKl = S + AT_TILE;
        const __half* sVh = S + 2 * AT_TILE;
        const __half* sVl = S + 3 * AT_TILE;

        // ---- S = Q K^T (3-pass) ----
        float s[8][4] = {};
        #pragma unroll
        for (int ks = 0; ks < 4; ks++) {
            const int cc = ks * 16 + (blk & 1) * 8;
            #pragma unroll
            for (int np = 0; np < 4; np++) {
                const int rr = np * 16 + (blk >> 1) * 8 + lrow;
                uint32_t bh0, bh1, bh2, bh3, bl0, bl1, bl2, bl3;
                ldsm_x4(smem_u32(sKh + rr * VSTR + cc), bh0, bh1, bh2, bh3);
                ldsm_x4(smem_u32(sKl + rr * VSTR + cc), bl0, bl1, bl2, bl3);
                mma4(s[2 * np],     qh[ks], bh0, bh1);
                mma4(s[2 * np],     qh[ks], bl0, bl1);
                mma4(s[2 * np],     ql[ks], bh0, bh1);
                mma4(s[2 * np + 1], qh[ks], bh2, bh3);
                mma4(s[2 * np + 1], qh[ks], bl2, bl3);
                mma4(s[2 * np + 1], ql[ks], bh2, bh3);
            }
        }

        // ---- online softmax ----
        float mn0 = -1e30f, mn1 = -1e30f;
        #pragma unroll
        for (int nt = 0; nt < 8; nt++) {
            mn0 = fmaxf(mn0, fmaxf(s[nt][0], s[nt][1]));
            mn1 = fmaxf(mn1, fmaxf(s[nt][2], s[nt][3]));
        }
        mn0 = fmaxf(mn0, __shfl_xor_sync(0xffffffffu, mn0, 1));
        mn0 = fmaxf(mn0, __shfl_xor_sync(0xffffffffu, mn0, 2));
        mn1 = fmaxf(mn1, __shfl_xor_sync(0xffffffffu, mn1, 1));
        mn1 = fmaxf(mn1, __shfl_xor_sync(0xffffffffu, mn1, 2));
        const float M0 = fmaxf(m0, mn0), M1 = fmaxf(m1, mn1);
        const float al0 = __expf(m0 - M0), al1 = __expf(m1 - M1);
        m0 = M0; m1 = M1;

        float sum0 = 0.f, sum1 = 0.f;
        #pragma unroll
        for (int nt = 0; nt < 8; nt++) {
            s[nt][0] = __expf(s[nt][0] - M0); sum0 += s[nt][0];
            s[nt][1] = __expf(s[nt][1] - M0); sum0 += s[nt][1];
            s[nt][2] = __expf(s[nt][2] - M1); sum1 += s[nt][2];
            s[nt][3] = __expf(s[nt][3] - M1); sum1 += s[nt][3];
        }
        sum0 += __shfl_xor_sync(0xffffffffu, sum0, 1);
        sum0 += __shfl_xor_sync(0xffffffffu, sum0, 2);
        sum1 += __shfl_xor_sync(0xffffffffu, sum1, 1);
        sum1 += __shfl_xor_sync(0xffffffffu, sum1, 2);
        l0 = l0 * al0 + sum0;
        l1 = l1 * al1 + sum1;

        #pragma unroll
        for (int nt = 0; nt < 8; nt++) {
            o[nt][0] *= al0; o[nt][1] *= al0;
            o[nt][2] *= al1; o[nt][3] *= al1;
        }

        // ---- P -> fp16 hi/lo A-fragments ----
        uint32_t ph[4][4], pl[4][4];
        #pragma unroll
        for (int ks = 0; ks < 4; ks++) {
            split2(s[2 * ks][0],     s[2 * ks][1],     ph[ks][0], pl[ks][0]);
            split2(s[2 * ks][2],     s[2 * ks][3],     ph[ks][1], pl[ks][1]);
            split2(s[2 * ks + 1][0], s[2 * ks + 1][1], ph[ks][2], pl[ks][2]);
            split2(s[2 * ks + 1][2], s[2 * ks + 1][3], ph[ks][3], pl[ks][3]);
        }

        // ---- O += P V (3-pass); V^T smem is [d][kv] ----
        #pragma unroll
        for (int ks = 0; ks < 4; ks++) {
            const int cc = ks * 16 + (blk & 1) * 8;   // kv offset
            #pragma unroll
            for (int np = 0; np < 4; np++) {
                const int rr = np * 16 + (blk >> 1) * 8 + lrow;  // d rows
                uint32_t bh0, bh1, bh2, bh3, bl0, bl1, bl2, bl3;
                ldsm_x4(smem_u32(sVh + rr * VSTR + cc), bh0, bh1, bh2, bh3);
                ldsm_x4(smem_u32(sVl + rr * VSTR + cc), bl0, bl1, bl2, bl3);
                mma4(o[2 * np],     ph[ks], bh0, bh1);
                mma4(o[2 * np],     ph[ks], bl0, bl1);
                mma4(o[2 * np],     pl[ks], bh0, bh1);
                mma4(o[2 * np + 1], ph[ks], bh2, bh3);
                mma4(o[2 * np + 1], ph[ks], bl2, bl3);
                mma4(o[2 * np + 1], pl[ks], bh2, bh3);
            }
        }
        __syncthreads();
    }

    // ---- epilogue: normalize, split, write att halves [b*s][h*64+d] ----
    const float inv0 = 1.f / l0, inv1 = 1.f / l1;
    const int b = bh / NUM_HEADS, h = bh % NUM_HEADS;
    const int rg = q0 + 16 * w + (lane >> 2);
    #pragma unroll
    for (int nt = 0; nt < 8; nt++) {
        const int d = h * DKH + nt * 8 + (lane & 3) * 2;
        size_t p0 = (size_t)(b * SEQ + rg) * D_MODEL + d;
        size_t p1 = (size_t)(b * SEQ + rg + 8) * D_MODEL + d;
        uint32_t h0u, l0u, h1u, l1u;
        split2(o[nt][0] * inv0, o[nt][1] * inv0, h0u, l0u);
        split2(o[nt][2] * inv1, o[nt][3] * inv1, h1u, l1u);
        *(uint32_t*)(Oh + p0) = h0u;
        *(uint32_t*)(Ol + p0) = l0u;
        *(uint32_t*)(Oh + p1) = h1u;
        *(uint32_t*)(Ol + p1) = l1u;
    }
}

// =========================================================================
// Launch
// =========================================================================
extern "C" void kernel_launch(void* const* d_in, const int* in_sizes, int n_in,
                              void* d_out, int out_size)
{
    const float* query = (const float*)d_in[0];
    const float* key   = (const float*)d_in[1];
    const float* value = (const float*)d_in[2];
    const float* Wq = (const float*)d_in[3];
    const float* bq = (const float*)d_in[4];
    const float* Wk = (const float*)d_in[5];
    const float* bk = (const float*)d_in[6];
    const float* Wv = (const float*)d_in[7];
    const float* bv = (const float*)d_in[8];
    const float* Wo = (const float*)d_in[9];
    const float* bo = (const float*)d_in[10];
    float* out = (float*)d_out;

    __half *qh, *ql, *kh, *kl, *vth, *vtl, *xh, *xl, *wh, *wl, *ath, *atl;
    cudaGetSymbolAddress((void**)&qh,  g_qh);  cudaGetSymbolAddress((void**)&ql,  g_ql);
    cudaGetSymbolAddress((void**)&kh,  g_kh);  cudaGetSymbolAddress((void**)&kl,  g_kl);
    cudaGetSymbolAddress((void**)&vth, g_vth); cudaGetSymbolAddress((void**)&vtl, g_vtl);
    cudaGetSymbolAddress((void**)&xh,  g_xh);  cudaGetSymbolAddress((void**)&xl,  g_xl);
    cudaGetSymbolAddress((void**)&wh,  g_wh);  cudaGetSymbolAddress((void**)&wl,  g_wl);
    cudaGetSymbolAddress((void**)&ath, g_ath); cudaGetSymbolAddress((void**)&atl, g_atl);

    cudaFuncSetAttribute(attn_mma2, cudaFuncAttributeMaxDynamicSharedMemorySize,
                         2 * AT_STAGE * (int)sizeof(__half));

    const int NX4 = MROWS * D_MODEL / 4;     // activations
    const int NW4 = D_MODEL * D_MODEL / 4;   // weights
    dim3 ggrid(D_MODEL / GBN, MROWS / GBM);  // (12, 64)

    // Q projection
    cvt_split<<<1184, 256>>>(query, xh, xl, NX4);
    cvt_split<<<592, 256>>>(Wq, wh, wl, NW4);
    gemm_h<<<ggrid, 256>>>(xh, xl, wh, wl, bq, nullptr, qh, ql, 2);
    // K projection
    cvt_split<<<1184, 256>>>(key, xh, xl, NX4);
    cvt_split<<<592, 256>>>(Wk, wh, wl, NW4);
    gemm_h<<<ggrid, 256>>>(xh, xl, wh, wl, bk, nullptr, kh, kl, 1);
    // V projection (transposed output)
    cvt_split<<<1184, 256>>>(value, xh, xl, NX4);
    cvt_split<<<592, 256>>>(Wv, wh, wl, NW4);
    gemm_h<<<ggrid, 256>>>(xh, xl, wh, wl, bv, nullptr, vth, vtl, 3);

    // attention
    dim3 agrid(SEQ / QT, NBH);   // (32, 24)
    attn_mma2<<<agrid, 256, 2 * AT_STAGE * (int)sizeof(__half)>>>(
        qh, ql, kh, kl, vth, vtl, ath, atl);

    // output projection
    cvt_split<<<592, 256>>>(Wo, wh, wl, NW4);
    gemm_h<<<ggrid, 256>>>(ath, atl, wh, wl, bo, out, nullptr, nullptr, 0);
}

// round 5
// speedup vs baseline: 3.5532x; 1.0893x over previous
#include <cuda_runtime.h>
#include <cuda_fp16.h>
#include <math.h>
#include <stdint.h>

#define D_MODEL 768
#define NUM_HEADS 12
#define DKH 64
#define BATCH 2
#define SEQ 4096
#define MROWS (BATCH * SEQ)   // 8192
#define NBH (BATCH * NUM_HEADS)

// q prescale folds 1/sqrt(64) and log2(e):  log2(e)/8
#define QSCALE 0.18033688011112042f
// 4 nats in log2 units
#define SHIFT_LOG2 5.770780163555855f

// ---------------- scratch (device globals; no allocation) ----------------
#define QKV_ELEMS ((size_t)NBH * SEQ * DKH)
__device__ __half g_qh[QKV_ELEMS], g_ql[QKV_ELEMS];       // [bh][s][d], prescaled log2e/8
__device__ __half g_kh[QKV_ELEMS], g_kl[QKV_ELEMS];       // [bh][s][d]
__device__ __half g_vth[QKV_ELEMS], g_vtl[QKV_ELEMS];     // [bh][d][s]
__device__ __half g_xh[(size_t)MROWS * D_MODEL], g_xl[(size_t)MROWS * D_MODEL];
__device__ __half g_wh[(size_t)D_MODEL * D_MODEL], g_wl[(size_t)D_MODEL * D_MODEL];
__device__ __half g_ath[(size_t)MROWS * D_MODEL], g_atl[(size_t)MROWS * D_MODEL];
__device__ float  g_maxk[NBH];

// ---------------- helpers ----------------
__device__ __forceinline__ uint32_t smem_u32(const void* p) {
    return (uint32_t)__cvta_generic_to_shared(p);
}
__device__ __forceinline__ uint32_t pk(__half2 h) {
    union { __half2 h; uint32_t u; } x; x.h = h; return x.u;
}
__device__ __forceinline__ void ldsm_x4(uint32_t a, uint32_t& r0, uint32_t& r1,
                                        uint32_t& r2, uint32_t& r3) {
    asm volatile("ldmatrix.sync.aligned.m8n8.x4.shared.b16 {%0,%1,%2,%3}, [%4];"
                 : "=r"(r0), "=r"(r1), "=r"(r2), "=r"(r3) : "r"(a));
}
__device__ __forceinline__ void mma4(float* c, const uint32_t* a, uint32_t b0, uint32_t b1) {
    asm volatile(
        "mma.sync.aligned.m16n8k16.row.col.f32.f16.f16.f32 "
        "{%0,%1,%2,%3}, {%4,%5,%6,%7}, {%8,%9}, {%0,%1,%2,%3};"
        : "+f"(c[0]), "+f"(c[1]), "+f"(c[2]), "+f"(c[3])
        : "r"(a[0]), "r"(a[1]), "r"(a[2]), "r"(a[3]), "r"(b0), "r"(b1));
}
__device__ __forceinline__ void split2(float x, float y, uint32_t& hi, uint32_t& lo) {
    __half2 h = __floats2half2_rn(x, y);
    float rx = x - __half2float(__low2half(h));
    float ry = y - __half2float(__high2half(h));
    hi = pk(h);
    lo = pk(__floats2half2_rn(rx, ry));
}
__device__ __forceinline__ void cpa16(uint32_t s, const void* g) {
    asm volatile("cp.async.cg.shared.global [%0], [%1], 16;" :: "r"(s), "l"(g));
}
__device__ __forceinline__ void cpa_commit() {
    asm volatile("cp.async.commit_group;");
}
__device__ __forceinline__ float ex2(float x) {
    float y;
    asm("ex2.approx.f32 %0, %1;" : "=f"(y) : "f"(x));
    return y;
}

// =========================================================================
// Converter: fp32 -> (half hi, half lo)
// =========================================================================
__global__ __launch_bounds__(256) void cvt_split(
    const float* __restrict__ x, __half* __restrict__ hi,
    __half* __restrict__ lo, int n4)
{
    uint32_t* hio = (uint32_t*)hi;
    uint32_t* loo = (uint32_t*)lo;
    for (int i = blockIdx.x * 256 + threadIdx.x; i < n4; i += gridDim.x * 256) {
        float4 f = ((const float4*)x)[i];
        uint32_t h0, l0, h1, l1;
        split2(f.x, f.y, h0, l0);
        split2(f.z, f.w, h1, l1);
        hio[2 * i] = h0; hio[2 * i + 1] = h1;
        loo[2 * i] = l0; loo[2 * i + 1] = l1;
    }
}

// =========================================================================
// Per-bh max ||k_row|| (hi halves; slack absorbed by the -4nat shift)
// =========================================================================
__global__ __launch_bounds__(256) void kmax_kernel(const __half* __restrict__ kh,
                                                   float* __restrict__ maxk)
{
    __shared__ float red[256];
    const int bh = blockIdx.x;
    const __half* base = kh + (size_t)bh * SEQ * DKH;
    float mx = 0.f;
    for (int r = threadIdx.x; r < SEQ; r += 256) {
        const uint4* p = (const uint4*)(base + (size_t)r * DKH);
        float s = 0.f;
        #pragma unroll
        for (int i = 0; i < 8; i++) {
            uint4 u = p[i];
            uint32_t ws[4] = {u.x, u.y, u.z, u.w};
            #pragma unroll
            for (int j = 0; j < 4; j++) {
                float2 f = __half22float2(*(__half2*)&ws[j]);
                s += f.x * f.x + f.y * f.y;
            }
        }
        mx = fmaxf(mx, s);
    }
    red[threadIdx.x] = mx;
    __syncthreads();
    for (int st = 128; st > 0; st >>= 1) {
        if (threadIdx.x < st) red[threadIdx.x] = fmaxf(red[threadIdx.x], red[threadIdx.x + st]);
        __syncthreads();
    }
    if (threadIdx.x == 0) maxk[bh] = sqrtf(red[0]);
}

// =========================================================================
// GEMM (3-pass fp16 mma.sync), pre-split inputs, cp.async double-buffered.
// 2 CTAs/SM target.
// =========================================================================
#define GBM 128
#define GBN 64
#define GKC 16
#define GSTR 24
#define NKC (D_MODEL / GKC)
#define GS_A (GBM * GSTR)
#define GS_B (GBN * GSTR)
#define GS_STAGE (2 * GS_A + 2 * GS_B)

__global__ __launch_bounds__(256, 2) void gemm_h(
    const __half* __restrict__ Ah, const __half* __restrict__ Al,
    const __half* __restrict__ Wh, const __half* __restrict__ Wl,
    const float* __restrict__ bias, float* __restrict__ outf,
    __half* __restrict__ outh, __half* __restrict__ outl, int mode)
{
    __shared__ __align__(16) __half gs[2 * GS_STAGE];

    const int tid = threadIdx.x;
    const int w = tid >> 5;
    const int lane = tid & 31;
    const int row0 = blockIdx.y * GBM;
    const int col0 = blockIdx.x * GBN;

    const int ar = tid >> 1;
    const int aoff = (tid & 1) * 8;
    const int br = tid >> 1;
    const int blk = lane >> 3;
    const int lrow = lane & 7;

    float acc[8][4] = {};

    auto issue = [&](int kc, int st) {
        const int k0 = kc * GKC;
        __half* S = gs + st * GS_STAGE;
        uint32_t dA = smem_u32(S + ar * GSTR + aoff);
        cpa16(dA,            Ah + (size_t)(row0 + ar) * D_MODEL + k0 + aoff);
        cpa16(dA + GS_A * 2, Al + (size_t)(row0 + ar) * D_MODEL + k0 + aoff);
        if (tid < 128) {
            uint32_t dB = smem_u32(S + 2 * GS_A + br * GSTR + aoff);
            cpa16(dB,            Wh + (size_t)(col0 + br) * D_MODEL + k0 + aoff);
            cpa16(dB + GS_B * 2, Wl + (size_t)(col0 + br) * D_MODEL + k0 + aoff);
        }
    };

    issue(0, 0);
    cpa_commit();

    for (int kc = 0; kc < NKC; kc++) {
        if (kc + 1 < NKC) {
            issue(kc + 1, (kc + 1) & 1);
            cpa_commit();
            asm volatile("cp.async.wait_group 1;");
        } else {
            asm volatile("cp.async.wait_group 0;");
        }
        __syncthreads();

        const __half* S = gs + (kc & 1) * GS_STAGE;
        const __half* sAh = S;
        const __half* sAl = S + GS_A;
        const __half* sBh = S + 2 * GS_A;
        const __half* sBl = S + 2 * GS_A + GS_B;

        uint32_t ahi[4], alo[4];
        const int arow = 16 * w + (blk & 1) * 8 + lrow;
        const int acol = (blk >> 1) * 8;
        ldsm_x4(smem_u32(sAh + arow * GSTR + acol), ahi[0], ahi[1], ahi[2], ahi[3]);
        ldsm_x4(smem_u32(sAl + arow * GSTR + acol), alo[0], alo[1], alo[2], alo[3]);

        #pragma unroll
        for (int np = 0; np < 4; np++) {
            const int brow = np * 16 + (blk >> 1) * 8 + lrow;
            const int bcol = (blk & 1) * 8;
            uint32_t bh0, bh1, bh2, bh3, bl0, bl1, bl2, bl3;
            ldsm_x4(smem_u32(sBh + brow * GSTR + bcol), bh0, bh1, bh2, bh3);
            ldsm_x4(smem_u32(sBl + brow * GSTR + bcol), bl0, bl1, bl2, bl3);
            mma4(acc[2 * np],     ahi, bh0, bh1);
            mma4(acc[2 * np + 1], ahi, bh2, bh3);
            mma4(acc[2 * np],     ahi, bl0, bl1);
            mma4(acc[2 * np + 1], ahi, bl2, bl3);
            mma4(acc[2 * np],     alo, bh0, bh1);
            mma4(acc[2 * np + 1], alo, bh2, bh3);
        }
        __syncthreads();
    }

    const float scale = (mode == 2) ? QSCALE : 1.0f;
    const int rloc = 16 * w + (lane >> 2);
    #pragma unroll
    for (int nt = 0; nt < 8; nt++) {
        const int n = col0 + nt * 8 + (lane & 3) * 2;
        const float bx = bias[n], by = bias[n + 1];
        const int m0 = row0 + rloc;
        float o00 = (acc[nt][0] + bx) * scale;
        float o01 = (acc[nt][1] + by) * scale;
        float o10 = (acc[nt][2] + bx) * scale;
        float o11 = (acc[nt][3] + by) * scale;
        if (mode == 0) {
            *(float2*)(outf + (size_t)m0 * D_MODEL + n) = make_float2(o00, o01);
            *(float2*)(outf + (size_t)(m0 + 8) * D_MODEL + n) = make_float2(o10, o11);
        } else {
            const int h = n >> 6, d = n & 63;
            const int b0m = m0 >> 12, s0 = m0 & (SEQ - 1);
            const int b1m = (m0 + 8) >> 12, s1 = (m0 + 8) & (SEQ - 1);
            uint32_t h0u, l0u, h1u, l1u;
            split2(o00, o01, h0u, l0u);
            split2(o10, o11, h1u, l1u);
            if (mode == 3) {
                size_t p0 = ((size_t)(b0m * NUM_HEADS + h) * DKH + d) * SEQ + s0;
                size_t p1 = ((size_t)(b1m * NUM_HEADS + h) * DKH + d) * SEQ + s1;
                __half2 H0 = *(__half2*)&h0u, L0 = *(__half2*)&l0u;
                __half2 H1 = *(__half2*)&h1u, L1 = *(__half2*)&l1u;
                outh[p0] = __low2half(H0);  outh[p0 + SEQ] = __high2half(H0);
                outl[p0] = __low2half(L0);  outl[p0 + SEQ] = __high2half(L0);
                outh[p1] = __low2half(H1);  outh[p1 + SEQ] = __high2half(H1);
                outl[p1] = __low2half(L1);  outl[p1 + SEQ] = __high2half(L1);
            } else {
                size_t p0 = ((size_t)(b0m * NUM_HEADS + h) * SEQ + s0) * DKH + d;
                size_t p1 = ((size_t)(b1m * NUM_HEADS + h) * SEQ + s1) * DKH + d;
                *(uint32_t*)(outh + p0) = h0u;
                *(uint32_t*)(outl + p0) = l0u;
                *(uint32_t*)(outh + p1) = h1u;
                *(uint32_t*)(outl + p1) = l1u;
            }
        }
    }
}

// =========================================================================
// Flash attention, mma.sync 3-pass, SAFE-MAX softmax (no online rescale).
// 256 thr / 8 warps, Q tile 128 rows (SMEM-resident), KV tile 64, 2-stage
// cp.async. 2 CTAs/SM target. Dynamic smem 110592 B.
// =========================================================================
#define QT 128
#define KVT 64
#define VSTR 72
#define QTILE (QT * VSTR)            // halves
#define KTILE (KVT * VSTR)
#define STG (4 * KTILE)              // Kh,Kl,Vh,Vl per stage
#define ATT_SMEM ((2 * QTILE + 2 * STG) * 2)   // bytes = 110592
#define NT (SEQ / KVT)               // 64

__global__ __launch_bounds__(256, 2) void attn_sm(
    const __half* __restrict__ Qh_, const __half* __restrict__ Ql_,
    const __half* __restrict__ Kh_, const __half* __restrict__ Kl_,
    const __half* __restrict__ VTh_, const __half* __restrict__ VTl_,
    const float* __restrict__ maxk,
    __half* __restrict__ Oh_, __half* __restrict__ Ol_)
{
    extern __shared__ __align__(16) __half sm[];
    __half* sQh = sm;
    __half* sQl = sm + QTILE;
    __half* sStage = sm + 2 * QTILE;

    const int tid = threadIdx.x;
    const int w = tid >> 5;
    const int lane = tid & 31;
    const int q0 = blockIdx.x * QT;
    const int bh = blockIdx.y;
    const int blk = lane >> 3;
    const int lrow = lane & 7;

    const __half* Qgh = Qh_ + (size_t)bh * SEQ * DKH;
    const __half* Qgl = Ql_ + (size_t)bh * SEQ * DKH;
    const __half* Kgh = Kh_ + (size_t)bh * SEQ * DKH;
    const __half* Kgl = Kl_ + (size_t)bh * SEQ * DKH;
    const __half* Vgh = VTh_ + (size_t)bh * DKH * SEQ;
    const __half* Vgl = VTl_ + (size_t)bh * DKH * SEQ;

    // ---- K/V stage loader ----
    auto issue_kv = [&](int t, int st) {
        const int kt = t * KVT;
        __half* S = sStage + st * STG;
        #pragma unroll
        for (int i = 0; i < 8; i++) {
            const int ci = tid + i * 256;      // 0..2047
            const int arr = ci >> 9;           // 0 Kh,1 Kl,2 Vh,3 Vl
            const int c = ci & 511;
            const int r = c >> 3, c8 = c & 7;
            const uint32_t dst = smem_u32(S + arr * KTILE + r * VSTR + c8 * 8);
            const __half* src;
            if (arr == 0)      src = Kgh + (size_t)(kt + r) * DKH + c8 * 8;
            else if (arr == 1) src = Kgl + (size_t)(kt + r) * DKH + c8 * 8;
            else if (arr == 2) src = Vgh + (size_t)r * SEQ + kt + c8 * 8;
            else               src = Vgl + (size_t)r * SEQ + kt + c8 * 8;
            cpa16(dst, src);
        }
    };

    // ---- prologue: Q tile + stage 0 (group 0), stage 1 (group 1) ----
    #pragma unroll
    for (int i = 0; i < 8; i++) {
        const int ci = tid + i * 256;          // 0..2047
        const int arr = ci >> 10;              // 0 Qh, 1 Ql
        const int c = ci & 1023;
        const int r = c >> 3, c8 = c & 7;
        const __half* src = (arr ? Qgl : Qgh) + (size_t)(q0 + r) * DKH + c8 * 8;
        cpa16(smem_u32((arr ? sQl : sQh) + r * VSTR + c8 * 8), src);
    }
    issue_kv(0, 0);
    cpa_commit();
    issue_kv(1, 1);
    cpa_commit();

    // ---- safe-max bounds for this thread's two rows ----
    const int r0 = 16 * w + (lane >> 2);
    float nq0 = 0.f, nq1 = 0.f;
    {
        const uint4* p0 = (const uint4*)(Qgh + (size_t)(q0 + r0) * DKH);
        const uint4* p1 = (const uint4*)(Qgh + (size_t)(q0 + r0 + 8) * DKH);
        #pragma unroll
        for (int i = 0; i < 8; i++) {
            uint4 u0 = p0[i], u1 = p1[i];
            uint32_t a0[4] = {u0.x, u0.y, u0.z, u0.w};
            uint32_t a1[4] = {u1.x, u1.y, u1.z, u1.w};
            #pragma unroll
            for (int j = 0; j < 4; j++) {
                float2 f0 = __half22float2(*(__half2*)&a0[j]);
                float2 f1 = __half22float2(*(__half2*)&a1[j]);
                nq0 += f0.x * f0.x + f0.y * f0.y;
                nq1 += f1.x * f1.x + f1.y * f1.y;
            }
        }
    }
    const float mk = maxk[bh];
    const float M20 = sqrtf(nq0) * mk - SHIFT_LOG2;
    const float M21 = sqrtf(nq1) * mk - SHIFT_LOG2;

    float o[8][4] = {};
    float lsum0 = 0.f, lsum1 = 0.f;

    for (int t = 0; t < NT; t++) {
        if (t + 1 < NT) {
            issue_kv(t + 1, (t + 1) & 1);
            cpa_commit();
            asm volatile("cp.async.wait_group 1;");
        } else {
            asm volatile("cp.async.wait_group 0;");
        }
        __syncthreads();

        const __half* S = sStage + (t & 1) * STG;
        const __half* sKh = S;
        const __half* sKl = S + KTILE;
        const __half* sVh = S + 2 * KTILE;
        const __half* sVl = S + 3 * KTILE;

        // ---- S = Q K^T (3-pass), A from SMEM ----
        float s[8][4] = {};
        #pragma unroll
        for (int ks = 0; ks < 4; ks++) {
            uint32_t ahi[4], alo[4];
            const int arow = 16 * w + (blk & 1) * 8 + lrow;
            const int acol = ks * 16 + (blk >> 1) * 8;
            ldsm_x4(smem_u32(sQh + arow * VSTR + acol), ahi[0], ahi[1], ahi[2], ahi[3]);
            ldsm_x4(smem_u32(sQl + arow * VSTR + acol), alo[0], alo[1], alo[2], alo[3]);
            #pragma unroll
            for (int np = 0; np < 4; np++) {
                const int brow = np * 16 + (blk >> 1) * 8 + lrow;
                const int bcol = ks * 16 + (blk & 1) * 8;
                uint32_t bh0, bh1, bh2, bh3, bl0, bl1, bl2, bl3;
                ldsm_x4(smem_u32(sKh + brow * VSTR + bcol), bh0, bh1, bh2, bh3);
                ldsm_x4(smem_u32(sKl + brow * VSTR + bcol), bl0, bl1, bl2, bl3);
                mma4(s[2 * np],     ahi, bh0, bh1);
                mma4(s[2 * np + 1], ahi, bh2, bh3);
                mma4(s[2 * np],     ahi, bl0, bl1);
                mma4(s[2 * np + 1], ahi, bl2, bl3);
                mma4(s[2 * np],     alo, bh0, bh1);
                mma4(s[2 * np + 1], alo, bh2, bh3);
            }
        }

        // ---- per-16-col chunk: exp2 (fixed bound), split, PV mma ----
        #pragma unroll
        for (int ks = 0; ks < 4; ks++) {
            float e00 = ex2(s[2 * ks][0] - M20);
            float e01 = ex2(s[2 * ks][1] - M20);
            float e02 = ex2(s[2 * ks][2] - M21);
            float e03 = ex2(s[2 * ks][3] - M21);
            float e10 = ex2(s[2 * ks + 1][0] - M20);
            float e11 = ex2(s[2 * ks + 1][1] - M20);
            float e12 = ex2(s[2 * ks + 1][2] - M21);
            float e13 = ex2(s[2 * ks + 1][3] - M21);
            lsum0 += e00 + e01 + e10 + e11;
            lsum1 += e02 + e03 + e12 + e13;

            uint32_t ph4[4], pl4[4];
            split2(e00, e01, ph4[0], pl4[0]);
            split2(e02, e03, ph4[1], pl4[1]);
            split2(e10, e11, ph4[2], pl4[2]);
            split2(e12, e13, ph4[3], pl4[3]);

            #pragma unroll
            for (int npd = 0; npd < 4; npd++) {
                const int vrow = npd * 16 + (blk >> 1) * 8 + lrow;  // d rows
                const int vcol = ks * 16 + (blk & 1) * 8;           // kv cols
                uint32_t vh0, vh1, vh2, vh3, vl0, vl1, vl2, vl3;
                ldsm_x4(smem_u32(sVh + vrow * VSTR + vcol), vh0, vh1, vh2, vh3);
                ldsm_x4(smem_u32(sVl + vrow * VSTR + vcol), vl0, vl1, vl2, vl3);
                mma4(o[2 * npd],     ph4, vh0, vh1);
                mma4(o[2 * npd + 1], ph4, vh2, vh3);
                mma4(o[2 * npd],     ph4, vl0, vl1);
                mma4(o[2 * npd + 1], ph4, vl2, vl3);
                mma4(o[2 * npd],     pl4, vh0, vh1);
                mma4(o[2 * npd + 1], pl4, vh2, vh3);
            }
        }
        __syncthreads();
    }

    // ---- epilogue: reduce row sums across the 4 owning threads ----
    lsum0 += __shfl_xor_sync(0xffffffffu, lsum0, 1);
    lsum0 += __shfl_xor_sync(0xffffffffu, lsum0, 2);
    lsum1 += __shfl_xor_sync(0xffffffffu, lsum1, 1);
    lsum1 += __shfl_xor_sync(0xffffffffu, lsum1, 2);
    const float inv0 = 1.f / lsum0, inv1 = 1.f / lsum1;

    const int b = bh / NUM_HEADS, h = bh % NUM_HEADS;
    #pragma unroll
    for (int nt = 0; nt < 8; nt++) {
        const int d = h * DKH + nt * 8 + (lane & 3) * 2;
        size_t p0 = (size_t)(b * SEQ + q0 + r0) * D_MODEL + d;
        size_t p1 = (size_t)(b * SEQ + q0 + r0 + 8) * D_MODEL + d;
        uint32_t h0u, l0u, h1u, l1u;
        split2(o[nt][0] * inv0, o[nt][1] * inv0, h0u, l0u);
        split2(o[nt][2] * inv1, o[nt][3] * inv1, h1u, l1u);
        *(uint32_t*)(Oh_ + p0) = h0u;
        *(uint32_t*)(Ol_ + p0) = l0u;
        *(uint32_t*)(Oh_ + p1) = h1u;
        *(uint32_t*)(Ol_ + p1) = l1u;
    }
}

// =========================================================================
// Launch
// =========================================================================
extern "C" void kernel_launch(void* const* d_in, const int* in_sizes, int n_in,
                              void* d_out, int out_size)
{
    const float* query = (const float*)d_in[0];
    const float* key   = (const float*)d_in[1];
    const float* value = (const float*)d_in[2];
    const float* Wq = (const float*)d_in[3];
    const float* bq = (const float*)d_in[4];
    const float* Wk = (const float*)d_in[5];
    const float* bk = (const float*)d_in[6];
    const float* Wv = (const float*)d_in[7];
    const float* bv = (const float*)d_in[8];
    const float* Wo = (const float*)d_in[9];
    const float* bo = (const float*)d_in[10];
    float* out = (float*)d_out;

    __half *qh, *ql, *kh, *kl, *vth, *vtl, *xh, *xl, *wh, *wl, *ath, *atl;
    float* maxk;
    cudaGetSymbolAddress((void**)&qh,  g_qh);  cudaGetSymbolAddress((void**)&ql,  g_ql);
    cudaGetSymbolAddress((void**)&kh,  g_kh);  cudaGetSymbolAddress((void**)&kl,  g_kl);
    cudaGetSymbolAddress((void**)&vth, g_vth); cudaGetSymbolAddress((void**)&vtl, g_vtl);
    cudaGetSymbolAddress((void**)&xh,  g_xh);  cudaGetSymbolAddress((void**)&xl,  g_xl);
    cudaGetSymbolAddress((void**)&wh,  g_wh);  cudaGetSymbolAddress((void**)&wl,  g_wl);
    cudaGetSymbolAddress((void**)&ath, g_ath); cudaGetSymbolAddress((void**)&atl, g_atl);
    cudaGetSymbolAddress((void**)&maxk, g_maxk);

    cudaFuncSetAttribute(attn_sm, cudaFuncAttributeMaxDynamicSharedMemorySize, ATT_SMEM);

    const int NX4 = MROWS * D_MODEL / 4;
    const int NW4 = D_MODEL * D_MODEL / 4;
    dim3 ggrid(D_MODEL / GBN, MROWS / GBM);   // (12, 64)

    // Q projection (scaled log2e/8)
    cvt_split<<<1184, 256>>>(query, xh, xl, NX4);
    cvt_split<<<592, 256>>>(Wq, wh, wl, NW4);
    gemm_h<<<ggrid, 256>>>(xh, xl, wh, wl, bq, nullptr, qh, ql, 2);
    // K projection
    cvt_split<<<1184, 256>>>(key, xh, xl, NX4);
    cvt_split<<<592, 256>>>(Wk, wh, wl, NW4);
    gemm_h<<<ggrid, 256>>>(xh, xl, wh, wl, bk, nullptr, kh, kl, 1);
    kmax_kernel<<<NBH, 256>>>(kh, maxk);
    // V projection (transposed output)
    cvt_split<<<1184, 256>>>(value, xh, xl, NX4);
    cvt_split<<<592, 256>>>(Wv, wh, wl, NW4);
    gemm_h<<<ggrid, 256>>>(xh, xl, wh, wl, bv, nullptr, vth, vtl, 3);

    // attention (safe-max, mma.sync)
    dim3 agrid(SEQ / QT, NBH);   // (32, 24)
    attn_sm<<<agrid, 256, ATT_SMEM>>>(qh, ql, kh, kl, vth, vtl, maxk, ath, atl);

    // output projection
    cvt_split<<<592, 256>>>(Wo, wh, wl, NW4);
    gemm_h<<<ggrid, 256>>>(ath, atl, wh, wl, bo, out, nullptr, nullptr, 0);
}

// round 6
// speedup vs baseline: 4.4677x; 1.2574x over previous
#include <cuda_runtime.h>
#include <cuda_fp16.h>
#include <math.h>
#include <stdint.h>

#define D_MODEL 768
#define NUM_HEADS 12
#define DKH 64
#define BATCH 2
#define SEQ 4096
#define MROWS (BATCH * SEQ)   // 8192
#define NBH (BATCH * NUM_HEADS)

// q prescale folds 1/sqrt(64) and log2(e):  log2(e)/8
#define QSCALE 0.18033688011112042f
// 4 nats in log2 units
#define SHIFT_LOG2 5.770780163555855f

// ---------------- scratch (device globals; no allocation) ----------------
#define QKV_ELEMS ((size_t)NBH * SEQ * DKH)
__device__ __half g_qh[QKV_ELEMS], g_ql[QKV_ELEMS];       // [bh][s][d], prescaled log2e/8
__device__ __half g_kh[QKV_ELEMS];                        // [bh][s][d] (hi only)
__device__ __half g_vth[QKV_ELEMS];                       // [bh][d][s] (hi only)
__device__ __half g_xh[(size_t)MROWS * D_MODEL], g_xl[(size_t)MROWS * D_MODEL];
__device__ __half g_wh[(size_t)D_MODEL * D_MODEL], g_wl[(size_t)D_MODEL * D_MODEL];
__device__ __half g_ath[(size_t)MROWS * D_MODEL], g_atl[(size_t)MROWS * D_MODEL];
__device__ float  g_maxk[NBH];

// ---------------- helpers ----------------
__device__ __forceinline__ uint32_t smem_u32(const void* p) {
    return (uint32_t)__cvta_generic_to_shared(p);
}
__device__ __forceinline__ uint32_t pk(__half2 h) {
    union { __half2 h; uint32_t u; } x; x.h = h; return x.u;
}
__device__ __forceinline__ void ldsm_x4(uint32_t a, uint32_t& r0, uint32_t& r1,
                                        uint32_t& r2, uint32_t& r3) {
    asm volatile("ldmatrix.sync.aligned.m8n8.x4.shared.b16 {%0,%1,%2,%3}, [%4];"
                 : "=r"(r0), "=r"(r1), "=r"(r2), "=r"(r3) : "r"(a));
}
__device__ __forceinline__ void mma4(float* c, const uint32_t* a, uint32_t b0, uint32_t b1) {
    asm volatile(
        "mma.sync.aligned.m16n8k16.row.col.f32.f16.f16.f32 "
        "{%0,%1,%2,%3}, {%4,%5,%6,%7}, {%8,%9}, {%0,%1,%2,%3};"
        : "+f"(c[0]), "+f"(c[1]), "+f"(c[2]), "+f"(c[3])
        : "r"(a[0]), "r"(a[1]), "r"(a[2]), "r"(a[3]), "r"(b0), "r"(b1));
}
__device__ __forceinline__ void split2(float x, float y, uint32_t& hi, uint32_t& lo) {
    __half2 h = __floats2half2_rn(x, y);
    float rx = x - __half2float(__low2half(h));
    float ry = y - __half2float(__high2half(h));
    hi = pk(h);
    lo = pk(__floats2half2_rn(rx, ry));
}
__device__ __forceinline__ void cpa16(uint32_t s, const void* g) {
    asm volatile("cp.async.cg.shared.global [%0], [%1], 16;" :: "r"(s), "l"(g));
}
__device__ __forceinline__ void cpa_commit() {
    asm volatile("cp.async.commit_group;");
}
__device__ __forceinline__ float ex2(float x) {
    float y;
    asm("ex2.approx.f32 %0, %1;" : "=f"(y) : "f"(x));
    return y;
}

// =========================================================================
// Converter: fp32 -> (half hi, half lo)
// =========================================================================
__global__ __launch_bounds__(256) void cvt_split(
    const float* __restrict__ x, __half* __restrict__ hi,
    __half* __restrict__ lo, int n4)
{
    uint32_t* hio = (uint32_t*)hi;
    uint32_t* loo = (uint32_t*)lo;
    for (int i = blockIdx.x * 256 + threadIdx.x; i < n4; i += gridDim.x * 256) {
        float4 f = ((const float4*)x)[i];
        uint32_t h0, l0, h1, l1;
        split2(f.x, f.y, h0, l0);
        split2(f.z, f.w, h1, l1);
        hio[2 * i] = h0; hio[2 * i + 1] = h1;
        loo[2 * i] = l0; loo[2 * i + 1] = l1;
    }
}

// =========================================================================
// Per-bh max ||k_row|| (hi halves; slack absorbed by the -4nat shift)
// =========================================================================
__global__ __launch_bounds__(256) void kmax_kernel(const __half* __restrict__ kh,
                                                   float* __restrict__ maxk)
{
    __shared__ float red[256];
    const int bh = blockIdx.x;
    const __half* base = kh + (size_t)bh * SEQ * DKH;
    float mx = 0.f;
    for (int r = threadIdx.x; r < SEQ; r += 256) {
        const uint4* p = (const uint4*)(base + (size_t)r * DKH);
        float s = 0.f;
        #pragma unroll
        for (int i = 0; i < 8; i++) {
            uint4 u = p[i];
            uint32_t ws[4] = {u.x, u.y, u.z, u.w};
            #pragma unroll
            for (int j = 0; j < 4; j++) {
                float2 f = __half22float2(*(__half2*)&ws[j]);
                s += f.x * f.x + f.y * f.y;
            }
        }
        mx = fmaxf(mx, s);
    }
    red[threadIdx.x] = mx;
    __syncthreads();
    for (int st = 128; st > 0; st >>= 1) {
        if (threadIdx.x < st) red[threadIdx.x] = fmaxf(red[threadIdx.x], red[threadIdx.x + st]);
        __syncthreads();
    }
    if (threadIdx.x == 0) maxk[bh] = sqrtf(red[0]);
}

// =========================================================================
// GEMM (3-pass fp16 mma.sync), pre-split inputs, cp.async double-buffered.
// mode 0: fp32 flat; mode 1: head-split halves; mode 2: +QSCALE;
// mode 3: head-split transposed.  outl==nullptr -> hi-only stores.
// =========================================================================
#define GBM 128
#define GBN 64
#define GKC 16
#define GSTR 24
#define NKC (D_MODEL / GKC)
#define GS_A (GBM * GSTR)
#define GS_B (GBN * GSTR)
#define GS_STAGE (2 * GS_A + 2 * GS_B)

__global__ __launch_bounds__(256, 2) void gemm_h(
    const __half* __restrict__ Ah, const __half* __restrict__ Al,
    const __half* __restrict__ Wh, const __half* __restrict__ Wl,
    const float* __restrict__ bias, float* __restrict__ outf,
    __half* __restrict__ outh, __half* __restrict__ outl, int mode)
{
    __shared__ __align__(16) __half gs[2 * GS_STAGE];

    const int tid = threadIdx.x;
    const int w = tid >> 5;
    const int lane = tid & 31;
    const int row0 = blockIdx.y * GBM;
    const int col0 = blockIdx.x * GBN;

    const int ar = tid >> 1;
    const int aoff = (tid & 1) * 8;
    const int br = tid >> 1;
    const int blk = lane >> 3;
    const int lrow = lane & 7;

    float acc[8][4] = {};

    auto issue = [&](int kc, int st) {
        const int k0 = kc * GKC;
        __half* S = gs + st * GS_STAGE;
        uint32_t dA = smem_u32(S + ar * GSTR + aoff);
        cpa16(dA,            Ah + (size_t)(row0 + ar) * D_MODEL + k0 + aoff);
        cpa16(dA + GS_A * 2, Al + (size_t)(row0 + ar) * D_MODEL + k0 + aoff);
        if (tid < 128) {
            uint32_t dB = smem_u32(S + 2 * GS_A + br * GSTR + aoff);
            cpa16(dB,            Wh + (size_t)(col0 + br) * D_MODEL + k0 + aoff);
            cpa16(dB + GS_B * 2, Wl + (size_t)(col0 + br) * D_MODEL + k0 + aoff);
        }
    };

    issue(0, 0);
    cpa_commit();

    for (int kc = 0; kc < NKC; kc++) {
        if (kc + 1 < NKC) {
            issue(kc + 1, (kc + 1) & 1);
            cpa_commit();
            asm volatile("cp.async.wait_group 1;");
        } else {
            asm volatile("cp.async.wait_group 0;");
        }
        __syncthreads();

        const __half* S = gs + (kc & 1) * GS_STAGE;
        const __half* sAh = S;
        const __half* sAl = S + GS_A;
        const __half* sBh = S + 2 * GS_A;
        const __half* sBl = S + 2 * GS_A + GS_B;

        uint32_t ahi[4], alo[4];
        const int arow = 16 * w + (blk & 1) * 8 + lrow;
        const int acol = (blk >> 1) * 8;
        ldsm_x4(smem_u32(sAh + arow * GSTR + acol), ahi[0], ahi[1], ahi[2], ahi[3]);
        ldsm_x4(smem_u32(sAl + arow * GSTR + acol), alo[0], alo[1], alo[2], alo[3]);

        #pragma unroll
        for (int np = 0; np < 4; np++) {
            const int brow = np * 16 + (blk >> 1) * 8 + lrow;
            const int bcol = (blk & 1) * 8;
            uint32_t bh0, bh1, bh2, bh3, bl0, bl1, bl2, bl3;
            ldsm_x4(smem_u32(sBh + brow * GSTR + bcol), bh0, bh1, bh2, bh3);
            ldsm_x4(smem_u32(sBl + brow * GSTR + bcol), bl0, bl1, bl2, bl3);
            mma4(acc[2 * np],     ahi, bh0, bh1);
            mma4(acc[2 * np + 1], ahi, bh2, bh3);
            mma4(acc[2 * np],     ahi, bl0, bl1);
            mma4(acc[2 * np + 1], ahi, bl2, bl3);
            mma4(acc[2 * np],     alo, bh0, bh1);
            mma4(acc[2 * np + 1], alo, bh2, bh3);
        }
        __syncthreads();
    }

    const float scale = (mode == 2) ? QSCALE : 1.0f;
    const int rloc = 16 * w + (lane >> 2);
    #pragma unroll
    for (int nt = 0; nt < 8; nt++) {
        const int n = col0 + nt * 8 + (lane & 3) * 2;
        const float bx = bias[n], by = bias[n + 1];
        const int m0 = row0 + rloc;
        float o00 = (acc[nt][0] + bx) * scale;
        float o01 = (acc[nt][1] + by) * scale;
        float o10 = (acc[nt][2] + bx) * scale;
        float o11 = (acc[nt][3] + by) * scale;
        if (mode == 0) {
            *(float2*)(outf + (size_t)m0 * D_MODEL + n) = make_float2(o00, o01);
            *(float2*)(outf + (size_t)(m0 + 8) * D_MODEL + n) = make_float2(o10, o11);
        } else {
            const int h = n >> 6, d = n & 63;
            const int b0m = m0 >> 12, s0 = m0 & (SEQ - 1);
            const int b1m = (m0 + 8) >> 12, s1 = (m0 + 8) & (SEQ - 1);
            uint32_t h0u, l0u, h1u, l1u;
            split2(o00, o01, h0u, l0u);
            split2(o10, o11, h1u, l1u);
            if (mode == 3) {
                size_t p0 = ((size_t)(b0m * NUM_HEADS + h) * DKH + d) * SEQ + s0;
                size_t p1 = ((size_t)(b1m * NUM_HEADS + h) * DKH + d) * SEQ + s1;
                __half2 H0 = *(__half2*)&h0u, H1 = *(__half2*)&h1u;
                outh[p0] = __low2half(H0);  outh[p0 + SEQ] = __high2half(H0);
                outh[p1] = __low2half(H1);  outh[p1 + SEQ] = __high2half(H1);
                if (outl) {
                    __half2 L0 = *(__half2*)&l0u, L1 = *(__half2*)&l1u;
                    outl[p0] = __low2half(L0);  outl[p0 + SEQ] = __high2half(L0);
                    outl[p1] = __low2half(L1);  outl[p1 + SEQ] = __high2half(L1);
                }
            } else {
                size_t p0 = ((size_t)(b0m * NUM_HEADS + h) * SEQ + s0) * DKH + d;
                size_t p1 = ((size_t)(b1m * NUM_HEADS + h) * SEQ + s1) * DKH + d;
                *(uint32_t*)(outh + p0) = h0u;
                *(uint32_t*)(outh + p1) = h1u;
                if (outl) {
                    *(uint32_t*)(outl + p0) = l0u;
                    *(uint32_t*)(outl + p1) = l1u;
                }
            }
        }
    }
}

// =========================================================================
// Flash attention, 2-pass mma.sync (A-corrected), SAFE-MAX softmax.
// K/V hi-only. 256 thr / 8 warps, Q tile 128 (SMEM), KV tile 64, 2-stage.
// Dynamic smem 73728 B; 2 CTAs/SM.
// =========================================================================
#define QT 128
#define KVT 64
#define VSTR 72
#define QTILE (QT * VSTR)            // halves
#define KTILE (KVT * VSTR)
#define STG (2 * KTILE)              // Kh,Vh per stage
#define ATT_SMEM ((2 * QTILE + 2 * STG) * 2)   // 73728 B
#define NT (SEQ / KVT)               // 64

__global__ __launch_bounds__(256, 2) void attn_sm(
    const __half* __restrict__ Qh_, const __half* __restrict__ Ql_,
    const __half* __restrict__ Kh_, const __half* __restrict__ VTh_,
    const float* __restrict__ maxk,
    __half* __restrict__ Oh_, __half* __restrict__ Ol_)
{
    extern __shared__ __align__(16) __half sm[];
    __half* sQh = sm;
    __half* sQl = sm + QTILE;
    __half* sStage = sm + 2 * QTILE;

    const int tid = threadIdx.x;
    const int w = tid >> 5;
    const int lane = tid & 31;
    const int q0 = blockIdx.x * QT;
    const int bh = blockIdx.y;
    const int blk = lane >> 3;
    const int lrow = lane & 7;

    const __half* Qgh = Qh_ + (size_t)bh * SEQ * DKH;
    const __half* Qgl = Ql_ + (size_t)bh * SEQ * DKH;
    const __half* Kgh = Kh_ + (size_t)bh * SEQ * DKH;
    const __half* Vgh = VTh_ + (size_t)bh * DKH * SEQ;

    // ---- K/V stage loader: 1024 cp.async of 16B ----
    auto issue_kv = [&](int t, int st) {
        const int kt = t * KVT;
        __half* S = sStage + st * STG;
        #pragma unroll
        for (int i = 0; i < 4; i++) {
            const int ci = tid + i * 256;      // 0..1023
            const int arr = ci >> 9;           // 0 Kh, 1 Vh
            const int c = ci & 511;
            const int r = c >> 3, c8 = c & 7;
            const uint32_t dst = smem_u32(S + arr * KTILE + r * VSTR + c8 * 8);
            const __half* src = arr ? (Vgh + (size_t)r * SEQ + kt + c8 * 8)
                                    : (Kgh + (size_t)(kt + r) * DKH + c8 * 8);
            cpa16(dst, src);
        }
    };

    // ---- prologue: Q tile (hi+lo) + stages 0,1 ----
    #pragma unroll
    for (int i = 0; i < 8; i++) {
        const int ci = tid + i * 256;          // 0..2047
        const int arr = ci >> 10;              // 0 Qh, 1 Ql
        const int c = ci & 1023;
        const int r = c >> 3, c8 = c & 7;
        const __half* src = (arr ? Qgl : Qgh) + (size_t)(q0 + r) * DKH + c8 * 8;
        cpa16(smem_u32((arr ? sQl : sQh) + r * VSTR + c8 * 8), src);
    }
    issue_kv(0, 0);
    cpa_commit();
    issue_kv(1, 1);
    cpa_commit();

    // ---- safe-max bounds for this thread's two rows ----
    const int r0 = 16 * w + (lane >> 2);
    float nq0 = 0.f, nq1 = 0.f;
    {
        const uint4* p0 = (const uint4*)(Qgh + (size_t)(q0 + r0) * DKH);
        const uint4* p1 = (const uint4*)(Qgh + (size_t)(q0 + r0 + 8) * DKH);
        #pragma unroll
        for (int i = 0; i < 8; i++) {
            uint4 u0 = p0[i], u1 = p1[i];
            uint32_t a0[4] = {u0.x, u0.y, u0.z, u0.w};
            uint32_t a1[4] = {u1.x, u1.y, u1.z, u1.w};
            #pragma unroll
            for (int j = 0; j < 4; j++) {
                float2 f0 = __half22float2(*(__half2*)&a0[j]);
                float2 f1 = __half22float2(*(__half2*)&a1[j]);
                nq0 += f0.x * f0.x + f0.y * f0.y;
                nq1 += f1.x * f1.x + f1.y * f1.y;
            }
        }
    }
    const float mk = maxk[bh];
    const float M20 = sqrtf(nq0) * mk - SHIFT_LOG2;
    const float M21 = sqrtf(nq1) * mk - SHIFT_LOG2;

    float o[8][4] = {};
    float lsum0 = 0.f, lsum1 = 0.f;

    for (int t = 0; t < NT; t++) {
        if (t + 1 < NT) {
            issue_kv(t + 1, (t + 1) & 1);
            cpa_commit();
            asm volatile("cp.async.wait_group 1;");
        } else {
            asm volatile("cp.async.wait_group 0;");
        }
        __syncthreads();

        const __half* S = sStage + (t & 1) * STG;
        const __half* sKh = S;
        const __half* sVh = S + KTILE;

        // ---- S = Q K^T (2-pass: (qhi+qlo) * khi) ----
        float s[8][4] = {};
        #pragma unroll
        for (int ks = 0; ks < 4; ks++) {
            uint32_t ahi[4], alo[4];
            const int arow = 16 * w + (blk & 1) * 8 + lrow;
            const int acol = ks * 16 + (blk >> 1) * 8;
            ldsm_x4(smem_u32(sQh + arow * VSTR + acol), ahi[0], ahi[1], ahi[2], ahi[3]);
            ldsm_x4(smem_u32(sQl + arow * VSTR + acol), alo[0], alo[1], alo[2], alo[3]);
            #pragma unroll
            for (int np = 0; np < 4; np++) {
                const int brow = np * 16 + (blk >> 1) * 8 + lrow;
                const int bcol = ks * 16 + (blk & 1) * 8;
                uint32_t bh0, bh1, bh2, bh3;
                ldsm_x4(smem_u32(sKh + brow * VSTR + bcol), bh0, bh1, bh2, bh3);
                mma4(s[2 * np],     ahi, bh0, bh1);
                mma4(s[2 * np + 1], ahi, bh2, bh3);
                mma4(s[2 * np],     alo, bh0, bh1);
                mma4(s[2 * np + 1], alo, bh2, bh3);
            }
        }

        // ---- per-16-col chunk: exp2 (fixed bound), split, PV (2-pass) ----
        #pragma unroll
        for (int ks = 0; ks < 4; ks++) {
            float e00 = ex2(s[2 * ks][0] - M20);
            float e01 = ex2(s[2 * ks][1] - M20);
            float e02 = ex2(s[2 * ks][2] - M21);
            float e03 = ex2(s[2 * ks][3] - M21);
            float e10 = ex2(s[2 * ks + 1][0] - M20);
            float e11 = ex2(s[2 * ks + 1][1] - M20);
            float e12 = ex2(s[2 * ks + 1][2] - M21);
            float e13 = ex2(s[2 * ks + 1][3] - M21);
            lsum0 += e00 + e01 + e10 + e11;
            lsum1 += e02 + e03 + e12 + e13;

            uint32_t ph4[4], pl4[4];
            split2(e00, e01, ph4[0], pl4[0]);
            split2(e02, e03, ph4[1], pl4[1]);
            split2(e10, e11, ph4[2], pl4[2]);
            split2(e12, e13, ph4[3], pl4[3]);

            #pragma unroll
            for (int npd = 0; npd < 4; npd++) {
                const int vrow = npd * 16 + (blk >> 1) * 8 + lrow;  // d rows
                const int vcol = ks * 16 + (blk & 1) * 8;           // kv cols
                uint32_t vh0, vh1, vh2, vh3;
                ldsm_x4(smem_u32(sVh + vrow * VSTR + vcol), vh0, vh1, vh2, vh3);
                mma4(o[2 * npd],     ph4, vh0, vh1);
                mma4(o[2 * npd + 1], ph4, vh2, vh3);
                mma4(o[2 * npd],     pl4, vh0, vh1);
                mma4(o[2 * npd + 1], pl4, vh2, vh3);
            }
        }
        __syncthreads();
    }

    // ---- epilogue ----
    lsum0 += __shfl_xor_sync(0xffffffffu, lsum0, 1);
    lsum0 += __shfl_xor_sync(0xffffffffu, lsum0, 2);
    lsum1 += __shfl_xor_sync(0xffffffffu, lsum1, 1);
    lsum1 += __shfl_xor_sync(0xffffffffu, lsum1, 2);
    const float inv0 = 1.f / lsum0, inv1 = 1.f / lsum1;

    const int b = bh / NUM_HEADS, h = bh % NUM_HEADS;
    #pragma unroll
    for (int nt = 0; nt < 8; nt++) {
        const int d = h * DKH + nt * 8 + (lane & 3) * 2;
        size_t p0 = (size_t)(b * SEQ + q0 + r0) * D_MODEL + d;
        size_t p1 = (size_t)(b * SEQ + q0 + r0 + 8) * D_MODEL + d;
        uint32_t h0u, l0u, h1u, l1u;
        split2(o[nt][0] * inv0, o[nt][1] * inv0, h0u, l0u);
        split2(o[nt][2] * inv1, o[nt][3] * inv1, h1u, l1u);
        *(uint32_t*)(Oh_ + p0) = h0u;
        *(uint32_t*)(Ol_ + p0) = l0u;
        *(uint32_t*)(Oh_ + p1) = h1u;
        *(uint32_t*)(Ol_ + p1) = l1u;
    }
}

// =========================================================================
// Launch
// =========================================================================
extern "C" void kernel_launch(void* const* d_in, const int* in_sizes, int n_in,
                              void* d_out, int out_size)
{
    const float* query = (const float*)d_in[0];
    const float* key   = (const float*)d_in[1];
    const float* value = (const float*)d_in[2];
    const float* Wq = (const float*)d_in[3];
    const float* bq = (const float*)d_in[4];
    const float* Wk = (const float*)d_in[5];
    const float* bk = (const float*)d_in[6];
    const float* Wv = (const float*)d_in[7];
    const float* bv = (const float*)d_in[8];
    const float* Wo = (const float*)d_in[9];
    const float* bo = (const float*)d_in[10];
    float* out = (float*)d_out;

    __half *qh, *ql, *kh, *vth, *xh, *xl, *wh, *wl, *ath, *atl;
    float* maxk;
    cudaGetSymbolAddress((void**)&qh,  g_qh);  cudaGetSymbolAddress((void**)&ql,  g_ql);
    cudaGetSymbolAddress((void**)&kh,  g_kh);
    cudaGetSymbolAddress((void**)&vth, g_vth);
    cudaGetSymbolAddress((void**)&xh,  g_xh);  cudaGetSymbolAddress((void**)&xl,  g_xl);
    cudaGetSymbolAddress((void**)&wh,  g_wh);  cudaGetSymbolAddress((void**)&wl,  g_wl);
    cudaGetSymbolAddress((void**)&ath, g_ath); cudaGetSymbolAddress((void**)&atl, g_atl);
    cudaGetSymbolAddress((void**)&maxk, g_maxk);

    cudaFuncSetAttribute(attn_sm, cudaFuncAttributeMaxDynamicSharedMemorySize, ATT_SMEM);

    const int NX4 = MROWS * D_MODEL / 4;
    const int NW4 = D_MODEL * D_MODEL / 4;
    dim3 ggrid(D_MODEL / GBN, MROWS / GBM);   // (12, 64)

    // Q projection (scaled log2e/8), hi+lo out
    cvt_split<<<1184, 256>>>(query, xh, xl, NX4);
    cvt_split<<<592, 256>>>(Wq, wh, wl, NW4);
    gemm_h<<<ggrid, 256>>>(xh, xl, wh, wl, bq, nullptr, qh, ql, 2);
    // K projection, hi only
    cvt_split<<<1184, 256>>>(key, xh, xl, NX4);
    cvt_split<<<592, 256>>>(Wk, wh, wl, NW4);
    gemm_h<<<ggrid, 256>>>(xh, xl, wh, wl, bk, nullptr, kh, nullptr, 1);
    kmax_kernel<<<NBH, 256>>>(kh, maxk);
    // V projection (transposed), hi only
    cvt_split<<<1184, 256>>>(value, xh, xl, NX4);
    cvt_split<<<592, 256>>>(Wv, wh, wl, NW4);
    gemm_h<<<ggrid, 256>>>(xh, xl, wh, wl, bv, nullptr, vth, nullptr, 3);

    // attention (safe-max, 2-pass)
    dim3 agrid(SEQ / QT, NBH);   // (32, 24)
    attn_sm<<<agrid, 256, ATT_SMEM>>>(qh, ql, kh, vth, maxk, ath, atl);

    // output projection (3-pass)
    cvt_split<<<592, 256>>>(Wo, wh, wl, NW4);
    gemm_h<<<ggrid, 256>>>(ath, atl, wh, wl, bo, out, nullptr, nullptr, 0);
}

// round 7
// speedup vs baseline: 4.9092x; 1.0988x over previous
#include <cuda_runtime.h>
#include <cuda_fp16.h>
#include <math.h>
#include <stdint.h>

#define D_MODEL 768
#define NUM_HEADS 12
#define DKH 64
#define BATCH 2
#define SEQ 4096
#define MROWS (BATCH * SEQ)   // 8192
#define NBH (BATCH * NUM_HEADS)

// q prescale folds 1/sqrt(64) and log2(e):  log2(e)/8
#define QSCALE 0.18033688011112042f
// 4 nats in log2 units
#define SHIFT_LOG2 5.770780163555855f

// ---------------- scratch (device globals; no allocation) ----------------
#define QKV_ELEMS ((size_t)NBH * SEQ * DKH)
__device__ __half g_qh[QKV_ELEMS], g_ql[QKV_ELEMS];       // [bh][s][d], prescaled log2e/8
__device__ __half g_kh[QKV_ELEMS];                        // [bh][s][d] (hi only)
__device__ __half g_vth[QKV_ELEMS];                       // [bh][d][s] (hi only)
__device__ __half g_xh[(size_t)MROWS * D_MODEL], g_xl[(size_t)MROWS * D_MODEL];
__device__ __half g_wh[(size_t)D_MODEL * D_MODEL], g_wl[(size_t)D_MODEL * D_MODEL];
__device__ __half g_ath[(size_t)MROWS * D_MODEL], g_atl[(size_t)MROWS * D_MODEL];
__device__ float  g_maxk[NBH];

// ---------------- helpers ----------------
__device__ __forceinline__ uint32_t smem_u32(const void* p) {
    return (uint32_t)__cvta_generic_to_shared(p);
}
__device__ __forceinline__ uint32_t pk(__half2 h) {
    union { __half2 h; uint32_t u; } x; x.h = h; return x.u;
}
__device__ __forceinline__ void ldsm_x4(uint32_t a, uint32_t& r0, uint32_t& r1,
                                        uint32_t& r2, uint32_t& r3) {
    asm volatile("ldmatrix.sync.aligned.m8n8.x4.shared.b16 {%0,%1,%2,%3}, [%4];"
                 : "=r"(r0), "=r"(r1), "=r"(r2), "=r"(r3) : "r"(a));
}
__device__ __forceinline__ void mma4(float* c, const uint32_t* a, uint32_t b0, uint32_t b1) {
    asm volatile(
        "mma.sync.aligned.m16n8k16.row.col.f32.f16.f16.f32 "
        "{%0,%1,%2,%3}, {%4,%5,%6,%7}, {%8,%9}, {%0,%1,%2,%3};"
        : "+f"(c[0]), "+f"(c[1]), "+f"(c[2]), "+f"(c[3])
        : "r"(a[0]), "r"(a[1]), "r"(a[2]), "r"(a[3]), "r"(b0), "r"(b1));
}
__device__ __forceinline__ void split2(float x, float y, uint32_t& hi, uint32_t& lo) {
    __half2 h = __floats2half2_rn(x, y);
    float rx = x - __half2float(__low2half(h));
    float ry = y - __half2float(__high2half(h));
    hi = pk(h);
    lo = pk(__floats2half2_rn(rx, ry));
}
__device__ __forceinline__ void cpa16(uint32_t s, const void* g) {
    asm volatile("cp.async.cg.shared.global [%0], [%1], 16;" :: "r"(s), "l"(g));
}
__device__ __forceinline__ void cpa_commit() {
    asm volatile("cp.async.commit_group;");
}
__device__ __forceinline__ float ex2(float x) {
    float y;
    asm("ex2.approx.f32 %0, %1;" : "=f"(y) : "f"(x));
    return y;
}

// =========================================================================
// Converter: fp32 -> (half hi, half lo)
// =========================================================================
__global__ __launch_bounds__(256) void cvt_split(
    const float* __restrict__ x, __half* __restrict__ hi,
    __half* __restrict__ lo, int n4)
{
    uint32_t* hio = (uint32_t*)hi;
    uint32_t* loo = (uint32_t*)lo;
    for (int i = blockIdx.x * 256 + threadIdx.x; i < n4; i += gridDim.x * 256) {
        float4 f = ((const float4*)x)[i];
        uint32_t h0, l0, h1, l1;
        split2(f.x, f.y, h0, l0);
        split2(f.z, f.w, h1, l1);
        hio[2 * i] = h0; hio[2 * i + 1] = h1;
        loo[2 * i] = l0; loo[2 * i + 1] = l1;
    }
}

// =========================================================================
// Per-bh max ||k_row|| (hi halves; slack absorbed by the -4nat shift)
// =========================================================================
__global__ __launch_bounds__(256) void kmax_kernel(const __half* __restrict__ kh,
                                                   float* __restrict__ maxk)
{
    __shared__ float red[256];
    const int bh = blockIdx.x;
    const __half* base = kh + (size_t)bh * SEQ * DKH;
    float mx = 0.f;
    for (int r = threadIdx.x; r < SEQ; r += 256) {
        const uint4* p = (const uint4*)(base + (size_t)r * DKH);
        float s = 0.f;
        #pragma unroll
        for (int i = 0; i < 8; i++) {
            uint4 u = p[i];
            uint32_t ws[4] = {u.x, u.y, u.z, u.w};
            #pragma unroll
            for (int j = 0; j < 4; j++) {
                float2 f = __half22float2(*(__half2*)&ws[j]);
                s += f.x * f.x + f.y * f.y;
            }
        }
        mx = fmaxf(mx, s);
    }
    red[threadIdx.x] = mx;
    __syncthreads();
    for (int st = 128; st > 0; st >>= 1) {
        if (threadIdx.x < st) red[threadIdx.x] = fmaxf(red[threadIdx.x], red[threadIdx.x + st]);
        __syncthreads();
    }
    if (threadIdx.x == 0) maxk[bh] = sqrtf(red[0]);
}

// =========================================================================
// GEMM, fp16 mma.sync, K-chunk 32, cp.async double-buffered, dynamic smem.
// 3-pass if Wl != nullptr else 2-pass (A-corrected only).
// mode 0: fp32 flat; 1: head-split halves; 2: +QSCALE; 3: transposed.
// outl==nullptr -> hi-only stores.
// =========================================================================
#define GBM 128
#define GBN 64
#define GKC 32
#define GSTR 40
#define NKC (D_MODEL / GKC)      // 24
#define GS_A (GBM * GSTR)        // 5120 halves
#define GS_B (GBN * GSTR)        // 2560 halves
#define GS_STAGE (2 * GS_A + 2 * GS_B)   // 15360 halves
#define GEM_SMEM (2 * GS_STAGE * 2)      // 61440 bytes

__global__ __launch_bounds__(256, 2) void gemm_h(
    const __half* __restrict__ Ah, const __half* __restrict__ Al,
    const __half* __restrict__ Wh, const __half* __restrict__ Wl,
    const float* __restrict__ bias, float* __restrict__ outf,
    __half* __restrict__ outh, __half* __restrict__ outl, int mode)
{
    extern __shared__ __align__(16) __half gs[];

    const int tid = threadIdx.x;
    const int w = tid >> 5;
    const int lane = tid & 31;
    const int row0 = blockIdx.y * GBM;
    const int col0 = blockIdx.x * GBN;
    const int blk = lane >> 3;
    const int lrow = lane & 7;
    const bool useBlo = (Wl != nullptr);

    float acc[8][4] = {};

    auto issue = [&](int kc, int st) {
        const int k0 = kc * GKC;
        __half* S = gs + st * GS_STAGE;
        #pragma unroll
        for (int i = 0; i < 6; i++) {
            const int ci = tid + i * 256;          // 0..1535
            if (ci < 1024) {                       // A hi (0..511) / lo (512..1023)
                const int hl = ci >> 9;
                const int idx = ci & 511;
                const int r = idx >> 2, c4 = idx & 3;
                cpa16(smem_u32(S + hl * GS_A + r * GSTR + c4 * 8),
                      (hl ? Al : Ah) + (size_t)(row0 + r) * D_MODEL + k0 + c4 * 8);
            } else {                               // B hi (1024..1279) / lo (1280..1535)
                const int hl = (ci >> 8) & 1;
                if (hl && !useBlo) continue;
                const int idx = ci & 255;
                const int r = idx >> 2, c4 = idx & 3;
                cpa16(smem_u32(S + 2 * GS_A + hl * GS_B + r * GSTR + c4 * 8),
                      (hl ? Wl : Wh) + (size_t)(col0 + r) * D_MODEL + k0 + c4 * 8);
            }
        }
    };

    issue(0, 0);
    cpa_commit();

    for (int kc = 0; kc < NKC; kc++) {
        if (kc + 1 < NKC) {
            issue(kc + 1, (kc + 1) & 1);
            cpa_commit();
            asm volatile("cp.async.wait_group 1;");
        } else {
            asm volatile("cp.async.wait_group 0;");
        }
        __syncthreads();

        const __half* S = gs + (kc & 1) * GS_STAGE;
        const __half* sAh = S;
        const __half* sAl = S + GS_A;
        const __half* sBh = S + 2 * GS_A;
        const __half* sBl = S + 2 * GS_A + GS_B;

        #pragma unroll
        for (int kk = 0; kk < 2; kk++) {
            uint32_t ahi[4], alo[4];
            const int arow = 16 * w + (blk & 1) * 8 + lrow;
            const int acol = kk * 16 + (blk >> 1) * 8;
            ldsm_x4(smem_u32(sAh + arow * GSTR + acol), ahi[0], ahi[1], ahi[2], ahi[3]);
            ldsm_x4(smem_u32(sAl + arow * GSTR + acol), alo[0], alo[1], alo[2], alo[3]);

            #pragma unroll
            for (int np = 0; np < 4; np++) {
                const int brow = np * 16 + (blk >> 1) * 8 + lrow;
                const int bcol = kk * 16 + (blk & 1) * 8;
                uint32_t bh0, bh1, bh2, bh3;
                ldsm_x4(smem_u32(sBh + brow * GSTR + bcol), bh0, bh1, bh2, bh3);
                mma4(acc[2 * np],     ahi, bh0, bh1);
                mma4(acc[2 * np + 1], ahi, bh2, bh3);
                mma4(acc[2 * np],     alo, bh0, bh1);
                mma4(acc[2 * np + 1], alo, bh2, bh3);
                if (useBlo) {
                    uint32_t bl0, bl1, bl2, bl3;
                    ldsm_x4(smem_u32(sBl + brow * GSTR + bcol), bl0, bl1, bl2, bl3);
                    mma4(acc[2 * np],     ahi, bl0, bl1);
                    mma4(acc[2 * np + 1], ahi, bl2, bl3);
                }
            }
        }
        __syncthreads();
    }

    const float scale = (mode == 2) ? QSCALE : 1.0f;
    const int rloc = 16 * w + (lane >> 2);
    #pragma unroll
    for (int nt = 0; nt < 8; nt++) {
        const int n = col0 + nt * 8 + (lane & 3) * 2;
        const float bx = bias[n], by = bias[n + 1];
        const int m0 = row0 + rloc;
        float o00 = (acc[nt][0] + bx) * scale;
        float o01 = (acc[nt][1] + by) * scale;
        float o10 = (acc[nt][2] + bx) * scale;
        float o11 = (acc[nt][3] + by) * scale;
        if (mode == 0) {
            *(float2*)(outf + (size_t)m0 * D_MODEL + n) = make_float2(o00, o01);
            *(float2*)(outf + (size_t)(m0 + 8) * D_MODEL + n) = make_float2(o10, o11);
        } else {
            const int h = n >> 6, d = n & 63;
            const int b0m = m0 >> 12, s0 = m0 & (SEQ - 1);
            const int b1m = (m0 + 8) >> 12, s1 = (m0 + 8) & (SEQ - 1);
            uint32_t h0u, l0u, h1u, l1u;
            split2(o00, o01, h0u, l0u);
            split2(o10, o11, h1u, l1u);
            if (mode == 3) {
                size_t p0 = ((size_t)(b0m * NUM_HEADS + h) * DKH + d) * SEQ + s0;
                size_t p1 = ((size_t)(b1m * NUM_HEADS + h) * DKH + d) * SEQ + s1;
                __half2 H0 = *(__half2*)&h0u, H1 = *(__half2*)&h1u;
                outh[p0] = __low2half(H0);  outh[p0 + SEQ] = __high2half(H0);
                outh[p1] = __low2half(H1);  outh[p1 + SEQ] = __high2half(H1);
                if (outl) {
                    __half2 L0 = *(__half2*)&l0u, L1 = *(__half2*)&l1u;
                    outl[p0] = __low2half(L0);  outl[p0 + SEQ] = __high2half(L0);
                    outl[p1] = __low2half(L1);  outl[p1 + SEQ] = __high2half(L1);
                }
            } else {
                size_t p0 = ((size_t)(b0m * NUM_HEADS + h) * SEQ + s0) * DKH + d;
                size_t p1 = ((size_t)(b1m * NUM_HEADS + h) * SEQ + s1) * DKH + d;
                *(uint32_t*)(outh + p0) = h0u;
                *(uint32_t*)(outh + p1) = h1u;
                if (outl) {
                    *(uint32_t*)(outl + p0) = l0u;
                    *(uint32_t*)(outl + p1) = l1u;
                }
            }
        }
    }
}

// =========================================================================
// Flash attention, 2-pass mma.sync, SAFE-MAX softmax, KV stage 128
// (2 x 64-kv subtiles per stage). 256 thr / 8 warps, Q tile 128 (SMEM),
// 2-stage cp.async. Dynamic smem 108544 B; 2 CTAs/SM.
// Stage layout: K [128 kv][64 d] stride 72; V^T [64 d][128 kv] stride 136.
// =========================================================================
#define QT 128
#define KVS 128                       // kv per stage
#define QSTR 72
#define VSTR2 136
#define QTILE (QT * QSTR)             // halves
#define KTILE2 (KVS * QSTR)           // 9216 halves
#define VTILE2 (DKH * VSTR2)          // 8704 halves
#define STG2 (KTILE2 + VTILE2)        // 17920 halves
#define ATT_SMEM ((2 * QTILE + 2 * STG2) * 2)   // 108544 B
#define NT2 (SEQ / KVS)               // 32

__global__ __launch_bounds__(256, 2) void attn_sm(
    const __half* __restrict__ Qh_, const __half* __restrict__ Ql_,
    const __half* __restrict__ Kh_, const __half* __restrict__ VTh_,
    const float* __restrict__ maxk,
    __half* __restrict__ Oh_, __half* __restrict__ Ol_)
{
    extern __shared__ __align__(16) __half sm[];
    __half* sQh = sm;
    __half* sQl = sm + QTILE;
    __half* sStage = sm + 2 * QTILE;

    const int tid = threadIdx.x;
    const int w = tid >> 5;
    const int lane = tid & 31;
    const int q0 = blockIdx.x * QT;
    const int bh = blockIdx.y;
    const int blk = lane >> 3;
    const int lrow = lane & 7;

    const __half* Qgh = Qh_ + (size_t)bh * SEQ * DKH;
    const __half* Qgl = Ql_ + (size_t)bh * SEQ * DKH;
    const __half* Kgh = Kh_ + (size_t)bh * SEQ * DKH;
    const __half* Vgh = VTh_ + (size_t)bh * DKH * SEQ;

    // ---- K/V stage loader: 2048 x 16B cp.async, 8 per thread ----
    auto issue_kv = [&](int t, int st) {
        const int kt = t * KVS;
        __half* S = sStage + st * STG2;
        #pragma unroll
        for (int i = 0; i < 8; i++) {
            const int ci = tid + i * 256;      // 0..2047
            if (ci < 1024) {                   // K: 128 rows x 8 ops
                const int r = ci >> 3, c8 = ci & 7;
                cpa16(smem_u32(S + r * QSTR + c8 * 8),
                      Kgh + (size_t)(kt + r) * DKH + c8 * 8);
            } else {                           // V: 64 rows x 16 ops
                const int idx = ci - 1024;
                const int r = idx >> 4, c16 = idx & 15;
                cpa16(smem_u32(S + KTILE2 + r * VSTR2 + c16 * 8),
                      Vgh + (size_t)r * SEQ + kt + c16 * 8);
            }
        }
    };

    // ---- prologue: Q tile (hi+lo) + stages 0,1 ----
    #pragma unroll
    for (int i = 0; i < 8; i++) {
        const int ci = tid + i * 256;          // 0..2047
        const int arr = ci >> 10;              // 0 Qh, 1 Ql
        const int c = ci & 1023;
        const int r = c >> 3, c8 = c & 7;
        const __half* src = (arr ? Qgl : Qgh) + (size_t)(q0 + r) * DKH + c8 * 8;
        cpa16(smem_u32((arr ? sQl : sQh) + r * QSTR + c8 * 8), src);
    }
    issue_kv(0, 0);
    cpa_commit();
    issue_kv(1, 1);
    cpa_commit();

    // ---- safe-max bounds for this thread's two rows ----
    const int r0 = 16 * w + (lane >> 2);
    float nq0 = 0.f, nq1 = 0.f;
    {
        const uint4* p0 = (const uint4*)(Qgh + (size_t)(q0 + r0) * DKH);
        const uint4* p1 = (const uint4*)(Qgh + (size_t)(q0 + r0 + 8) * DKH);
        #pragma unroll
        for (int i = 0; i < 8; i++) {
            uint4 u0 = p0[i], u1 = p1[i];
            uint32_t a0[4] = {u0.x, u0.y, u0.z, u0.w};
            uint32_t a1[4] = {u1.x, u1.y, u1.z, u1.w};
            #pragma unroll
            for (int j = 0; j < 4; j++) {
                float2 f0 = __half22float2(*(__half2*)&a0[j]);
                float2 f1 = __half22float2(*(__half2*)&a1[j]);
                nq0 += f0.x * f0.x + f0.y * f0.y;
                nq1 += f1.x * f1.x + f1.y * f1.y;
            }
        }
    }
    const float mk = maxk[bh];
    const float M20 = sqrtf(nq0) * mk - SHIFT_LOG2;
    const float M21 = sqrtf(nq1) * mk - SHIFT_LOG2;

    float o[8][4] = {};
    float lsum0 = 0.f, lsum1 = 0.f;

    for (int t = 0; t < NT2; t++) {
        if (t + 1 < NT2) {
            issue_kv(t + 1, (t + 1) & 1);
            cpa_commit();
            asm volatile("cp.async.wait_group 1;");
        } else {
            asm volatile("cp.async.wait_group 0;");
        }
        __syncthreads();

        const __half* S = sStage + (t & 1) * STG2;
        const __half* sKh = S;
        const __half* sVh = S + KTILE2;

        #pragma unroll
        for (int j = 0; j < 2; j++) {
            // ---- S = Q K^T (2-pass) over kv subtile j ----
            float s[8][4] = {};
            #pragma unroll
            for (int ks = 0; ks < 4; ks++) {
                uint32_t ahi[4], alo[4];
                const int arow = 16 * w + (blk & 1) * 8 + lrow;
                const int acol = ks * 16 + (blk >> 1) * 8;
                ldsm_x4(smem_u32(sQh + arow * QSTR + acol), ahi[0], ahi[1], ahi[2], ahi[3]);
                ldsm_x4(smem_u32(sQl + arow * QSTR + acol), alo[0], alo[1], alo[2], alo[3]);
                #pragma unroll
                for (int np = 0; np < 4; np++) {
                    const int brow = j * 64 + np * 16 + (blk >> 1) * 8 + lrow;
                    const int bcol = ks * 16 + (blk & 1) * 8;
                    uint32_t bh0, bh1, bh2, bh3;
                    ldsm_x4(smem_u32(sKh + brow * QSTR + bcol), bh0, bh1, bh2, bh3);
                    mma4(s[2 * np],     ahi, bh0, bh1);
                    mma4(s[2 * np + 1], ahi, bh2, bh3);
                    mma4(s[2 * np],     alo, bh0, bh1);
                    mma4(s[2 * np + 1], alo, bh2, bh3);
                }
            }

            // ---- exp2 (fixed bound) + split + PV (2-pass) ----
            #pragma unroll
            for (int ks = 0; ks < 4; ks++) {
                float e00 = ex2(s[2 * ks][0] - M20);
                float e01 = ex2(s[2 * ks][1] - M20);
                float e02 = ex2(s[2 * ks][2] - M21);
                float e03 = ex2(s[2 * ks][3] - M21);
                float e10 = ex2(s[2 * ks + 1][0] - M20);
                float e11 = ex2(s[2 * ks + 1][1] - M20);
                float e12 = ex2(s[2 * ks + 1][2] - M21);
                float e13 = ex2(s[2 * ks + 1][3] - M21);
                lsum0 += e00 + e01 + e10 + e11;
                lsum1 += e02 + e03 + e12 + e13;

                uint32_t ph4[4], pl4[4];
                split2(e00, e01, ph4[0], pl4[0]);
                split2(e02, e03, ph4[1], pl4[1]);
                split2(e10, e11, ph4[2], pl4[2]);
                split2(e12, e13, ph4[3], pl4[3]);

                #pragma unroll
                for (int npd = 0; npd < 4; npd++) {
                    const int vrow = npd * 16 + (blk >> 1) * 8 + lrow;       // d rows
                    const int vcol = j * 64 + ks * 16 + (blk & 1) * 8;       // kv cols
                    uint32_t vh0, vh1, vh2, vh3;
                    ldsm_x4(smem_u32(sVh + vrow * VSTR2 + vcol), vh0, vh1, vh2, vh3);
                    mma4(o[2 * npd],     ph4, vh0, vh1);
                    mma4(o[2 * npd + 1], ph4, vh2, vh3);
                    mma4(o[2 * npd],     pl4, vh0, vh1);
                    mma4(o[2 * npd + 1], pl4, vh2, vh3);
                }
            }
        }
        __syncthreads();
    }

    // ---- epilogue ----
    lsum0 += __shfl_xor_sync(0xffffffffu, lsum0, 1);
    lsum0 += __shfl_xor_sync(0xffffffffu, lsum0, 2);
    lsum1 += __shfl_xor_sync(0xffffffffu, lsum1, 1);
    lsum1 += __shfl_xor_sync(0xffffffffu, lsum1, 2);
    const float inv0 = 1.f / lsum0, inv1 = 1.f / lsum1;

    const int b = bh / NUM_HEADS, h = bh % NUM_HEADS;
    #pragma unroll
    for (int nt = 0; nt < 8; nt++) {
        const int d = h * DKH + nt * 8 + (lane & 3) * 2;
        size_t p0 = (size_t)(b * SEQ + q0 + r0) * D_MODEL + d;
        size_t p1 = (size_t)(b * SEQ + q0 + r0 + 8) * D_MODEL + d;
        uint32_t h0u, l0u, h1u, l1u;
        split2(o[nt][0] * inv0, o[nt][1] * inv0, h0u, l0u);
        split2(o[nt][2] * inv1, o[nt][3] * inv1, h1u, l1u);
        *(uint32_t*)(Oh_ + p0) = h0u;
        *(uint32_t*)(Ol_ + p0) = l0u;
        *(uint32_t*)(Oh_ + p1) = h1u;
        *(uint32_t*)(Ol_ + p1) = l1u;
    }
}

// =========================================================================
// Launch
// =========================================================================
extern "C" void kernel_launch(void* const* d_in, const int* in_sizes, int n_in,
                              void* d_out, int out_size)
{
    const float* query = (const float*)d_in[0];
    const float* key   = (const float*)d_in[1];
    const float* value = (const float*)d_in[2];
    const float* Wq = (const float*)d_in[3];
    const float* bq = (const float*)d_in[4];
    const float* Wk = (const float*)d_in[5];
    const float* bk = (const float*)d_in[6];
    const float* Wv = (const float*)d_in[7];
    const float* bv = (const float*)d_in[8];
    const float* Wo = (const float*)d_in[9];
    const float* bo = (const float*)d_in[10];
    float* out = (float*)d_out;

    __half *qh, *ql, *kh, *vth, *xh, *xl, *wh, *wl, *ath, *atl;
    float* maxk;
    cudaGetSymbolAddress((void**)&qh,  g_qh);  cudaGetSymbolAddress((void**)&ql,  g_ql);
    cudaGetSymbolAddress((void**)&kh,  g_kh);
    cudaGetSymbolAddress((void**)&vth, g_vth);
    cudaGetSymbolAddress((void**)&xh,  g_xh);  cudaGetSymbolAddress((void**)&xl,  g_xl);
    cudaGetSymbolAddress((void**)&wh,  g_wh);  cudaGetSymbolAddress((void**)&wl,  g_wl);
    cudaGetSymbolAddress((void**)&ath, g_ath); cudaGetSymbolAddress((void**)&atl, g_atl);
    cudaGetSymbolAddress((void**)&maxk, g_maxk);

    cudaFuncSetAttribute(attn_sm, cudaFuncAttributeMaxDynamicSharedMemorySize, ATT_SMEM);
    cudaFuncSetAttribute(gemm_h, cudaFuncAttributeMaxDynamicSharedMemorySize, GEM_SMEM);

    const int NX4 = MROWS * D_MODEL / 4;
    const int NW4 = D_MODEL * D_MODEL / 4;
    dim3 ggrid(D_MODEL / GBN, MROWS / GBM);   // (12, 64)

    // Q projection (scaled log2e/8), 3-pass, hi+lo out
    cvt_split<<<1184, 256>>>(query, xh, xl, NX4);
    cvt_split<<<592, 256>>>(Wq, wh, wl, NW4);
    gemm_h<<<ggrid, 256, GEM_SMEM>>>(xh, xl, wh, wl, bq, nullptr, qh, ql, 2);
    // K projection, 2-pass (output fp16-quantized anyway), hi only
    cvt_split<<<1184, 256>>>(key, xh, xl, NX4);
    cvt_split<<<592, 256>>>(Wk, wh, wl, NW4);
    gemm_h<<<ggrid, 256, GEM_SMEM>>>(xh, xl, wh, nullptr, bk, nullptr, kh, nullptr, 1);
    kmax_kernel<<<NBH, 256>>>(kh, maxk);
    // V projection (transposed), 2-pass, hi only
    cvt_split<<<1184, 256>>>(value, xh, xl, NX4);
    cvt_split<<<592, 256>>>(Wv, wh, wl, NW4);
    gemm_h<<<ggrid, 256, GEM_SMEM>>>(xh, xl, wh, nullptr, bv, nullptr, vth, nullptr, 3);

    // attention (safe-max, 2-pass, 128-kv stages)
    dim3 agrid(SEQ / QT, NBH);   // (32, 24)
    attn_sm<<<agrid, 256, ATT_SMEM>>>(qh, ql, kh, vth, maxk, ath, atl);

    // output projection (3-pass)
    cvt_split<<<592, 256>>>(Wo, wh, wl, NW4);
    gemm_h<<<ggrid, 256, GEM_SMEM>>>(ath, atl, wh, wl, bo, out, nullptr, nullptr, 0);
}

// round 8
// speedup vs baseline: 6.2572x; 1.2746x over previous
#include <cuda_runtime.h>
#include <cuda_fp16.h>
#include <math.h>
#include <stdint.h>

#define D_MODEL 768
#define NUM_HEADS 12
#define DKH 64
#define BATCH 2
#define SEQ 4096
#define MROWS (BATCH * SEQ)   // 8192
#define NBH (BATCH * NUM_HEADS)

// q prescale folds 1/sqrt(64) and log2(e):  log2(e)/8
#define QSCALE 0.18033688011112042f
// 4 nats in log2 units
#define SHIFT_LOG2 5.770780163555855f

// ---------------- scratch (device globals; no allocation) ----------------
#define QKV_ELEMS ((size_t)NBH * SEQ * DKH)
#define XN ((size_t)MROWS * D_MODEL)
#define WN ((size_t)D_MODEL * D_MODEL)
__device__ __half g_qh[QKV_ELEMS], g_ql[QKV_ELEMS];       // [bh][s][d], prescaled log2e/8
__device__ __half g_kh[QKV_ELEMS];                        // [bh][s][d] (hi only)
__device__ __half g_vth[QKV_ELEMS];                       // [bh][d][s] (hi only)
__device__ __half g_xqh[XN], g_xql[XN];
__device__ __half g_xkh[XN], g_xkl[XN];
__device__ __half g_xvh[XN], g_xvl[XN];
__device__ __half g_wqh[WN], g_wql[WN];
__device__ __half g_wkh[WN], g_wkl[WN];
__device__ __half g_wvh[WN], g_wvl[WN];
__device__ __half g_woh[WN], g_wol[WN];
__device__ __half g_ath[XN], g_atl[XN];
__device__ float  g_maxk[NBH];

// ---------------- helpers ----------------
__device__ __forceinline__ uint32_t smem_u32(const void* p) {
    return (uint32_t)__cvta_generic_to_shared(p);
}
__device__ __forceinline__ uint32_t pk(__half2 h) {
    union { __half2 h; uint32_t u; } x; x.h = h; return x.u;
}
__device__ __forceinline__ void ldsm_x4(uint32_t a, uint32_t& r0, uint32_t& r1,
                                        uint32_t& r2, uint32_t& r3) {
    asm volatile("ldmatrix.sync.aligned.m8n8.x4.shared.b16 {%0,%1,%2,%3}, [%4];"
                 : "=r"(r0), "=r"(r1), "=r"(r2), "=r"(r3) : "r"(a));
}
__device__ __forceinline__ void mma4(float* c, const uint32_t* a, uint32_t b0, uint32_t b1) {
    asm volatile(
        "mma.sync.aligned.m16n8k16.row.col.f32.f16.f16.f32 "
        "{%0,%1,%2,%3}, {%4,%5,%6,%7}, {%8,%9}, {%0,%1,%2,%3};"
        : "+f"(c[0]), "+f"(c[1]), "+f"(c[2]), "+f"(c[3])
        : "r"(a[0]), "r"(a[1]), "r"(a[2]), "r"(a[3]), "r"(b0), "r"(b1));
}
__device__ __forceinline__ void split2(float x, float y, uint32_t& hi, uint32_t& lo) {
    __half2 h = __floats2half2_rn(x, y);
    float rx = x - __half2float(__low2half(h));
    float ry = y - __half2float(__high2half(h));
    hi = pk(h);
    lo = pk(__floats2half2_rn(rx, ry));
}
__device__ __forceinline__ void cpa16(uint32_t s, const void* g) {
    asm volatile("cp.async.cg.shared.global [%0], [%1], 16;" :: "r"(s), "l"(g));
}
__device__ __forceinline__ void cpa_commit() {
    asm volatile("cp.async.commit_group;");
}
__device__ __forceinline__ float ex2(float x) {
    float y;
    asm("ex2.approx.f32 %0, %1;" : "=f"(y) : "f"(x));
    return y;
}

// =========================================================================
// Converters (batched)
// =========================================================================
__global__ __launch_bounds__(256) void cvt_acts(
    const float* __restrict__ q, const float* __restrict__ k,
    const float* __restrict__ v, int n4)
{
    const float* src = (blockIdx.y == 0) ? q : (blockIdx.y == 1) ? k : v;
    __half* hi = (blockIdx.y == 0) ? g_xqh : (blockIdx.y == 1) ? g_xkh : g_xvh;
    __half* lo = (blockIdx.y == 0) ? g_xql : (blockIdx.y == 1) ? g_xkl : g_xvl;
    uint32_t* hio = (uint32_t*)hi;
    uint32_t* loo = (uint32_t*)lo;
    for (int i = blockIdx.x * 256 + threadIdx.x; i < n4; i += gridDim.x * 256) {
        float4 f = ((const float4*)src)[i];
        uint32_t h0, l0, h1, l1;
        split2(f.x, f.y, h0, l0);
        split2(f.z, f.w, h1, l1);
        hio[2 * i] = h0; hio[2 * i + 1] = h1;
        loo[2 * i] = l0; loo[2 * i + 1] = l1;
    }
}

__global__ __launch_bounds__(256) void cvt_wts(
    const float* __restrict__ wq, const float* __restrict__ wk,
    const float* __restrict__ wv, const float* __restrict__ wo, int n4)
{
    const float* src = (blockIdx.y == 0) ? wq : (blockIdx.y == 1) ? wk
                      : (blockIdx.y == 2) ? wv : wo;
    __half* hi = (blockIdx.y == 0) ? g_wqh : (blockIdx.y == 1) ? g_wkh
               : (blockIdx.y == 2) ? g_wvh : g_woh;
    __half* lo = (blockIdx.y == 0) ? g_wql : (blockIdx.y == 1) ? g_wkl
               : (blockIdx.y == 2) ? g_wvl : g_wol;
    uint32_t* hio = (uint32_t*)hi;
    uint32_t* loo = (uint32_t*)lo;
    for (int i = blockIdx.x * 256 + threadIdx.x; i < n4; i += gridDim.x * 256) {
        float4 f = ((const float4*)src)[i];
        uint32_t h0, l0, h1, l1;
        split2(f.x, f.y, h0, l0);
        split2(f.z, f.w, h1, l1);
        hio[2 * i] = h0; hio[2 * i + 1] = h1;
        loo[2 * i] = l0; loo[2 * i + 1] = l1;
    }
}

// =========================================================================
// Per-bh max ||k_row||
// =========================================================================
__global__ __launch_bounds__(256) void kmax_kernel(const __half* __restrict__ kh,
                                                   float* __restrict__ maxk)
{
    __shared__ float red[256];
    const int bh = blockIdx.x;
    const __half* base = kh + (size_t)bh * SEQ * DKH;
    float mx = 0.f;
    for (int r = threadIdx.x; r < SEQ; r += 256) {
        const uint4* p = (const uint4*)(base + (size_t)r * DKH);
        float s = 0.f;
        #pragma unroll
        for (int i = 0; i < 8; i++) {
            uint4 u = p[i];
            uint32_t ws[4] = {u.x, u.y, u.z, u.w};
            #pragma unroll
            for (int j = 0; j < 4; j++) {
                float2 f = __half22float2(*(__half2*)&ws[j]);
                s += f.x * f.x + f.y * f.y;
            }
        }
        mx = fmaxf(mx, s);
    }
    red[threadIdx.x] = mx;
    __syncthreads();
    for (int st = 128; st > 0; st >>= 1) {
        if (threadIdx.x < st) red[threadIdx.x] = fmaxf(red[threadIdx.x], red[threadIdx.x + st]);
        __syncthreads();
    }
    if (threadIdx.x == 0) maxk[bh] = sqrtf(red[0]);
}

// =========================================================================
// GEMM body (device inline), K-chunk 32, cp.async double-buffered.
// 3-pass if Wl != nullptr else 2-pass (A-corrected).
// mode 0: fp32 flat; 1: head-split halves; 2: +QSCALE; 3: transposed.
// =========================================================================
#define GBM 128
#define GBN 64
#define GKC 32
#define GSTR 40
#define NKC (D_MODEL / GKC)      // 24
#define GS_A (GBM * GSTR)
#define GS_B (GBN * GSTR)
#define GS_STAGE (2 * GS_A + 2 * GS_B)
#define GEM_SMEM (2 * GS_STAGE * 2)      // 61440 bytes

__device__ __forceinline__ void gemm_body(
    __half* gs,
    const __half* __restrict__ Ah, const __half* __restrict__ Al,
    const __half* __restrict__ Wh, const __half* __restrict__ Wl,
    const float* __restrict__ bias, float* __restrict__ outf,
    __half* __restrict__ outh, __half* __restrict__ outl, int mode)
{
    const int tid = threadIdx.x;
    const int w = tid >> 5;
    const int lane = tid & 31;
    const int row0 = blockIdx.y * GBM;
    const int col0 = blockIdx.x * GBN;
    const int blk = lane >> 3;
    const int lrow = lane & 7;
    const bool useBlo = (Wl != nullptr);

    float acc[8][4] = {};

    auto issue = [&](int kc, int st) {
        const int k0 = kc * GKC;
        __half* S = gs + st * GS_STAGE;
        #pragma unroll
        for (int i = 0; i < 6; i++) {
            const int ci = tid + i * 256;
            if (ci < 1024) {
                const int hl = ci >> 9;
                const int idx = ci & 511;
                const int r = idx >> 2, c4 = idx & 3;
                cpa16(smem_u32(S + hl * GS_A + r * GSTR + c4 * 8),
                      (hl ? Al : Ah) + (size_t)(row0 + r) * D_MODEL + k0 + c4 * 8);
            } else {
                const int hl = (ci >> 8) & 1;
                if (hl && !useBlo) continue;
                const int idx = ci & 255;
                const int r = idx >> 2, c4 = idx & 3;
                cpa16(smem_u32(S + 2 * GS_A + hl * GS_B + r * GSTR + c4 * 8),
                      (hl ? Wl : Wh) + (size_t)(col0 + r) * D_MODEL + k0 + c4 * 8);
            }
        }
    };

    issue(0, 0);
    cpa_commit();

    for (int kc = 0; kc < NKC; kc++) {
        if (kc + 1 < NKC) {
            issue(kc + 1, (kc + 1) & 1);
            cpa_commit();
            asm volatile("cp.async.wait_group 1;");
        } else {
            asm volatile("cp.async.wait_group 0;");
        }
        __syncthreads();

        const __half* S = gs + (kc & 1) * GS_STAGE;
        const __half* sAh = S;
        const __half* sAl = S + GS_A;
        const __half* sBh = S + 2 * GS_A;
        const __half* sBl = S + 2 * GS_A + GS_B;

        #pragma unroll
        for (int kk = 0; kk < 2; kk++) {
            uint32_t ahi[4], alo[4];
            const int arow = 16 * w + (blk & 1) * 8 + lrow;
            const int acol = kk * 16 + (blk >> 1) * 8;
            ldsm_x4(smem_u32(sAh + arow * GSTR + acol), ahi[0], ahi[1], ahi[2], ahi[3]);
            ldsm_x4(smem_u32(sAl + arow * GSTR + acol), alo[0], alo[1], alo[2], alo[3]);

            #pragma unroll
            for (int np = 0; np < 4; np++) {
                const int brow = np * 16 + (blk >> 1) * 8 + lrow;
                const int bcol = kk * 16 + (blk & 1) * 8;
                uint32_t bh0, bh1, bh2, bh3;
                ldsm_x4(smem_u32(sBh + brow * GSTR + bcol), bh0, bh1, bh2, bh3);
                mma4(acc[2 * np],     ahi, bh0, bh1);
                mma4(acc[2 * np + 1], ahi, bh2, bh3);
                mma4(acc[2 * np],     alo, bh0, bh1);
                mma4(acc[2 * np + 1], alo, bh2, bh3);
                if (useBlo) {
                    uint32_t bl0, bl1, bl2, bl3;
                    ldsm_x4(smem_u32(sBl + brow * GSTR + bcol), bl0, bl1, bl2, bl3);
                    mma4(acc[2 * np],     ahi, bl0, bl1);
                    mma4(acc[2 * np + 1], ahi, bl2, bl3);
                }
            }
        }
        __syncthreads();
    }

    const float scale = (mode == 2) ? QSCALE : 1.0f;
    const int rloc = 16 * w + (lane >> 2);
    #pragma unroll
    for (int nt = 0; nt < 8; nt++) {
        const int n = col0 + nt * 8 + (lane & 3) * 2;
        const float bx = bias[n], by = bias[n + 1];
        const int m0 = row0 + rloc;
        float o00 = (acc[nt][0] + bx) * scale;
        float o01 = (acc[nt][1] + by) * scale;
        float o10 = (acc[nt][2] + bx) * scale;
        float o11 = (acc[nt][3] + by) * scale;
        if (mode == 0) {
            *(float2*)(outf + (size_t)m0 * D_MODEL + n) = make_float2(o00, o01);
            *(float2*)(outf + (size_t)(m0 + 8) * D_MODEL + n) = make_float2(o10, o11);
        } else {
            const int h = n >> 6, d = n & 63;
            const int b0m = m0 >> 12, s0 = m0 & (SEQ - 1);
            const int b1m = (m0 + 8) >> 12, s1 = (m0 + 8) & (SEQ - 1);
            uint32_t h0u, l0u, h1u, l1u;
            split2(o00, o01, h0u, l0u);
            split2(o10, o11, h1u, l1u);
            if (mode == 3) {
                size_t p0 = ((size_t)(b0m * NUM_HEADS + h) * DKH + d) * SEQ + s0;
                size_t p1 = ((size_t)(b1m * NUM_HEADS + h) * DKH + d) * SEQ + s1;
                __half2 H0 = *(__half2*)&h0u, H1 = *(__half2*)&h1u;
                outh[p0] = __low2half(H0);  outh[p0 + SEQ] = __high2half(H0);
                outh[p1] = __low2half(H1);  outh[p1 + SEQ] = __high2half(H1);
            } else {
                size_t p0 = ((size_t)(b0m * NUM_HEADS + h) * SEQ + s0) * DKH + d;
                size_t p1 = ((size_t)(b1m * NUM_HEADS + h) * SEQ + s1) * DKH + d;
                *(uint32_t*)(outh + p0) = h0u;
                *(uint32_t*)(outh + p1) = h1u;
                if (outl) {
                    *(uint32_t*)(outl + p0) = l0u;
                    *(uint32_t*)(outl + p1) = l1u;
                }
            }
        }
    }
}

// Fused Q/K/V projections: blockIdx.z = 0 (Q, 3-pass), 1 (K, 2-pass), 2 (V, 2-pass T)
__global__ __launch_bounds__(256, 2) void gemm_qkv(
    const float* __restrict__ bq, const float* __restrict__ bk,
    const float* __restrict__ bv)
{
    extern __shared__ __align__(16) __half gs[];
    if (blockIdx.z == 0)
        gemm_body(gs, g_xqh, g_xql, g_wqh, g_wql, bq, nullptr, g_qh, g_ql, 2);
    else if (blockIdx.z == 1)
        gemm_body(gs, g_xkh, g_xkl, g_wkh, nullptr, bk, nullptr, g_kh, nullptr, 1);
    else
        gemm_body(gs, g_xvh, g_xvl, g_wvh, nullptr, bv, nullptr, g_vth, nullptr, 3);
}

// Output projection: 3-pass, fp32 out
__global__ __launch_bounds__(256, 2) void gemm_out(
    const float* __restrict__ bo, float* __restrict__ outf)
{
    extern __shared__ __align__(16) __half gs[];
    gemm_body(gs, g_ath, g_atl, g_woh, g_wol, bo, outf, nullptr, nullptr, 0);
}

// =========================================================================
// Flash attention, 2-pass QK / 1-pass PV, SAFE-MAX softmax, KV stage 128.
// 256 thr / 8 warps, Q tile 128 (SMEM), 2-stage cp.async, 2 CTAs/SM.
// =========================================================================
#define QT 128
#define KVS 128
#define QSTR 72
#define VSTR2 136
#define QTILE (QT * QSTR)
#define KTILE2 (KVS * QSTR)
#define VTILE2 (DKH * VSTR2)
#define STG2 (KTILE2 + VTILE2)
#define ATT_SMEM ((2 * QTILE + 2 * STG2) * 2)   // 108544 B
#define NT2 (SEQ / KVS)               // 32

__global__ __launch_bounds__(256, 2) void attn_sm(
    const __half* __restrict__ Qh_, const __half* __restrict__ Ql_,
    const __half* __restrict__ Kh_, const __half* __restrict__ VTh_,
    const float* __restrict__ maxk,
    __half* __restrict__ Oh_, __half* __restrict__ Ol_)
{
    extern __shared__ __align__(16) __half sm[];
    __half* sQh = sm;
    __half* sQl = sm + QTILE;
    __half* sStage = sm + 2 * QTILE;

    const int tid = threadIdx.x;
    const int w = tid >> 5;
    const int lane = tid & 31;
    const int q0 = blockIdx.x * QT;
    const int bh = blockIdx.y;
    const int blk = lane >> 3;
    const int lrow = lane & 7;

    const __half* Qgh = Qh_ + (size_t)bh * SEQ * DKH;
    const __half* Qgl = Ql_ + (size_t)bh * SEQ * DKH;
    const __half* Kgh = Kh_ + (size_t)bh * SEQ * DKH;
    const __half* Vgh = VTh_ + (size_t)bh * DKH * SEQ;

    auto issue_kv = [&](int t, int st) {
        const int kt = t * KVS;
        __half* S = sStage + st * STG2;
        #pragma unroll
        for (int i = 0; i < 8; i++) {
            const int ci = tid + i * 256;
            if (ci < 1024) {
                const int r = ci >> 3, c8 = ci & 7;
                cpa16(smem_u32(S + r * QSTR + c8 * 8),
                      Kgh + (size_t)(kt + r) * DKH + c8 * 8);
            } else {
                const int idx = ci - 1024;
                const int r = idx >> 4, c16 = idx & 15;
                cpa16(smem_u32(S + KTILE2 + r * VSTR2 + c16 * 8),
                      Vgh + (size_t)r * SEQ + kt + c16 * 8);
            }
        }
    };

    #pragma unroll
    for (int i = 0; i < 8; i++) {
        const int ci = tid + i * 256;
        const int arr = ci >> 10;
        const int c = ci & 1023;
        const int r = c >> 3, c8 = c & 7;
        const __half* src = (arr ? Qgl : Qgh) + (size_t)(q0 + r) * DKH + c8 * 8;
        cpa16(smem_u32((arr ? sQl : sQh) + r * QSTR + c8 * 8), src);
    }
    issue_kv(0, 0);
    cpa_commit();
    issue_kv(1, 1);
    cpa_commit();

    // ---- safe-max bounds ----
    const int r0 = 16 * w + (lane >> 2);
    float nq0 = 0.f, nq1 = 0.f;
    {
        const uint4* p0 = (const uint4*)(Qgh + (size_t)(q0 + r0) * DKH);
        const uint4* p1 = (const uint4*)(Qgh + (size_t)(q0 + r0 + 8) * DKH);
        #pragma unroll
        for (int i = 0; i < 8; i++) {
            uint4 u0 = p0[i], u1 = p1[i];
            uint32_t a0[4] = {u0.x, u0.y, u0.z, u0.w};
            uint32_t a1[4] = {u1.x, u1.y, u1.z, u1.w};
            #pragma unroll
            for (int j = 0; j < 4; j++) {
                float2 f0 = __half22float2(*(__half2*)&a0[j]);
                float2 f1 = __half22float2(*(__half2*)&a1[j]);
                nq0 += f0.x * f0.x + f0.y * f0.y;
                nq1 += f1.x * f1.x + f1.y * f1.y;
            }
        }
    }
    const float mk = maxk[bh];
    const float M20 = sqrtf(nq0) * mk - SHIFT_LOG2;
    const float M21 = sqrtf(nq1) * mk - SHIFT_LOG2;

    float o[8][4] = {};
    float lsum0 = 0.f, lsum1 = 0.f;

    for (int t = 0; t < NT2; t++) {
        if (t + 1 < NT2) {
            issue_kv(t + 1, (t + 1) & 1);
            cpa_commit();
            asm volatile("cp.async.wait_group 1;");
        } else {
            asm volatile("cp.async.wait_group 0;");
        }
        __syncthreads();

        const __half* S = sStage + (t & 1) * STG2;
        const __half* sKh = S;
        const __half* sVh = S + KTILE2;

        #pragma unroll
        for (int j = 0; j < 2; j++) {
            // ---- S = Q K^T (2-pass) ----
            float s[8][4] = {};
            #pragma unroll
            for (int ks = 0; ks < 4; ks++) {
                uint32_t ahi[4], alo[4];
                const int arow = 16 * w + (blk & 1) * 8 + lrow;
                const int acol = ks * 16 + (blk >> 1) * 8;
                ldsm_x4(smem_u32(sQh + arow * QSTR + acol), ahi[0], ahi[1], ahi[2], ahi[3]);
                ldsm_x4(smem_u32(sQl + arow * QSTR + acol), alo[0], alo[1], alo[2], alo[3]);
                #pragma unroll
                for (int np = 0; np < 4; np++) {
                    const int brow = j * 64 + np * 16 + (blk >> 1) * 8 + lrow;
                    const int bcol = ks * 16 + (blk & 1) * 8;
                    uint32_t bh0, bh1, bh2, bh3;
                    ldsm_x4(smem_u32(sKh + brow * QSTR + bcol), bh0, bh1, bh2, bh3);
                    mma4(s[2 * np],     ahi, bh0, bh1);
                    mma4(s[2 * np + 1], ahi, bh2, bh3);
                    mma4(s[2 * np],     alo, bh0, bh1);
                    mma4(s[2 * np + 1], alo, bh2, bh3);
                }
            }

            // ---- exp2 (fixed bound) + direct half convert + PV (1-pass) ----
            #pragma unroll
            for (int ks = 0; ks < 4; ks++) {
                float e00 = ex2(s[2 * ks][0] - M20);
                float e01 = ex2(s[2 * ks][1] - M20);
                float e02 = ex2(s[2 * ks][2] - M21);
                float e03 = ex2(s[2 * ks][3] - M21);
                float e10 = ex2(s[2 * ks + 1][0] - M20);
                float e11 = ex2(s[2 * ks + 1][1] - M20);
                float e12 = ex2(s[2 * ks + 1][2] - M21);
                float e13 = ex2(s[2 * ks + 1][3] - M21);
                lsum0 += e00 + e01 + e10 + e11;
                lsum1 += e02 + e03 + e12 + e13;

                uint32_t ph4[4];
                ph4[0] = pk(__floats2half2_rn(e00, e01));
                ph4[1] = pk(__floats2half2_rn(e02, e03));
                ph4[2] = pk(__floats2half2_rn(e10, e11));
                ph4[3] = pk(__floats2half2_rn(e12, e13));

                #pragma unroll
                for (int npd = 0; npd < 4; npd++) {
                    const int vrow = npd * 16 + (blk >> 1) * 8 + lrow;
                    const int vcol = j * 64 + ks * 16 + (blk & 1) * 8;
                    uint32_t vh0, vh1, vh2, vh3;
                    ldsm_x4(smem_u32(sVh + vrow * VSTR2 + vcol), vh0, vh1, vh2, vh3);
                    mma4(o[2 * npd],     ph4, vh0, vh1);
                    mma4(o[2 * npd + 1], ph4, vh2, vh3);
                }
            }
        }
        __syncthreads();
    }

    // ---- epilogue ----
    lsum0 += __shfl_xor_sync(0xffffffffu, lsum0, 1);
    lsum0 += __shfl_xor_sync(0xffffffffu, lsum0, 2);
    lsum1 += __shfl_xor_sync(0xffffffffu, lsum1, 1);
    lsum1 += __shfl_xor_sync(0xffffffffu, lsum1, 2);
    const float inv0 = 1.f / lsum0, inv1 = 1.f / lsum1;

    const int b = bh / NUM_HEADS, h = bh % NUM_HEADS;
    #pragma unroll
    for (int nt = 0; nt < 8; nt++) {
        const int d = h * DKH + nt * 8 + (lane & 3) * 2;
        size_t p0 = (size_t)(b * SEQ + q0 + r0) * D_MODEL + d;
        size_t p1 = (size_t)(b * SEQ + q0 + r0 + 8) * D_MODEL + d;
        uint32_t h0u, l0u, h1u, l1u;
        split2(o[nt][0] * inv0, o[nt][1] * inv0, h0u, l0u);
        split2(o[nt][2] * inv1, o[nt][3] * inv1, h1u, l1u);
        *(uint32_t*)(Oh_ + p0) = h0u;
        *(uint32_t*)(Ol_ + p0) = l0u;
        *(uint32_t*)(Oh_ + p1) = h1u;
        *(uint32_t*)(Ol_ + p1) = l1u;
    }
}

// =========================================================================
// Launch
// =========================================================================
extern "C" void kernel_launch(void* const* d_in, const int* in_sizes, int n_in,
                              void* d_out, int out_size)
{
    const float* query = (const float*)d_in[0];
    const float* key   = (const float*)d_in[1];
    const float* value = (const float*)d_in[2];
    const float* bq = (const float*)d_in[4];
    const float* bk = (const float*)d_in[6];
    const float* bv = (const float*)d_in[8];
    const float* bo = (const float*)d_in[10];
    const float* Wq = (const float*)d_in[3];
    const float* Wk = (const float*)d_in[5];
    const float* Wv = (const float*)d_in[7];
    const float* Wo = (const float*)d_in[9];
    float* out = (float*)d_out;

    __half *qh, *ql, *kh, *vth, *ath, *atl;
    float* maxk;
    cudaGetSymbolAddress((void**)&qh,  g_qh);  cudaGetSymbolAddress((void**)&ql,  g_ql);
    cudaGetSymbolAddress((void**)&kh,  g_kh);
    cudaGetSymbolAddress((void**)&vth, g_vth);
    cudaGetSymbolAddress((void**)&ath, g_ath); cudaGetSymbolAddress((void**)&atl, g_atl);
    cudaGetSymbolAddress((void**)&maxk, g_maxk);

    cudaFuncSetAttribute(attn_sm, cudaFuncAttributeMaxDynamicSharedMemorySize, ATT_SMEM);
    cudaFuncSetAttribute(gemm_qkv, cudaFuncAttributeMaxDynamicSharedMemorySize, GEM_SMEM);
    cudaFuncSetAttribute(gemm_out, cudaFuncAttributeMaxDynamicSharedMemorySize, GEM_SMEM);

    const int NX4 = MROWS * D_MODEL / 4;
    const int NW4 = D_MODEL * D_MODEL / 4;

    // batched converters
    dim3 agrid_cvt(592, 3);
    cvt_acts<<<agrid_cvt, 256>>>(query, key, value, NX4);
    dim3 wgrid_cvt(296, 4);
    cvt_wts<<<wgrid_cvt, 256>>>(Wq, Wk, Wv, Wo, NW4);

    // fused Q/K/V projections
    dim3 qkvgrid(D_MODEL / GBN, MROWS / GBM, 3);   // (12, 64, 3)
    gemm_qkv<<<qkvgrid, 256, GEM_SMEM>>>(bq, bk, bv);

    kmax_kernel<<<NBH, 256>>>(kh, maxk);

    // attention
    dim3 agrid(SEQ / QT, NBH);   // (32, 24)
    attn_sm<<<agrid, 256, ATT_SMEM>>>(qh, ql, kh, vth, maxk, ath, atl);

    // output projection
    dim3 ogrid(D_MODEL / GBN, MROWS / GBM);        // (12, 64)
    gemm_out<<<ogrid, 256, GEM_SMEM>>>(bo, out);
}

// round 9
// speedup vs baseline: 6.3655x; 1.0173x over previous
#include <cuda_runtime.h>
#include <cuda_fp16.h>
#include <math.h>
#include <stdint.h>

#define D_MODEL 768
#define NUM_HEADS 12
#define DKH 64
#define BATCH 2
#define SEQ 4096
#define MROWS (BATCH * SEQ)   // 8192
#define NBH (BATCH * NUM_HEADS)

#define QSCALE 0.18033688011112042f      // log2(e)/8
#define SHIFT_LOG2 5.770780163555855f    // 4 nats in log2

// ---------------- scratch (device globals; no allocation) ----------------
#define QKV_ELEMS ((size_t)NBH * SEQ * DKH)
#define XN ((size_t)MROWS * D_MODEL)
#define WN ((size_t)D_MODEL * D_MODEL)
__device__ __half g_qh[QKV_ELEMS], g_ql[QKV_ELEMS];
__device__ __half g_kh[QKV_ELEMS];
__device__ __half g_vth[QKV_ELEMS];
__device__ __half g_xqh[XN], g_xql[XN];
__device__ __half g_xkh[XN], g_xkl[XN];
__device__ __half g_xvh[XN], g_xvl[XN];
__device__ __half g_wqh[WN], g_wql[WN];
__device__ __half g_wkh[WN], g_wkl[WN];
__device__ __half g_wvh[WN], g_wvl[WN];
__device__ __half g_woh[WN], g_wol[WN];
__device__ __half g_ath[XN], g_atl[XN];
__device__ int    g_maxk2[NBH];          // max ||k||^2 as float bits (atomicMax)

// ---------------- helpers ----------------
__device__ __forceinline__ uint32_t smem_u32(const void* p) {
    return (uint32_t)__cvta_generic_to_shared(p);
}
__device__ __forceinline__ uint32_t pk(__half2 h) {
    union { __half2 h; uint32_t u; } x; x.h = h; return x.u;
}
__device__ __forceinline__ void ldsm_x4(uint32_t a, uint32_t& r0, uint32_t& r1,
                                        uint32_t& r2, uint32_t& r3) {
    asm volatile("ldmatrix.sync.aligned.m8n8.x4.shared.b16 {%0,%1,%2,%3}, [%4];"
                 : "=r"(r0), "=r"(r1), "=r"(r2), "=r"(r3) : "r"(a));
}
__device__ __forceinline__ void mma4(float* c, const uint32_t* a, uint32_t b0, uint32_t b1) {
    asm volatile(
        "mma.sync.aligned.m16n8k16.row.col.f32.f16.f16.f32 "
        "{%0,%1,%2,%3}, {%4,%5,%6,%7}, {%8,%9}, {%0,%1,%2,%3};"
        : "+f"(c[0]), "+f"(c[1]), "+f"(c[2]), "+f"(c[3])
        : "r"(a[0]), "r"(a[1]), "r"(a[2]), "r"(a[3]), "r"(b0), "r"(b1));
}
__device__ __forceinline__ void split2(float x, float y, uint32_t& hi, uint32_t& lo) {
    __half2 h = __floats2half2_rn(x, y);
    float rx = x - __half2float(__low2half(h));
    float ry = y - __half2float(__high2half(h));
    hi = pk(h);
    lo = pk(__floats2half2_rn(rx, ry));
}
__device__ __forceinline__ void cpa16(uint32_t s, const void* g) {
    asm volatile("cp.async.cg.shared.global [%0], [%1], 16;" :: "r"(s), "l"(g));
}
__device__ __forceinline__ void cpa_commit() {
    asm volatile("cp.async.commit_group;");
}
__device__ __forceinline__ float ex2(float x) {
    float y;
    asm("ex2.approx.f32 %0, %1;" : "=f"(y) : "f"(x));
    return y;
}
__device__ __forceinline__ float h2sq(uint32_t u) {
    float2 f = __half22float2(*(__half2*)&u);
    return f.x * f.x + f.y * f.y;
}

// =========================================================================
// Fused converter: y = 0..2 activations (q,k,v), 3..6 weights (wq,wk,wv,wo)
// =========================================================================
__global__ __launch_bounds__(256) void cvt_all(
    const float* __restrict__ q, const float* __restrict__ k,
    const float* __restrict__ v, const float* __restrict__ wq,
    const float* __restrict__ wk, const float* __restrict__ wv,
    const float* __restrict__ wo)
{
    const int y = blockIdx.y;
    const float* src;
    __half *hi, *lo;
    int n4;
    switch (y) {
        case 0: src = q;  hi = g_xqh; lo = g_xql; n4 = XN / 4; break;
        case 1: src = k;  hi = g_xkh; lo = g_xkl; n4 = XN / 4; break;
        case 2: src = v;  hi = g_xvh; lo = g_xvl; n4 = XN / 4; break;
        case 3: src = wq; hi = g_wqh; lo = g_wql; n4 = WN / 4; break;
        case 4: src = wk; hi = g_wkh; lo = g_wkl; n4 = WN / 4; break;
        case 5: src = wv; hi = g_wvh; lo = g_wvl; n4 = WN / 4; break;
        default: src = wo; hi = g_woh; lo = g_wol; n4 = WN / 4; break;
    }
    uint32_t* hio = (uint32_t*)hi;
    uint32_t* loo = (uint32_t*)lo;
    for (int i = blockIdx.x * 256 + threadIdx.x; i < n4; i += gridDim.x * 256) {
        float4 f = ((const float4*)src)[i];
        uint32_t h0, l0, h1, l1;
        split2(f.x, f.y, h0, l0);
        split2(f.z, f.w, h1, l1);
        hio[2 * i] = h0; hio[2 * i + 1] = h1;
        loo[2 * i] = l0; loo[2 * i + 1] = l1;
    }
}

// =========================================================================
// kmax: grid (NBH, 8), atomicMax on float bits of ||k||^2 (all >= 0).
// Deterministic: same inputs -> same max on every replay.
// =========================================================================
__global__ __launch_bounds__(256) void kmax_kernel(const __half* __restrict__ kh,
                                                   int* __restrict__ maxk2)
{
    __shared__ float red[256];
    const int bh = blockIdx.x;
    const int part = blockIdx.y;
    const int rows = SEQ / 8;
    const __half* base = kh + (size_t)bh * SEQ * DKH + (size_t)part * rows * DKH;
    float mx = 0.f;
    for (int r = threadIdx.x; r < rows; r += 256) {
        const uint4* p = (const uint4*)(base + (size_t)r * DKH);
        float s = 0.f;
        #pragma unroll
        for (int i = 0; i < 8; i++) {
            uint4 u = p[i];
            s += h2sq(u.x) + h2sq(u.y) + h2sq(u.z) + h2sq(u.w);
        }
        mx = fmaxf(mx, s);
    }
    red[threadIdx.x] = mx;
    __syncthreads();
    for (int st = 128; st > 0; st >>= 1) {
        if (threadIdx.x < st) red[threadIdx.x] = fmaxf(red[threadIdx.x], red[threadIdx.x + st]);
        __syncthreads();
    }
    if (threadIdx.x == 0) atomicMax(&maxk2[bh], __float_as_int(red[0]));
}

// =========================================================================
// GEMM body, K-chunk 32, cp.async double-buffered.
// =========================================================================
#define GBM 128
#define GBN 64
#define GKC 32
#define GSTR 40
#define NKC (D_MODEL / GKC)
#define GS_A (GBM * GSTR)
#define GS_B (GBN * GSTR)
#define GS_STAGE (2 * GS_A + 2 * GS_B)
#define GEM_SMEM (2 * GS_STAGE * 2)

__device__ __forceinline__ void gemm_body(
    __half* gs,
    const __half* __restrict__ Ah, const __half* __restrict__ Al,
    const __half* __restrict__ Wh, const __half* __restrict__ Wl,
    const float* __restrict__ bias, float* __restrict__ outf,
    __half* __restrict__ outh, __half* __restrict__ outl, int mode)
{
    const int tid = threadIdx.x;
    const int w = tid >> 5;
    const int lane = tid & 31;
    const int row0 = blockIdx.y * GBM;
    const int col0 = blockIdx.x * GBN;
    const int blk = lane >> 3;
    const int lrow = lane & 7;
    const bool useBlo = (Wl != nullptr);

    float acc[8][4] = {};

    auto issue = [&](int kc, int st) {
        const int k0 = kc * GKC;
        __half* S = gs + st * GS_STAGE;
        #pragma unroll
        for (int i = 0; i < 6; i++) {
            const int ci = tid + i * 256;
            if (ci < 1024) {
                const int hl = ci >> 9;
                const int idx = ci & 511;
                const int r = idx >> 2, c4 = idx & 3;
                cpa16(smem_u32(S + hl * GS_A + r * GSTR + c4 * 8),
                      (hl ? Al : Ah) + (size_t)(row0 + r) * D_MODEL + k0 + c4 * 8);
            } else {
                const int hl = (ci >> 8) & 1;
                if (hl && !useBlo) continue;
                const int idx = ci & 255;
                const int r = idx >> 2, c4 = idx & 3;
                cpa16(smem_u32(S + 2 * GS_A + hl * GS_B + r * GSTR + c4 * 8),
                      (hl ? Wl : Wh) + (size_t)(col0 + r) * D_MODEL + k0 + c4 * 8);
            }
        }
    };

    issue(0, 0);
    cpa_commit();

    for (int kc = 0; kc < NKC; kc++) {
        if (kc + 1 < NKC) {
            issue(kc + 1, (kc + 1) & 1);
            cpa_commit();
            asm volatile("cp.async.wait_group 1;");
        } else {
            asm volatile("cp.async.wait_group 0;");
        }
        __syncthreads();

        const __half* S = gs + (kc & 1) * GS_STAGE;
        const __half* sAh = S;
        const __half* sAl = S + GS_A;
        const __half* sBh = S + 2 * GS_A;
        const __half* sBl = S + 2 * GS_A + GS_B;

        #pragma unroll
        for (int kk = 0; kk < 2; kk++) {
            uint32_t ahi[4], alo[4];
            const int arow = 16 * w + (blk & 1) * 8 + lrow;
            const int acol = kk * 16 + (blk >> 1) * 8;
            ldsm_x4(smem_u32(sAh + arow * GSTR + acol), ahi[0], ahi[1], ahi[2], ahi[3]);
            ldsm_x4(smem_u32(sAl + arow * GSTR + acol), alo[0], alo[1], alo[2], alo[3]);

            #pragma unroll
            for (int np = 0; np < 4; np++) {
                const int brow = np * 16 + (blk >> 1) * 8 + lrow;
                const int bcol = kk * 16 + (blk & 1) * 8;
                uint32_t bh0, bh1, bh2, bh3;
                ldsm_x4(smem_u32(sBh + brow * GSTR + bcol), bh0, bh1, bh2, bh3);
                mma4(acc[2 * np],     ahi, bh0, bh1);
                mma4(acc[2 * np + 1], ahi, bh2, bh3);
                mma4(acc[2 * np],     alo, bh0, bh1);
                mma4(acc[2 * np + 1], alo, bh2, bh3);
                if (useBlo) {
                    uint32_t bl0, bl1, bl2, bl3;
                    ldsm_x4(smem_u32(sBl + brow * GSTR + bcol), bl0, bl1, bl2, bl3);
                    mma4(acc[2 * np],     ahi, bl0, bl1);
                    mma4(acc[2 * np + 1], ahi, bl2, bl3);
                }
            }
        }
        __syncthreads();
    }

    const float scale = (mode == 2) ? QSCALE : 1.0f;
    const int rloc = 16 * w + (lane >> 2);
    #pragma unroll
    for (int nt = 0; nt < 8; nt++) {
        const int n = col0 + nt * 8 + (lane & 3) * 2;
        const float bx = bias[n], by = bias[n + 1];
        const int m0 = row0 + rloc;
        float o00 = (acc[nt][0] + bx) * scale;
        float o01 = (acc[nt][1] + by) * scale;
        float o10 = (acc[nt][2] + bx) * scale;
        float o11 = (acc[nt][3] + by) * scale;
        if (mode == 0) {
            *(float2*)(outf + (size_t)m0 * D_MODEL + n) = make_float2(o00, o01);
            *(float2*)(outf + (size_t)(m0 + 8) * D_MODEL + n) = make_float2(o10, o11);
        } else {
            const int h = n >> 6, d = n & 63;
            const int b0m = m0 >> 12, s0 = m0 & (SEQ - 1);
            const int b1m = (m0 + 8) >> 12, s1 = (m0 + 8) & (SEQ - 1);
            uint32_t h0u, l0u, h1u, l1u;
            split2(o00, o01, h0u, l0u);
            split2(o10, o11, h1u, l1u);
            if (mode == 3) {
                size_t p0 = ((size_t)(b0m * NUM_HEADS + h) * DKH + d) * SEQ + s0;
                size_t p1 = ((size_t)(b1m * NUM_HEADS + h) * DKH + d) * SEQ + s1;
                __half2 H0 = *(__half2*)&h0u, H1 = *(__half2*)&h1u;
                outh[p0] = __low2half(H0);  outh[p0 + SEQ] = __high2half(H0);
                outh[p1] = __low2half(H1);  outh[p1 + SEQ] = __high2half(H1);
            } else {
                size_t p0 = ((size_t)(b0m * NUM_HEADS + h) * SEQ + s0) * DKH + d;
                size_t p1 = ((size_t)(b1m * NUM_HEADS + h) * SEQ + s1) * DKH + d;
                *(uint32_t*)(outh + p0) = h0u;
                *(uint32_t*)(outh + p1) = h1u;
                if (outl) {
                    *(uint32_t*)(outl + p0) = l0u;
                    *(uint32_t*)(outl + p1) = l1u;
                }
            }
        }
    }
}

__global__ __launch_bounds__(256, 2) void gemm_qkv(
    const float* __restrict__ bq, const float* __restrict__ bk,
    const float* __restrict__ bv)
{
    extern __shared__ __align__(16) __half gs[];
    if (blockIdx.z == 0)
        gemm_body(gs, g_xqh, g_xql, g_wqh, g_wql, bq, nullptr, g_qh, g_ql, 2);
    else if (blockIdx.z == 1)
        gemm_body(gs, g_xkh, g_xkl, g_wkh, nullptr, bk, nullptr, g_kh, nullptr, 1);
    else
        gemm_body(gs, g_xvh, g_xvl, g_wvh, nullptr, bv, nullptr, g_vth, nullptr, 3);
}

__global__ __launch_bounds__(256, 2) void gemm_out(
    const float* __restrict__ bo, float* __restrict__ outf)
{
    extern __shared__ __align__(16) __half gs[];
    gemm_body(gs, g_ath, g_atl, g_woh, g_wol, bo, outf, nullptr, nullptr, 0);
}

// =========================================================================
// Flash attention: Q fragments register-resident for the whole kernel.
// 2-pass QK / 1-pass PV, SAFE-MAX softmax, KV stage 128, 2-stage cp.async.
// SMEM: 2 stages x (K 128x72 + V^T 64x136) halves = 71680 B. 2 CTAs/SM.
// =========================================================================
#define QT 128
#define KVS 128
#define KSTR 72
#define VSTR2 136
#define KTILE2 (KVS * KSTR)
#define VTILE2 (DKH * VSTR2)
#define STG2 (KTILE2 + VTILE2)
#define ATT_SMEM (2 * STG2 * 2)       // 71680 B
#define NT2 (SEQ / KVS)               // 32

__global__ __launch_bounds__(256, 2) void attn_sm(
    const __half* __restrict__ Qh_, const __half* __restrict__ Ql_,
    const __half* __restrict__ Kh_, const __half* __restrict__ VTh_,
    const int* __restrict__ maxk2,
    __half* __restrict__ Oh_, __half* __restrict__ Ol_)
{
    extern __shared__ __align__(16) __half sStage[];

    const int tid = threadIdx.x;
    const int w = tid >> 5;
    const int lane = tid & 31;
    const int q0 = blockIdx.x * QT;
    const int bh = blockIdx.y;
    const int blk = lane >> 3;
    const int lrow = lane & 7;

    const __half* Qgh = Qh_ + (size_t)bh * SEQ * DKH;
    const __half* Qgl = Ql_ + (size_t)bh * SEQ * DKH;
    const __half* Kgh = Kh_ + (size_t)bh * SEQ * DKH;
    const __half* Vgh = VTh_ + (size_t)bh * DKH * SEQ;

    auto issue_kv = [&](int t, int st) {
        const int kt = t * KVS;
        __half* S = sStage + st * STG2;
        #pragma unroll
        for (int i = 0; i < 8; i++) {
            const int ci = tid + i * 256;
            if (ci < 1024) {
                const int r = ci >> 3, c8 = ci & 7;
                cpa16(smem_u32(S + r * KSTR + c8 * 8),
                      Kgh + (size_t)(kt + r) * DKH + c8 * 8);
            } else {
                const int idx = ci - 1024;
                const int r = idx >> 4, c16 = idx & 15;
                cpa16(smem_u32(S + KTILE2 + r * VSTR2 + c16 * 8),
                      Vgh + (size_t)r * SEQ + kt + c16 * 8);
            }
        }
    };

    issue_kv(0, 0);
    cpa_commit();
    issue_kv(1, 1);
    cpa_commit();

    // ---- Q fragments in registers (whole kernel) ----
    uint32_t qh[4][4], ql[4][4];
    const int qr = q0 + 16 * w + (lane >> 2);
    #pragma unroll
    for (int ks = 0; ks < 4; ks++) {
        const int c0 = ks * 16 + (lane & 3) * 2;
        qh[ks][0] = *(const uint32_t*)(Qgh + (size_t)qr * DKH + c0);
        qh[ks][1] = *(const uint32_t*)(Qgh + (size_t)(qr + 8) * DKH + c0);
        qh[ks][2] = *(const uint32_t*)(Qgh + (size_t)qr * DKH + c0 + 8);
        qh[ks][3] = *(const uint32_t*)(Qgh + (size_t)(qr + 8) * DKH + c0 + 8);
        ql[ks][0] = *(const uint32_t*)(Qgl + (size_t)qr * DKH + c0);
        ql[ks][1] = *(const uint32_t*)(Qgl + (size_t)(qr + 8) * DKH + c0);
        ql[ks][2] = *(const uint32_t*)(Qgl + (size_t)qr * DKH + c0 + 8);
        ql[ks][3] = *(const uint32_t*)(Qgl + (size_t)(qr + 8) * DKH + c0 + 8);
    }

    // ---- safe-max bounds from register frags (lane&3 group covers 64 cols) ----
    float nq0 = 0.f, nq1 = 0.f;
    #pragma unroll
    for (int ks = 0; ks < 4; ks++) {
        nq0 += h2sq(qh[ks][0]) + h2sq(qh[ks][2]);
        nq1 += h2sq(qh[ks][1]) + h2sq(qh[ks][3]);
    }
    nq0 += __shfl_xor_sync(0xffffffffu, nq0, 1);
    nq0 += __shfl_xor_sync(0xffffffffu, nq0, 2);
    nq1 += __shfl_xor_sync(0xffffffffu, nq1, 1);
    nq1 += __shfl_xor_sync(0xffffffffu, nq1, 2);
    const float mk = sqrtf(__int_as_float(maxk2[bh]));
    const float M20 = sqrtf(nq0) * mk - SHIFT_LOG2;
    const float M21 = sqrtf(nq1) * mk - SHIFT_LOG2;

    float o[8][4] = {};
    float lsum0 = 0.f, lsum1 = 0.f;

    for (int t = 0; t < NT2; t++) {
        if (t + 1 < NT2) {
            issue_kv(t + 1, (t + 1) & 1);
            cpa_commit();
            asm volatile("cp.async.wait_group 1;");
        } else {
            asm volatile("cp.async.wait_group 0;");
        }
        __syncthreads();

        const __half* S = sStage + (t & 1) * STG2;
        const __half* sKh = S;
        const __half* sVh = S + KTILE2;

        #pragma unroll
        for (int j = 0; j < 2; j++) {
            // ---- S = Q K^T (2-pass, Q from registers) ----
            float s[8][4] = {};
            #pragma unroll
            for (int ks = 0; ks < 4; ks++) {
                #pragma unroll
                for (int np = 0; np < 4; np++) {
                    const int brow = j * 64 + np * 16 + (blk >> 1) * 8 + lrow;
                    const int bcol = ks * 16 + (blk & 1) * 8;
                    uint32_t bh0, bh1, bh2, bh3;
                    ldsm_x4(smem_u32(sKh + brow * KSTR + bcol), bh0, bh1, bh2, bh3);
                    mma4(s[2 * np],     qh[ks], bh0, bh1);
                    mma4(s[2 * np + 1], qh[ks], bh2, bh3);
                    mma4(s[2 * np],     ql[ks], bh0, bh1);
                    mma4(s[2 * np + 1], ql[ks], bh2, bh3);
                }
            }

            // ---- exp2 + half convert + PV (1-pass) ----
            #pragma unroll
            for (int ks = 0; ks < 4; ks++) {
                float e00 = ex2(s[2 * ks][0] - M20);
                float e01 = ex2(s[2 * ks][1] - M20);
                float e02 = ex2(s[2 * ks][2] - M21);
                float e03 = ex2(s[2 * ks][3] - M21);
                float e10 = ex2(s[2 * ks + 1][0] - M20);
                float e11 = ex2(s[2 * ks + 1][1] - M20);
                float e12 = ex2(s[2 * ks + 1][2] - M21);
                float e13 = ex2(s[2 * ks + 1][3] - M21);
                lsum0 += e00 + e01 + e10 + e11;
                lsum1 += e02 + e03 + e12 + e13;

                uint32_t ph4[4];
                ph4[0] = pk(__floats2half2_rn(e00, e01));
                ph4[1] = pk(__floats2half2_rn(e02, e03));
                ph4[2] = pk(__floats2half2_rn(e10, e11));
                ph4[3] = pk(__floats2half2_rn(e12, e13));

                #pragma unroll
                for (int npd = 0; npd < 4; npd++) {
                    const int vrow = npd * 16 + (blk >> 1) * 8 + lrow;
                    const int vcol = j * 64 + ks * 16 + (blk & 1) * 8;
                    uint32_t vh0, vh1, vh2, vh3;
                    ldsm_x4(smem_u32(sVh + vrow * VSTR2 + vcol), vh0, vh1, vh2, vh3);
                    mma4(o[2 * npd],     ph4, vh0, vh1);
                    mma4(o[2 * npd + 1], ph4, vh2, vh3);
                }
            }
        }
        __syncthreads();
    }

    // ---- epilogue ----
    lsum0 += __shfl_xor_sync(0xffffffffu, lsum0, 1);
    lsum0 += __shfl_xor_sync(0xffffffffu, lsum0, 2);
    lsum1 += __shfl_xor_sync(0xffffffffu, lsum1, 1);
    lsum1 += __shfl_xor_sync(0xffffffffu, lsum1, 2);
    const float inv0 = 1.f / lsum0, inv1 = 1.f / lsum1;

    const int b = bh / NUM_HEADS, h = bh % NUM_HEADS;
    const int r0 = 16 * w + (lane >> 2);
    #pragma unroll
    for (int nt = 0; nt < 8; nt++) {
        const int d = h * DKH + nt * 8 + (lane & 3) * 2;
        size_t p0 = (size_t)(b * SEQ + q0 + r0) * D_MODEL + d;
        size_t p1 = (size_t)(b * SEQ + q0 + r0 + 8) * D_MODEL + d;
        uint32_t h0u, l0u, h1u, l1u;
        split2(o[nt][0] * inv0, o[nt][1] * inv0, h0u, l0u);
        split2(o[nt][2] * inv1, o[nt][3] * inv1, h1u, l1u);
        *(uint32_t*)(Oh_ + p0) = h0u;
        *(uint32_t*)(Ol_ + p0) = l0u;
        *(uint32_t*)(Oh_ + p1) = h1u;
        *(uint32_t*)(Ol_ + p1) = l1u;
    }
}

// =========================================================================
// Launch
// =========================================================================
extern "C" void kernel_launch(void* const* d_in, const int* in_sizes, int n_in,
                              void* d_out, int out_size)
{
    const float* query = (const float*)d_in[0];
    const float* key   = (const float*)d_in[1];
    const float* value = (const float*)d_in[2];
    const float* Wq = (const float*)d_in[3];
    const float* bq = (const float*)d_in[4];
    const float* Wk = (const float*)d_in[5];
    const float* bk = (const float*)d_in[6];
    const float* Wv = (const float*)d_in[7];
    const float* bv = (const float*)d_in[8];
    const float* Wo = (const float*)d_in[9];
    const float* bo = (const float*)d_in[10];
    float* out = (float*)d_out;

    __half *qh, *ql, *kh, *vth, *ath, *atl;
    int* maxk2;
    cudaGetSymbolAddress((void**)&qh,  g_qh);  cudaGetSymbolAddress((void**)&ql,  g_ql);
    cudaGetSymbolAddress((void**)&kh,  g_kh);
    cudaGetSymbolAddress((void**)&vth, g_vth);
    cudaGetSymbolAddress((void**)&ath, g_ath); cudaGetSymbolAddress((void**)&atl, g_atl);
    cudaGetSymbolAddress((void**)&maxk2, g_maxk2);

    cudaFuncSetAttribute(attn_sm, cudaFuncAttributeMaxDynamicSharedMemorySize, ATT_SMEM);
    cudaFuncSetAttribute(gemm_qkv, cudaFuncAttributeMaxDynamicSharedMemorySize, GEM_SMEM);
    cudaFuncSetAttribute(gemm_out, cudaFuncAttributeMaxDynamicSharedMemorySize, GEM_SMEM);

    // single fused converter launch
    dim3 cvt_grid(592, 7);
    cvt_all<<<cvt_grid, 256>>>(query, key, value, Wq, Wk, Wv, Wo);

    // fused Q/K/V projections
    dim3 qkvgrid(D_MODEL / GBN, MROWS / GBM, 3);   // (12, 64, 3)
    gemm_qkv<<<qkvgrid, 256, GEM_SMEM>>>(bq, bk, bv);

    // kmax (parallel, atomicMax on float bits)
    dim3 kgrid(NBH, 8);
    kmax_kernel<<<kgrid, 256>>>(kh, maxk2);

    // attention
    dim3 agrid(SEQ / QT, NBH);   // (32, 24)
    attn_sm<<<agrid, 256, ATT_SMEM>>>(qh, ql, kh, vth, maxk2, ath, atl);

    // output projection
    dim3 ogrid(D_MODEL / GBN, MROWS / GBM);
    gemm_out<<<ogrid, 256, GEM_SMEM>>>(bo, out);
}

// round 10
// speedup vs baseline: 7.9038x; 1.2417x over previous
#include <cuda_runtime.h>
#include <cuda_fp16.h>
#include <math.h>
#include <stdint.h>

#define D_MODEL 768
#define NUM_HEADS 12
#define DKH 64
#define BATCH 2
#define SEQ 4096
#define MROWS (BATCH * SEQ)   // 8192
#define NBH (BATCH * NUM_HEADS)

#define QSCALE 0.18033688011112042f      // log2(e)/8
#define SHIFT_LOG2 5.770780163555855f    // 4 nats in log2

// ---------------- scratch (device globals; no allocation) ----------------
#define QKV_ELEMS ((size_t)NBH * SEQ * DKH)
#define XN ((size_t)MROWS * D_MODEL)
#define WN ((size_t)D_MODEL * D_MODEL)
__device__ __half g_qh[QKV_ELEMS];       // [bh][s][d], prescaled log2e/8, hi only
__device__ __half g_kh[QKV_ELEMS];       // hi only
__device__ __half g_vth[QKV_ELEMS];      // [bh][d][s], hi only
__device__ __half g_xqh[XN], g_xql[XN];
__device__ __half g_xkh[XN], g_xkl[XN];
__device__ __half g_xvh[XN], g_xvl[XN];
__device__ __half g_wqh[WN];
__device__ __half g_wkh[WN];
__device__ __half g_wvh[WN];
__device__ __half g_woh[WN], g_wol[WN];
__device__ __half g_ath[XN];             // attention out, hi only
__device__ int    g_maxk2[NBH];          // max ||k||^2 as float bits (atomicMax)

// ---------------- helpers ----------------
__device__ __forceinline__ uint32_t smem_u32(const void* p) {
    return (uint32_t)__cvta_generic_to_shared(p);
}
__device__ __forceinline__ uint32_t pk(__half2 h) {
    union { __half2 h; uint32_t u; } x; x.h = h; return x.u;
}
__device__ __forceinline__ void ldsm_x4(uint32_t a, uint32_t& r0, uint32_t& r1,
                                        uint32_t& r2, uint32_t& r3) {
    asm volatile("ldmatrix.sync.aligned.m8n8.x4.shared.b16 {%0,%1,%2,%3}, [%4];"
                 : "=r"(r0), "=r"(r1), "=r"(r2), "=r"(r3) : "r"(a));
}
__device__ __forceinline__ void mma4(float* c, const uint32_t* a, uint32_t b0, uint32_t b1) {
    asm volatile(
        "mma.sync.aligned.m16n8k16.row.col.f32.f16.f16.f32 "
        "{%0,%1,%2,%3}, {%4,%5,%6,%7}, {%8,%9}, {%0,%1,%2,%3};"
        : "+f"(c[0]), "+f"(c[1]), "+f"(c[2]), "+f"(c[3])
        : "r"(a[0]), "r"(a[1]), "r"(a[2]), "r"(a[3]), "r"(b0), "r"(b1));
}
__device__ __forceinline__ void split2(float x, float y, uint32_t& hi, uint32_t& lo) {
    __half2 h = __floats2half2_rn(x, y);
    float rx = x - __half2float(__low2half(h));
    float ry = y - __half2float(__high2half(h));
    hi = pk(h);
    lo = pk(__floats2half2_rn(rx, ry));
}
__device__ __forceinline__ void cpa16(uint32_t s, const void* g) {
    asm volatile("cp.async.cg.shared.global [%0], [%1], 16;" :: "r"(s), "l"(g));
}
__device__ __forceinline__ void cpa_commit() {
    asm volatile("cp.async.commit_group;");
}
__device__ __forceinline__ float ex2(float x) {
    float y;
    asm("ex2.approx.f32 %0, %1;" : "=f"(y) : "f"(x));
    return y;
}
__device__ __forceinline__ float h2sq(uint32_t u) {
    float2 f = __half22float2(*(__half2*)&u);
    return f.x * f.x + f.y * f.y;
}

// =========================================================================
// Fused converter: y = 0..2 activations hi+lo; y = 3..5 weights hi only;
// y = 6 Wo hi+lo.
// =========================================================================
__global__ __launch_bounds__(256) void cvt_all(
    const float* __restrict__ q, const float* __restrict__ k,
    const float* __restrict__ v, const float* __restrict__ wq,
    const float* __restrict__ wk, const float* __restrict__ wv,
    const float* __restrict__ wo)
{
    const int y = blockIdx.y;
    const float* src;
    __half *hi, *lo;
    int n4;
    switch (y) {
        case 0: src = q;  hi = g_xqh; lo = g_xql;   n4 = XN / 4; break;
        case 1: src = k;  hi = g_xkh; lo = g_xkl;   n4 = XN / 4; break;
        case 2: src = v;  hi = g_xvh; lo = g_xvl;   n4 = XN / 4; break;
        case 3: src = wq; hi = g_wqh; lo = nullptr; n4 = WN / 4; break;
        case 4: src = wk; hi = g_wkh; lo = nullptr; n4 = WN / 4; break;
        case 5: src = wv; hi = g_wvh; lo = nullptr; n4 = WN / 4; break;
        default: src = wo; hi = g_woh; lo = g_wol;  n4 = WN / 4; break;
    }
    uint32_t* hio = (uint32_t*)hi;
    uint32_t* loo = (uint32_t*)lo;
    for (int i = blockIdx.x * 256 + threadIdx.x; i < n4; i += gridDim.x * 256) {
        float4 f = ((const float4*)src)[i];
        uint32_t h0, l0, h1, l1;
        split2(f.x, f.y, h0, l0);
        split2(f.z, f.w, h1, l1);
        hio[2 * i] = h0; hio[2 * i + 1] = h1;
        if (lo) { loo[2 * i] = l0; loo[2 * i + 1] = l1; }
    }
}

// =========================================================================
// kmax: grid (NBH, 8), atomicMax on float bits of ||k||^2 (all >= 0).
// =========================================================================
__global__ __launch_bounds__(256) void kmax_kernel(const __half* __restrict__ kh,
                                                   int* __restrict__ maxk2)
{
    __shared__ float red[256];
    const int bh = blockIdx.x;
    const int part = blockIdx.y;
    const int rows = SEQ / 8;
    const __half* base = kh + (size_t)bh * SEQ * DKH + (size_t)part * rows * DKH;
    float mx = 0.f;
    for (int r = threadIdx.x; r < rows; r += 256) {
        const uint4* p = (const uint4*)(base + (size_t)r * DKH);
        float s = 0.f;
        #pragma unroll
        for (int i = 0; i < 8; i++) {
            uint4 u = p[i];
            s += h2sq(u.x) + h2sq(u.y) + h2sq(u.z) + h2sq(u.w);
        }
        mx = fmaxf(mx, s);
    }
    red[threadIdx.x] = mx;
    __syncthreads();
    for (int st = 128; st > 0; st >>= 1) {
        if (threadIdx.x < st) red[threadIdx.x] = fmaxf(red[threadIdx.x], red[threadIdx.x + st]);
        __syncthreads();
    }
    if (threadIdx.x == 0) atomicMax(&maxk2[bh], __float_as_int(red[0]));
}

// =========================================================================
// GEMM body, K-chunk 32, cp.async double-buffered. All GEMMs 2-pass:
//   Al != nullptr: C = (Ahi+Alo) * Whi      (A-corrected)
//   Wl != nullptr: C = Ahi * (Whi+Wlo)      (B-corrected)
// mode 0: fp32 flat; 1: head-split hi; 2: +QSCALE hi; 3: transposed hi.
// =========================================================================
#define GBM 128
#define GBN 64
#define GKC 32
#define GSTR 40
#define NKC (D_MODEL / GKC)
#define GS_A (GBM * GSTR)
#define GS_B (GBN * GSTR)
#define GS_STAGE (2 * GS_A + 2 * GS_B)
#define GEM_SMEM (2 * GS_STAGE * 2)

__device__ __forceinline__ void gemm_body(
    __half* gs,
    const __half* __restrict__ Ah, const __half* __restrict__ Al,
    const __half* __restrict__ Wh, const __half* __restrict__ Wl,
    const float* __restrict__ bias, float* __restrict__ outf,
    __half* __restrict__ outh, int mode)
{
    const int tid = threadIdx.x;
    const int w = tid >> 5;
    const int lane = tid & 31;
    const int row0 = blockIdx.y * GBM;
    const int col0 = blockIdx.x * GBN;
    const int blk = lane >> 3;
    const int lrow = lane & 7;
    const bool useAlo = (Al != nullptr);
    const bool useBlo = (Wl != nullptr);

    float acc[8][4] = {};

    auto issue = [&](int kc, int st) {
        const int k0 = kc * GKC;
        __half* S = gs + st * GS_STAGE;
        #pragma unroll
        for (int i = 0; i < 6; i++) {
            const int ci = tid + i * 256;
            if (ci < 1024) {
                const int hl = ci >> 9;
                if (hl && !useAlo) continue;
                const int idx = ci & 511;
                const int r = idx >> 2, c4 = idx & 3;
                cpa16(smem_u32(S + hl * GS_A + r * GSTR + c4 * 8),
                      (hl ? Al : Ah) + (size_t)(row0 + r) * D_MODEL + k0 + c4 * 8);
            } else {
                const int hl = (ci >> 8) & 1;
                if (hl && !useBlo) continue;
                const int idx = ci & 255;
                const int r = idx >> 2, c4 = idx & 3;
                cpa16(smem_u32(S + 2 * GS_A + hl * GS_B + r * GSTR + c4 * 8),
                      (hl ? Wl : Wh) + (size_t)(col0 + r) * D_MODEL + k0 + c4 * 8);
            }
        }
    };

    issue(0, 0);
    cpa_commit();

    for (int kc = 0; kc < NKC; kc++) {
        if (kc + 1 < NKC) {
            issue(kc + 1, (kc + 1) & 1);
            cpa_commit();
            asm volatile("cp.async.wait_group 1;");
        } else {
            asm volatile("cp.async.wait_group 0;");
        }
        __syncthreads();

        const __half* S = gs + (kc & 1) * GS_STAGE;
        const __half* sAh = S;
        const __half* sAl = S + GS_A;
        const __half* sBh = S + 2 * GS_A;
        const __half* sBl = S + 2 * GS_A + GS_B;

        #pragma unroll
        for (int kk = 0; kk < 2; kk++) {
            uint32_t ahi[4], alo[4];
            const int arow = 16 * w + (blk & 1) * 8 + lrow;
            const int acol = kk * 16 + (blk >> 1) * 8;
            ldsm_x4(smem_u32(sAh + arow * GSTR + acol), ahi[0], ahi[1], ahi[2], ahi[3]);
            if (useAlo)
                ldsm_x4(smem_u32(sAl + arow * GSTR + acol), alo[0], alo[1], alo[2], alo[3]);

            #pragma unroll
            for (int np = 0; np < 4; np++) {
                const int brow = np * 16 + (blk >> 1) * 8 + lrow;
                const int bcol = kk * 16 + (blk & 1) * 8;
                uint32_t bh0, bh1, bh2, bh3;
                ldsm_x4(smem_u32(sBh + brow * GSTR + bcol), bh0, bh1, bh2, bh3);
                mma4(acc[2 * np],     ahi, bh0, bh1);
                mma4(acc[2 * np + 1], ahi, bh2, bh3);
                if (useAlo) {
                    mma4(acc[2 * np],     alo, bh0, bh1);
                    mma4(acc[2 * np + 1], alo, bh2, bh3);
                }
                if (useBlo) {
                    uint32_t bl0, bl1, bl2, bl3;
                    ldsm_x4(smem_u32(sBl + brow * GSTR + bcol), bl0, bl1, bl2, bl3);
                    mma4(acc[2 * np],     ahi, bl0, bl1);
                    mma4(acc[2 * np + 1], ahi, bl2, bl3);
                }
            }
        }
        __syncthreads();
    }

    const float scale = (mode == 2) ? QSCALE : 1.0f;
    const int rloc = 16 * w + (lane >> 2);
    #pragma unroll
    for (int nt = 0; nt < 8; nt++) {
        const int n = col0 + nt * 8 + (lane & 3) * 2;
        const float bx = bias[n], by = bias[n + 1];
        const int m0 = row0 + rloc;
        float o00 = (acc[nt][0] + bx) * scale;
        float o01 = (acc[nt][1] + by) * scale;
        float o10 = (acc[nt][2] + bx) * scale;
        float o11 = (acc[nt][3] + by) * scale;
        if (mode == 0) {
            *(float2*)(outf + (size_t)m0 * D_MODEL + n) = make_float2(o00, o01);
            *(float2*)(outf + (size_t)(m0 + 8) * D_MODEL + n) = make_float2(o10, o11);
        } else {
            const int h = n >> 6, d = n & 63;
            const int b0m = m0 >> 12, s0 = m0 & (SEQ - 1);
            const int b1m = (m0 + 8) >> 12, s1 = (m0 + 8) & (SEQ - 1);
            uint32_t h0u = pk(__floats2half2_rn(o00, o01));
            uint32_t h1u = pk(__floats2half2_rn(o10, o11));
            if (mode == 3) {
                size_t p0 = ((size_t)(b0m * NUM_HEADS + h) * DKH + d) * SEQ + s0;
                size_t p1 = ((size_t)(b1m * NUM_HEADS + h) * DKH + d) * SEQ + s1;
                __half2 H0 = *(__half2*)&h0u, H1 = *(__half2*)&h1u;
                outh[p0] = __low2half(H0);  outh[p0 + SEQ] = __high2half(H0);
                outh[p1] = __low2half(H1);  outh[p1 + SEQ] = __high2half(H1);
            } else {
                size_t p0 = ((size_t)(b0m * NUM_HEADS + h) * SEQ + s0) * DKH + d;
                size_t p1 = ((size_t)(b1m * NUM_HEADS + h) * SEQ + s1) * DKH + d;
                *(uint32_t*)(outh + p0) = h0u;
                *(uint32_t*)(outh + p1) = h1u;
            }
        }
    }
}

__global__ __launch_bounds__(256, 2) void gemm_qkv(
    const float* __restrict__ bq, const float* __restrict__ bk,
    const float* __restrict__ bv)
{
    extern __shared__ __align__(16) __half gs[];
    if (blockIdx.z == 0)
        gemm_body(gs, g_xqh, g_xql, g_wqh, nullptr, bq, nullptr, g_qh, 2);
    else if (blockIdx.z == 1)
        gemm_body(gs, g_xkh, g_xkl, g_wkh, nullptr, bk, nullptr, g_kh, 1);
    else
        gemm_body(gs, g_xvh, g_xvl, g_wvh, nullptr, bv, nullptr, g_vth, 3);
}

__global__ __launch_bounds__(256, 2) void gemm_out(
    const float* __restrict__ bo, float* __restrict__ outf)
{
    extern __shared__ __align__(16) __half gs[];
    gemm_body(gs, g_ath, nullptr, g_woh, g_wol, bo, outf, nullptr, 0);
}

// =========================================================================
// Flash attention: Q hi-only register-resident, 1-pass QK / 1-pass PV,
// SAFE-MAX softmax, KV stage 128, 2-stage cp.async, 2 CTAs/SM.
// =========================================================================
#define QT 128
#define KVS 128
#define KSTR 72
#define VSTR2 136
#define KTILE2 (KVS * KSTR)
#define VTILE2 (DKH * VSTR2)
#define STG2 (KTILE2 + VTILE2)
#define ATT_SMEM (2 * STG2 * 2)       // 71680 B
#define NT2 (SEQ / KVS)               // 32

__global__ __launch_bounds__(256, 2) void attn_sm(
    const __half* __restrict__ Qh_,
    const __half* __restrict__ Kh_, const __half* __restrict__ VTh_,
    const int* __restrict__ maxk2,
    __half* __restrict__ Oh_)
{
    extern __shared__ __align__(16) __half sStage[];

    const int tid = threadIdx.x;
    const int w = tid >> 5;
    const int lane = tid & 31;
    const int q0 = blockIdx.x * QT;
    const int bh = blockIdx.y;
    const int blk = lane >> 3;
    const int lrow = lane & 7;

    const __half* Qgh = Qh_ + (size_t)bh * SEQ * DKH;
    const __half* Kgh = Kh_ + (size_t)bh * SEQ * DKH;
    const __half* Vgh = VTh_ + (size_t)bh * DKH * SEQ;

    auto issue_kv = [&](int t, int st) {
        const int kt = t * KVS;
        __half* S = sStage + st * STG2;
        #pragma unroll
        for (int i = 0; i < 8; i++) {
            const int ci = tid + i * 256;
            if (ci < 1024) {
                const int r = ci >> 3, c8 = ci & 7;
                cpa16(smem_u32(S + r * KSTR + c8 * 8),
                      Kgh + (size_t)(kt + r) * DKH + c8 * 8);
            } else {
                const int idx = ci - 1024;
                const int r = idx >> 4, c16 = idx & 15;
                cpa16(smem_u32(S + KTILE2 + r * VSTR2 + c16 * 8),
                      Vgh + (size_t)r * SEQ + kt + c16 * 8);
            }
        }
    };

    issue_kv(0, 0);
    cpa_commit();
    issue_kv(1, 1);
    cpa_commit();

    // ---- Q fragments in registers (hi only, whole kernel) ----
    uint32_t qh[4][4];
    const int qr = q0 + 16 * w + (lane >> 2);
    #pragma unroll
    for (int ks = 0; ks < 4; ks++) {
        const int c0 = ks * 16 + (lane & 3) * 2;
        qh[ks][0] = *(const uint32_t*)(Qgh + (size_t)qr * DKH + c0);
        qh[ks][1] = *(const uint32_t*)(Qgh + (size_t)(qr + 8) * DKH + c0);
        qh[ks][2] = *(const uint32_t*)(Qgh + (size_t)qr * DKH + c0 + 8);
        qh[ks][3] = *(const uint32_t*)(Qgh + (size_t)(qr + 8) * DKH + c0 + 8);
    }

    // ---- safe-max bounds from register frags ----
    float nq0 = 0.f, nq1 = 0.f;
    #pragma unroll
    for (int ks = 0; ks < 4; ks++) {
        nq0 += h2sq(qh[ks][0]) + h2sq(qh[ks][2]);
        nq1 += h2sq(qh[ks][1]) + h2sq(qh[ks][3]);
    }
    nq0 += __shfl_xor_sync(0xffffffffu, nq0, 1);
    nq0 += __shfl_xor_sync(0xffffffffu, nq0, 2);
    nq1 += __shfl_xor_sync(0xffffffffu, nq1, 1);
    nq1 += __shfl_xor_sync(0xffffffffu, nq1, 2);
    const float mk = sqrtf(__int_as_float(maxk2[bh]));
    const float M20 = sqrtf(nq0) * mk - SHIFT_LOG2;
    const float M21 = sqrtf(nq1) * mk - SHIFT_LOG2;

    float o[8][4] = {};
    float lsum0 = 0.f, lsum1 = 0.f;

    for (int t = 0; t < NT2; t++) {
        if (t + 1 < NT2) {
            issue_kv(t + 1, (t + 1) & 1);
            cpa_commit();
            asm volatile("cp.async.wait_group 1;");
        } else {
            asm volatile("cp.async.wait_group 0;");
        }
        __syncthreads();

        const __half* S = sStage + (t & 1) * STG2;
        const __half* sKh = S;
        const __half* sVh = S + KTILE2;

        #pragma unroll
        for (int j = 0; j < 2; j++) {
            // ---- S = Q K^T (1-pass, Q from registers) ----
            float s[8][4] = {};
            #pragma unroll
            for (int ks = 0; ks < 4; ks++) {
                #pragma unroll
                for (int np = 0; np < 4; np++) {
                    const int brow = j * 64 + np * 16 + (blk >> 1) * 8 + lrow;
                    const int bcol = ks * 16 + (blk & 1) * 8;
                    uint32_t bh0, bh1, bh2, bh3;
                    ldsm_x4(smem_u32(sKh + brow * KSTR + bcol), bh0, bh1, bh2, bh3);
                    mma4(s[2 * np],     qh[ks], bh0, bh1);
                    mma4(s[2 * np + 1], qh[ks], bh2, bh3);
                }
            }

            // ---- exp2 + half convert + PV (1-pass) ----
            #pragma unroll
            for (int ks = 0; ks < 4; ks++) {
                float e00 = ex2(s[2 * ks][0] - M20);
                float e01 = ex2(s[2 * ks][1] - M20);
                float e02 = ex2(s[2 * ks][2] - M21);
                float e03 = ex2(s[2 * ks][3] - M21);
                float e10 = ex2(s[2 * ks + 1][0] - M20);
                float e11 = ex2(s[2 * ks + 1][1] - M20);
                float e12 = ex2(s[2 * ks + 1][2] - M21);
                float e13 = ex2(s[2 * ks + 1][3] - M21);
                lsum0 += e00 + e01 + e10 + e11;
                lsum1 += e02 + e03 + e12 + e13;

                uint32_t ph4[4];
                ph4[0] = pk(__floats2half2_rn(e00, e01));
                ph4[1] = pk(__floats2half2_rn(e02, e03));
                ph4[2] = pk(__floats2half2_rn(e10, e11));
                ph4[3] = pk(__floats2half2_rn(e12, e13));

                #pragma unroll
                for (int npd = 0; npd < 4; npd++) {
                    const int vrow = npd * 16 + (blk >> 1) * 8 + lrow;
                    const int vcol = j * 64 + ks * 16 + (blk & 1) * 8;
                    uint32_t vh0, vh1, vh2, vh3;
                    ldsm_x4(smem_u32(sVh + vrow * VSTR2 + vcol), vh0, vh1, vh2, vh3);
                    mma4(o[2 * npd],     ph4, vh0, vh1);
                    mma4(o[2 * npd + 1], ph4, vh2, vh3);
                }
            }
        }
        __syncthreads();
    }

    // ---- epilogue (hi-only output) ----
    lsum0 += __shfl_xor_sync(0xffffffffu, lsum0, 1);
    lsum0 += __shfl_xor_sync(0xffffffffu, lsum0, 2);
    lsum1 += __shfl_xor_sync(0xffffffffu, lsum1, 1);
    lsum1 += __shfl_xor_sync(0xffffffffu, lsum1, 2);
    const float inv0 = 1.f / lsum0, inv1 = 1.f / lsum1;

    const int b = bh / NUM_HEADS, h = bh % NUM_HEADS;
    const int r0 = 16 * w + (lane >> 2);
    #pragma unroll
    for (int nt = 0; nt < 8; nt++) {
        const int d = h * DKH + nt * 8 + (lane & 3) * 2;
        size_t p0 = (size_t)(b * SEQ + q0 + r0) * D_MODEL + d;
        size_t p1 = (size_t)(b * SEQ + q0 + r0 + 8) * D_MODEL + d;
        *(uint32_t*)(Oh_ + p0) = pk(__floats2half2_rn(o[nt][0] * inv0, o[nt][1] * inv0));
        *(uint32_t*)(Oh_ + p1) = pk(__floats2half2_rn(o[nt][2] * inv1, o[nt][3] * inv1));
    }
}

// =========================================================================
// Launch
// =========================================================================
extern "C" void kernel_launch(void* const* d_in, const int* in_sizes, int n_in,
                              void* d_out, int out_size)
{
    const float* query = (const float*)d_in[0];
    const float* key   = (const float*)d_in[1];
    const float* value = (const float*)d_in[2];
    const float* Wq = (const float*)d_in[3];
    const float* bq = (const float*)d_in[4];
    const float* Wk = (const float*)d_in[5];
    const float* bk = (const float*)d_in[6];
    const float* Wv = (const float*)d_in[7];
    const float* bv = (const float*)d_in[8];
    const float* Wo = (const float*)d_in[9];
    const float* bo = (const float*)d_in[10];
    float* out = (float*)d_out;

    __half *qh, *kh, *vth, *ath;
    int* maxk2;
    cudaGetSymbolAddress((void**)&qh,  g_qh);
    cudaGetSymbolAddress((void**)&kh,  g_kh);
    cudaGetSymbolAddress((void**)&vth, g_vth);
    cudaGetSymbolAddress((void**)&ath, g_ath);
    cudaGetSymbolAddress((void**)&maxk2, g_maxk2);

    cudaFuncSetAttribute(attn_sm, cudaFuncAttributeMaxDynamicSharedMemorySize, ATT_SMEM);
    cudaFuncSetAttribute(gemm_qkv, cudaFuncAttributeMaxDynamicSharedMemorySize, GEM_SMEM);
    cudaFuncSetAttribute(gemm_out, cudaFuncAttributeMaxDynamicSharedMemorySize, GEM_SMEM);

    // single fused converter launch
    dim3 cvt_grid(592, 7);
    cvt_all<<<cvt_grid, 256>>>(query, key, value, Wq, Wk, Wv, Wo);

    // fused Q/K/V projections (all 2-pass A-corrected)
    dim3 qkvgrid(D_MODEL / GBN, MROWS / GBM, 3);   // (12, 64, 3)
    gemm_qkv<<<qkvgrid, 256, GEM_SMEM>>>(bq, bk, bv);

    // kmax
    dim3 kgrid(NBH, 8);
    kmax_kernel<<<kgrid, 256>>>(kh, maxk2);

    // attention (1-pass QK / 1-pass PV)
    dim3 agrid(SEQ / QT, NBH);   // (32, 24)
    attn_sm<<<agrid, 256, ATT_SMEM>>>(qh, kh, vth, maxk2, ath);

    // output projection (2-pass B-corrected)
    dim3 ogrid(D_MODEL / GBN, MROWS / GBM);
    gemm_out<<<ogrid, 256, GEM_SMEM>>>(bo, out);
}

// round 11
// speedup vs baseline: 8.1428x; 1.0302x over previous
#include <cuda_runtime.h>
#include <cuda_fp16.h>
#include <math.h>
#include <stdint.h>

#define D_MODEL 768
#define NUM_HEADS 12
#define DKH 64
#define BATCH 2
#define SEQ 4096
#define MROWS (BATCH * SEQ)   // 8192
#define NBH (BATCH * NUM_HEADS)

#define QSCALE 0.18033688011112042f      // log2(e)/8
#define SHIFT_LOG2 5.770780163555855f    // 4 nats in log2

// ---------------- scratch (device globals; no allocation) ----------------
#define QKV_ELEMS ((size_t)NBH * SEQ * DKH)
#define XN ((size_t)MROWS * D_MODEL)
#define WN ((size_t)D_MODEL * D_MODEL)
__device__ __half g_qh[QKV_ELEMS];       // [bh][s][d], prescaled log2e/8, hi only
__device__ __half g_kh[QKV_ELEMS];       // hi only
__device__ __half g_vth[QKV_ELEMS];      // [bh][d][s], hi only
__device__ __half g_xqh[XN], g_xql[XN];
__device__ __half g_xkh[XN], g_xkl[XN];
__device__ __half g_xvh[XN], g_xvl[XN];
__device__ __half g_wqh[WN];
__device__ __half g_wkh[WN];
__device__ __half g_wvh[WN];
__device__ __half g_woh[WN], g_wol[WN];
__device__ __half g_ath[XN];             // attention out, hi only
__device__ int    g_maxk2[NBH];          // max ||k||^2 as float bits (atomicMax)

// ---------------- helpers ----------------
__device__ __forceinline__ uint32_t smem_u32(const void* p) {
    return (uint32_t)__cvta_generic_to_shared(p);
}
__device__ __forceinline__ uint32_t pk(__half2 h) {
    union { __half2 h; uint32_t u; } x; x.h = h; return x.u;
}
__device__ __forceinline__ void ldsm_x4(uint32_t a, uint32_t& r0, uint32_t& r1,
                                        uint32_t& r2, uint32_t& r3) {
    asm volatile("ldmatrix.sync.aligned.m8n8.x4.shared.b16 {%0,%1,%2,%3}, [%4];"
                 : "=r"(r0), "=r"(r1), "=r"(r2), "=r"(r3) : "r"(a));
}
__device__ __forceinline__ void mma4(float* c, const uint32_t* a, uint32_t b0, uint32_t b1) {
    asm volatile(
        "mma.sync.aligned.m16n8k16.row.col.f32.f16.f16.f32 "
        "{%0,%1,%2,%3}, {%4,%5,%6,%7}, {%8,%9}, {%0,%1,%2,%3};"
        : "+f"(c[0]), "+f"(c[1]), "+f"(c[2]), "+f"(c[3])
        : "r"(a[0]), "r"(a[1]), "r"(a[2]), "r"(a[3]), "r"(b0), "r"(b1));
}
__device__ __forceinline__ void split2(float x, float y, uint32_t& hi, uint32_t& lo) {
    __half2 h = __floats2half2_rn(x, y);
    float rx = x - __half2float(__low2half(h));
    float ry = y - __half2float(__high2half(h));
    hi = pk(h);
    lo = pk(__floats2half2_rn(rx, ry));
}
__device__ __forceinline__ void cpa16(uint32_t s, const void* g) {
    asm volatile("cp.async.cg.shared.global [%0], [%1], 16;" :: "r"(s), "l"(g));
}
__device__ __forceinline__ void cpa_commit() {
    asm volatile("cp.async.commit_group;");
}
__device__ __forceinline__ float ex2(float x) {
    float y;
    asm("ex2.approx.f32 %0, %1;" : "=f"(y) : "f"(x));
    return y;
}
__device__ __forceinline__ float h2sq(uint32_t u) {
    float2 f = __half22float2(*(__half2*)&u);
    return f.x * f.x + f.y * f.y;
}

// =========================================================================
// Fused converter: y = 0..2 activations hi+lo; 3..5 weights hi; 6 Wo hi+lo.
// =========================================================================
__global__ __launch_bounds__(256) void cvt_all(
    const float* __restrict__ q, const float* __restrict__ k,
    const float* __restrict__ v, const float* __restrict__ wq,
    const float* __restrict__ wk, const float* __restrict__ wv,
    const float* __restrict__ wo)
{
    const int y = blockIdx.y;
    const float* src;
    __half *hi, *lo;
    int n4;
    switch (y) {
        case 0: src = q;  hi = g_xqh; lo = g_xql;   n4 = XN / 4; break;
        case 1: src = k;  hi = g_xkh; lo = g_xkl;   n4 = XN / 4; break;
        case 2: src = v;  hi = g_xvh; lo = g_xvl;   n4 = XN / 4; break;
        case 3: src = wq; hi = g_wqh; lo = nullptr; n4 = WN / 4; break;
        case 4: src = wk; hi = g_wkh; lo = nullptr; n4 = WN / 4; break;
        case 5: src = wv; hi = g_wvh; lo = nullptr; n4 = WN / 4; break;
        default: src = wo; hi = g_woh; lo = g_wol;  n4 = WN / 4; break;
    }
    uint32_t* hio = (uint32_t*)hi;
    uint32_t* loo = (uint32_t*)lo;
    for (int i = blockIdx.x * 256 + threadIdx.x; i < n4; i += gridDim.x * 256) {
        float4 f = ((const float4*)src)[i];
        uint32_t h0, l0, h1, l1;
        split2(f.x, f.y, h0, l0);
        split2(f.z, f.w, h1, l1);
        hio[2 * i] = h0; hio[2 * i + 1] = h1;
        if (lo) { loo[2 * i] = l0; loo[2 * i + 1] = l1; }
    }
}

// =========================================================================
// kmax: grid (NBH, 8), atomicMax on float bits of ||k||^2 (all >= 0).
// =========================================================================
__global__ __launch_bounds__(256) void kmax_kernel(const __half* __restrict__ kh,
                                                   int* __restrict__ maxk2)
{
    __shared__ float red[256];
    const int bh = blockIdx.x;
    const int part = blockIdx.y;
    const int rows = SEQ / 8;
    const __half* base = kh + (size_t)bh * SEQ * DKH + (size_t)part * rows * DKH;
    float mx = 0.f;
    for (int r = threadIdx.x; r < rows; r += 256) {
        const uint4* p = (const uint4*)(base + (size_t)r * DKH);
        float s = 0.f;
        #pragma unroll
        for (int i = 0; i < 8; i++) {
            uint4 u = p[i];
            s += h2sq(u.x) + h2sq(u.y) + h2sq(u.z) + h2sq(u.w);
        }
        mx = fmaxf(mx, s);
    }
    red[threadIdx.x] = mx;
    __syncthreads();
    for (int st = 128; st > 0; st >>= 1) {
        if (threadIdx.x < st) red[threadIdx.x] = fmaxf(red[threadIdx.x], red[threadIdx.x + st]);
        __syncthreads();
    }
    if (threadIdx.x == 0) atomicMax(&maxk2[bh], __float_as_int(red[0]));
}

// =========================================================================
// GEMM body, K-chunk 32, cp.async double-buffered. All GEMMs 2-pass.
// =========================================================================
#define GBM 128
#define GBN 64
#define GKC 32
#define GSTR 40
#define NKC (D_MODEL / GKC)
#define GS_A (GBM * GSTR)
#define GS_B (GBN * GSTR)
#define GS_STAGE (2 * GS_A + 2 * GS_B)
#define GEM_SMEM (2 * GS_STAGE * 2)

__device__ __forceinline__ void gemm_body(
    __half* gs,
    const __half* __restrict__ Ah, const __half* __restrict__ Al,
    const __half* __restrict__ Wh, const __half* __restrict__ Wl,
    const float* __restrict__ bias, float* __restrict__ outf,
    __half* __restrict__ outh, int mode)
{
    const int tid = threadIdx.x;
    const int w = tid >> 5;
    const int lane = tid & 31;
    const int row0 = blockIdx.y * GBM;
    const int col0 = blockIdx.x * GBN;
    const int blk = lane >> 3;
    const int lrow = lane & 7;
    const bool useAlo = (Al != nullptr);
    const bool useBlo = (Wl != nullptr);

    float acc[8][4] = {};

    auto issue = [&](int kc, int st) {
        const int k0 = kc * GKC;
        __half* S = gs + st * GS_STAGE;
        #pragma unroll
        for (int i = 0; i < 6; i++) {
            const int ci = tid + i * 256;
            if (ci < 1024) {
                const int hl = ci >> 9;
                if (hl && !useAlo) continue;
                const int idx = ci & 511;
                const int r = idx >> 2, c4 = idx & 3;
                cpa16(smem_u32(S + hl * GS_A + r * GSTR + c4 * 8),
                      (hl ? Al : Ah) + (size_t)(row0 + r) * D_MODEL + k0 + c4 * 8);
            } else {
                const int hl = (ci >> 8) & 1;
                if (hl && !useBlo) continue;
                const int idx = ci & 255;
                const int r = idx >> 2, c4 = idx & 3;
                cpa16(smem_u32(S + 2 * GS_A + hl * GS_B + r * GSTR + c4 * 8),
                      (hl ? Wl : Wh) + (size_t)(col0 + r) * D_MODEL + k0 + c4 * 8);
            }
        }
    };

    issue(0, 0);
    cpa_commit();

    for (int kc = 0; kc < NKC; kc++) {
        if (kc + 1 < NKC) {
            issue(kc + 1, (kc + 1) & 1);
            cpa_commit();
            asm volatile("cp.async.wait_group 1;");
        } else {
            asm volatile("cp.async.wait_group 0;");
        }
        __syncthreads();

        const __half* S = gs + (kc & 1) * GS_STAGE;
        const __half* sAh = S;
        const __half* sAl = S + GS_A;
        const __half* sBh = S + 2 * GS_A;
        const __half* sBl = S + 2 * GS_A + GS_B;

        #pragma unroll
        for (int kk = 0; kk < 2; kk++) {
            uint32_t ahi[4], alo[4];
            const int arow = 16 * w + (blk & 1) * 8 + lrow;
            const int acol = kk * 16 + (blk >> 1) * 8;
            ldsm_x4(smem_u32(sAh + arow * GSTR + acol), ahi[0], ahi[1], ahi[2], ahi[3]);
            if (useAlo)
                ldsm_x4(smem_u32(sAl + arow * GSTR + acol), alo[0], alo[1], alo[2], alo[3]);

            #pragma unroll
            for (int np = 0; np < 4; np++) {
                const int brow = np * 16 + (blk >> 1) * 8 + lrow;
                const int bcol = kk * 16 + (blk & 1) * 8;
                uint32_t bh0, bh1, bh2, bh3;
                ldsm_x4(smem_u32(sBh + brow * GSTR + bcol), bh0, bh1, bh2, bh3);
                mma4(acc[2 * np],     ahi, bh0, bh1);
                mma4(acc[2 * np + 1], ahi, bh2, bh3);
                if (useAlo) {
                    mma4(acc[2 * np],     alo, bh0, bh1);
                    mma4(acc[2 * np + 1], alo, bh2, bh3);
                }
                if (useBlo) {
                    uint32_t bl0, bl1, bl2, bl3;
                    ldsm_x4(smem_u32(sBl + brow * GSTR + bcol), bl0, bl1, bl2, bl3);
                    mma4(acc[2 * np],     ahi, bl0, bl1);
                    mma4(acc[2 * np + 1], ahi, bl2, bl3);
                }
            }
        }
        __syncthreads();
    }

    const float scale = (mode == 2) ? QSCALE : 1.0f;
    const int rloc = 16 * w + (lane >> 2);
    #pragma unroll
    for (int nt = 0; nt < 8; nt++) {
        const int n = col0 + nt * 8 + (lane & 3) * 2;
        const float bx = bias[n], by = bias[n + 1];
        const int m0 = row0 + rloc;
        float o00 = (acc[nt][0] + bx) * scale;
        float o01 = (acc[nt][1] + by) * scale;
        float o10 = (acc[nt][2] + bx) * scale;
        float o11 = (acc[nt][3] + by) * scale;
        if (mode == 0) {
            *(float2*)(outf + (size_t)m0 * D_MODEL + n) = make_float2(o00, o01);
            *(float2*)(outf + (size_t)(m0 + 8) * D_MODEL + n) = make_float2(o10, o11);
        } else {
            const int h = n >> 6, d = n & 63;
            const int b0m = m0 >> 12, s0 = m0 & (SEQ - 1);
            const int b1m = (m0 + 8) >> 12, s1 = (m0 + 8) & (SEQ - 1);
            uint32_t h0u = pk(__floats2half2_rn(o00, o01));
            uint32_t h1u = pk(__floats2half2_rn(o10, o11));
            if (mode == 3) {
                size_t p0 = ((size_t)(b0m * NUM_HEADS + h) * DKH + d) * SEQ + s0;
                size_t p1 = ((size_t)(b1m * NUM_HEADS + h) * DKH + d) * SEQ + s1;
                __half2 H0 = *(__half2*)&h0u, H1 = *(__half2*)&h1u;
                outh[p0] = __low2half(H0);  outh[p0 + SEQ] = __high2half(H0);
                outh[p1] = __low2half(H1);  outh[p1 + SEQ] = __high2half(H1);
            } else {
                size_t p0 = ((size_t)(b0m * NUM_HEADS + h) * SEQ + s0) * DKH + d;
                size_t p1 = ((size_t)(b1m * NUM_HEADS + h) * SEQ + s1) * DKH + d;
                *(uint32_t*)(outh + p0) = h0u;
                *(uint32_t*)(outh + p1) = h1u;
            }
        }
    }
}

__global__ __launch_bounds__(256, 2) void gemm_qkv(
    const float* __restrict__ bq, const float* __restrict__ bk,
    const float* __restrict__ bv)
{
    extern __shared__ __align__(16) __half gs[];
    if (blockIdx.z == 0)
        gemm_body(gs, g_xqh, g_xql, g_wqh, nullptr, bq, nullptr, g_qh, 2);
    else if (blockIdx.z == 1)
        gemm_body(gs, g_xkh, g_xkl, g_wkh, nullptr, bk, nullptr, g_kh, 1);
    else
        gemm_body(gs, g_xvh, g_xvl, g_wvh, nullptr, bv, nullptr, g_vth, 3);
}

__global__ __launch_bounds__(256, 2) void gemm_out(
    const float* __restrict__ bo, float* __restrict__ outf)
{
    extern __shared__ __align__(16) __half gs[];
    gemm_body(gs, g_ath, nullptr, g_woh, g_wol, bo, outf, nullptr, 0);
}

// =========================================================================
// Flash attention: 128 threads / 4 warps, 32 q-rows per warp (2 row-tiles),
// 1-pass QK / 1-pass PV, accumulators initialized to -M (safe-max folded
// into MMA), KV stage 128 processed as 4x 32-kv chunks, 2-stage cp.async.
// SMEM 71680 B/CTA; 2 CTAs/SM. Each K/V ldsm feeds 4 MMAs (was 2).
// =========================================================================
#define QT 128
#define KVS 128
#define KSTR 72
#define VSTR2 136
#define KTILE2 (KVS * KSTR)
#define VTILE2 (DKH * VSTR2)
#define STG2 (KTILE2 + VTILE2)
#define ATT_SMEM (2 * STG2 * 2)       // 71680 B
#define NT2 (SEQ / KVS)               // 32

__global__ __launch_bounds__(128, 2) void attn_sm(
    const __half* __restrict__ Qh_,
    const __half* __restrict__ Kh_, const __half* __restrict__ VTh_,
    const int* __restrict__ maxk2,
    __half* __restrict__ Oh_)
{
    extern __shared__ __align__(16) __half sStage[];

    const int tid = threadIdx.x;
    const int w = tid >> 5;            // 0..3
    const int lane = tid & 31;
    const int q0 = blockIdx.x * QT;
    const int bh = blockIdx.y;
    const int blk = lane >> 3;
    const int lrow = lane & 7;

    const __half* Qgh = Qh_ + (size_t)bh * SEQ * DKH;
    const __half* Kgh = Kh_ + (size_t)bh * SEQ * DKH;
    const __half* Vgh = VTh_ + (size_t)bh * DKH * SEQ;

    // ---- K/V stage loader: 2048 x 16B cp.async, 16 per thread ----
    auto issue_kv = [&](int t, int st) {
        const int kt = t * KVS;
        __half* S = sStage + st * STG2;
        #pragma unroll
        for (int i = 0; i < 16; i++) {
            const int ci = tid + i * 128;
            if (ci < 1024) {
                const int r = ci >> 3, c8 = ci & 7;
                cpa16(smem_u32(S + r * KSTR + c8 * 8),
                      Kgh + (size_t)(kt + r) * DKH + c8 * 8);
            } else {
                const int idx = ci - 1024;
                const int r = idx >> 4, c16 = idx & 15;
                cpa16(smem_u32(S + KTILE2 + r * VSTR2 + c16 * 8),
                      Vgh + (size_t)r * SEQ + kt + c16 * 8);
            }
        }
    };

    issue_kv(0, 0);
    cpa_commit();
    issue_kv(1, 1);
    cpa_commit();

    // ---- Q fragments in registers: 2 row-tiles of 16 (32 rows/warp) ----
    uint32_t qh0[4][4], qh1[4][4];
    const int qr = q0 + 32 * w + (lane >> 2);
    #pragma unroll
    for (int ks = 0; ks < 4; ks++) {
        const int c0 = ks * 16 + (lane & 3) * 2;
        qh0[ks][0] = *(const uint32_t*)(Qgh + (size_t)qr * DKH + c0);
        qh0[ks][1] = *(const uint32_t*)(Qgh + (size_t)(qr + 8) * DKH + c0);
        qh0[ks][2] = *(const uint32_t*)(Qgh + (size_t)qr * DKH + c0 + 8);
        qh0[ks][3] = *(const uint32_t*)(Qgh + (size_t)(qr + 8) * DKH + c0 + 8);
        qh1[ks][0] = *(const uint32_t*)(Qgh + (size_t)(qr + 16) * DKH + c0);
        qh1[ks][1] = *(const uint32_t*)(Qgh + (size_t)(qr + 24) * DKH + c0);
        qh1[ks][2] = *(const uint32_t*)(Qgh + (size_t)(qr + 16) * DKH + c0 + 8);
        qh1[ks][3] = *(const uint32_t*)(Qgh + (size_t)(qr + 24) * DKH + c0 + 8);
    }

    // ---- safe-max bounds: 4 rows per thread ----
    float nq0 = 0.f, nq1 = 0.f, nq2 = 0.f, nq3 = 0.f;
    #pragma unroll
    for (int ks = 0; ks < 4; ks++) {
        nq0 += h2sq(qh0[ks][0]) + h2sq(qh0[ks][2]);
        nq1 += h2sq(qh0[ks][1]) + h2sq(qh0[ks][3]);
        nq2 += h2sq(qh1[ks][0]) + h2sq(qh1[ks][2]);
        nq3 += h2sq(qh1[ks][1]) + h2sq(qh1[ks][3]);
    }
    nq0 += __shfl_xor_sync(0xffffffffu, nq0, 1);
    nq0 += __shfl_xor_sync(0xffffffffu, nq0, 2);
    nq1 += __shfl_xor_sync(0xffffffffu, nq1, 1);
    nq1 += __shfl_xor_sync(0xffffffffu, nq1, 2);
    nq2 += __shfl_xor_sync(0xffffffffu, nq2, 1);
    nq2 += __shfl_xor_sync(0xffffffffu, nq2, 2);
    nq3 += __shfl_xor_sync(0xffffffffu, nq3, 1);
    nq3 += __shfl_xor_sync(0xffffffffu, nq3, 2);
    const float mk = sqrtf(__int_as_float(maxk2[bh]));
    const float M0 = sqrtf(nq0) * mk - SHIFT_LOG2;
    const float M1 = sqrtf(nq1) * mk - SHIFT_LOG2;
    const float M2 = sqrtf(nq2) * mk - SHIFT_LOG2;
    const float M3 = sqrtf(nq3) * mk - SHIFT_LOG2;

    float o0[8][4] = {}, o1[8][4] = {};
    float ls0 = 0.f, ls1 = 0.f, ls2 = 0.f, ls3 = 0.f;

    for (int t = 0; t < NT2; t++) {
        if (t + 1 < NT2) {
            issue_kv(t + 1, (t + 1) & 1);
            cpa_commit();
            asm volatile("cp.async.wait_group 1;");
        } else {
            asm volatile("cp.async.wait_group 0;");
        }
        __syncthreads();

        const __half* S = sStage + (t & 1) * STG2;
        const __half* sKh = S;
        const __half* sVh = S + KTILE2;

        // process 128 kv as 4 chunks of 32
        #pragma unroll
        for (int c = 0; c < 4; c++) {
            // ---- S = Q K^T, accumulators pre-seeded with -M ----
            float s0[4][4], s1[4][4];
            #pragma unroll
            for (int nt = 0; nt < 4; nt++) {
                s0[nt][0] = -M0; s0[nt][1] = -M0; s0[nt][2] = -M1; s0[nt][3] = -M1;
                s1[nt][0] = -M2; s1[nt][1] = -M2; s1[nt][2] = -M3; s1[nt][3] = -M3;
            }
            #pragma unroll
            for (int ks = 0; ks < 4; ks++) {
                #pragma unroll
                for (int np = 0; np < 2; np++) {
                    const int brow = c * 32 + np * 16 + (blk >> 1) * 8 + lrow;
                    const int bcol = ks * 16 + (blk & 1) * 8;
                    uint32_t bh0, bh1, bh2, bh3;
                    ldsm_x4(smem_u32(sKh + brow * KSTR + bcol), bh0, bh1, bh2, bh3);
                    mma4(s0[2 * np],     qh0[ks], bh0, bh1);
                    mma4(s0[2 * np + 1], qh0[ks], bh2, bh3);
                    mma4(s1[2 * np],     qh1[ks], bh0, bh1);
                    mma4(s1[2 * np + 1], qh1[ks], bh2, bh3);
                }
            }

            // ---- exp2 (bound already folded in) + pack ----
            uint32_t p0[2][4], p1[2][4];
            #pragma unroll
            for (int kk = 0; kk < 2; kk++) {
                float a00 = ex2(s0[2 * kk][0]),     a01 = ex2(s0[2 * kk][1]);
                float a02 = ex2(s0[2 * kk][2]),     a03 = ex2(s0[2 * kk][3]);
                float a10 = ex2(s0[2 * kk + 1][0]), a11 = ex2(s0[2 * kk + 1][1]);
                float a12 = ex2(s0[2 * kk + 1][2]), a13 = ex2(s0[2 * kk + 1][3]);
                ls0 += a00 + a01 + a10 + a11;
                ls1 += a02 + a03 + a12 + a13;
                p0[kk][0] = pk(__floats2half2_rn(a00, a01));
                p0[kk][1] = pk(__floats2half2_rn(a02, a03));
                p0[kk][2] = pk(__floats2half2_rn(a10, a11));
                p0[kk][3] = pk(__floats2half2_rn(a12, a13));

                float b00 = ex2(s1[2 * kk][0]),     b01 = ex2(s1[2 * kk][1]);
                float b02 = ex2(s1[2 * kk][2]),     b03 = ex2(s1[2 * kk][3]);
                float b10 = ex2(s1[2 * kk + 1][0]), b11 = ex2(s1[2 * kk + 1][1]);
                float b12 = ex2(s1[2 * kk + 1][2]), b13 = ex2(s1[2 * kk + 1][3]);
                ls2 += b00 + b01 + b10 + b11;
                ls3 += b02 + b03 + b12 + b13;
                p1[kk][0] = pk(__floats2half2_rn(b00, b01));
                p1[kk][1] = pk(__floats2half2_rn(b02, b03));
                p1[kk][2] = pk(__floats2half2_rn(b10, b11));
                p1[kk][3] = pk(__floats2half2_rn(b12, b13));
            }

            // ---- O += P V ----
            #pragma unroll
            for (int npd = 0; npd < 4; npd++) {
                #pragma unroll
                for (int kk = 0; kk < 2; kk++) {
                    const int vrow = npd * 16 + (blk >> 1) * 8 + lrow;
                    const int vcol = c * 32 + kk * 16 + (blk & 1) * 8;
                    uint32_t vh0, vh1, vh2, vh3;
                    ldsm_x4(smem_u32(sVh + vrow * VSTR2 + vcol), vh0, vh1, vh2, vh3);
                    mma4(o0[2 * npd],     p0[kk], vh0, vh1);
                    mma4(o0[2 * npd + 1], p0[kk], vh2, vh3);
                    mma4(o1[2 * npd],     p1[kk], vh0, vh1);
                    mma4(o1[2 * npd + 1], p1[kk], vh2, vh3);
                }
            }
        }
        __syncthreads();
    }

    // ---- epilogue ----
    ls0 += __shfl_xor_sync(0xffffffffu, ls0, 1);
    ls0 += __shfl_xor_sync(0xffffffffu, ls0, 2);
    ls1 += __shfl_xor_sync(0xffffffffu, ls1, 1);
    ls1 += __shfl_xor_sync(0xffffffffu, ls1, 2);
    ls2 += __shfl_xor_sync(0xffffffffu, ls2, 1);
    ls2 += __shfl_xor_sync(0xffffffffu, ls2, 2);
    ls3 += __shfl_xor_sync(0xffffffffu, ls3, 1);
    ls3 += __shfl_xor_sync(0xffffffffu, ls3, 2);
    const float i0 = 1.f / ls0, i1 = 1.f / ls1, i2 = 1.f / ls2, i3 = 1.f / ls3;

    const int b = bh / NUM_HEADS, h = bh % NUM_HEADS;
    const int r0 = 32 * w + (lane >> 2);
    #pragma unroll
    for (int nt = 0; nt < 8; nt++) {
        const int d = h * DKH + nt * 8 + (lane & 3) * 2;
        size_t pA = (size_t)(b * SEQ + q0 + r0) * D_MODEL + d;
        size_t pB = (size_t)(b * SEQ + q0 + r0 + 8) * D_MODEL + d;
        size_t pC = (size_t)(b * SEQ + q0 + r0 + 16) * D_MODEL + d;
        size_t pD = (size_t)(b * SEQ + q0 + r0 + 24) * D_MODEL + d;
        *(uint32_t*)(Oh_ + pA) = pk(__floats2half2_rn(o0[nt][0] * i0, o0[nt][1] * i0));
        *(uint32_t*)(Oh_ + pB) = pk(__floats2half2_rn(o0[nt][2] * i1, o0[nt][3] * i1));
        *(uint32_t*)(Oh_ + pC) = pk(__floats2half2_rn(o1[nt][0] * i2, o1[nt][1] * i2));
        *(uint32_t*)(Oh_ + pD) = pk(__floats2half2_rn(o1[nt][2] * i3, o1[nt][3] * i3));
    }
}

// =========================================================================
// Launch
// =========================================================================
extern "C" void kernel_launch(void* const* d_in, const int* in_sizes, int n_in,
                              void* d_out, int out_size)
{
    const float* query = (const float*)d_in[0];
    const float* key   = (const float*)d_in[1];
    const float* value = (const float*)d_in[2];
    const float* Wq = (const float*)d_in[3];
    const float* bq = (const float*)d_in[4];
    const float* Wk = (const float*)d_in[5];
    const float* bk = (const float*)d_in[6];
    const float* Wv = (const float*)d_in[7];
    const float* bv = (const float*)d_in[8];
    const float* Wo = (const float*)d_in[9];
    const float* bo = (const float*)d_in[10];
    float* out = (float*)d_out;

    __half *qh, *kh, *vth, *ath;
    int* maxk2;
    cudaGetSymbolAddress((void**)&qh,  g_qh);
    cudaGetSymbolAddress((void**)&kh,  g_kh);
    cudaGetSymbolAddress((void**)&vth, g_vth);
    cudaGetSymbolAddress((void**)&ath, g_ath);
    cudaGetSymbolAddress((void**)&maxk2, g_maxk2);

    cudaFuncSetAttribute(attn_sm, cudaFuncAttributeMaxDynamicSharedMemorySize, ATT_SMEM);
    cudaFuncSetAttribute(gemm_qkv, cudaFuncAttributeMaxDynamicSharedMemorySize, GEM_SMEM);
    cudaFuncSetAttribute(gemm_out, cudaFuncAttributeMaxDynamicSharedMemorySize, GEM_SMEM);

    // single fused converter launch
    dim3 cvt_grid(592, 7);
    cvt_all<<<cvt_grid, 256>>>(query, key, value, Wq, Wk, Wv, Wo);

    // fused Q/K/V projections (2-pass A-corrected)
    dim3 qkvgrid(D_MODEL / GBN, MROWS / GBM, 3);   // (12, 64, 3)
    gemm_qkv<<<qkvgrid, 256, GEM_SMEM>>>(bq, bk, bv);

    // kmax
    dim3 kgrid(NBH, 8);
    kmax_kernel<<<kgrid, 256>>>(kh, maxk2);

    // attention (4 warps, 32 q-rows/warp)
    dim3 agrid(SEQ / QT, NBH);   // (32, 24)
    attn_sm<<<agrid, 128, ATT_SMEM>>>(qh, kh, vth, maxk2, ath);

    // output projection (2-pass B-corrected)
    dim3 ogrid(D_MODEL / GBN, MROWS / GBM);
    gemm_out<<<ogrid, 256, GEM_SMEM>>>(bo, out);
}